// round 1
// baseline (speedup 1.0000x reference)
#include <cuda_runtime.h>

// CrissCrossAttention fp32 baseline.
// B=4, C=256, H=W=128, Cq=32, 4 heads (c_q=8/head, c_v=64/head).
//
// Pipeline:
//   1) proj_kernel: q = Wq@x+bq, k = Wk@x+bk, v = Wv@x+bv  (one fused SGEMM, M=320,K=256,N=65536)
//   2) transpose_kernel: per-plane 128x128 transpose of q,k,v (for coalesced vertical pass)
//   3) attn_kernel(vertical=0): per (bh,h) row attention, writes o_h
//   4) attn_kernel(vertical=1): per (bh,w) column attention, fuses out = gamma*(o_h+o_v)+x

#define BATCH 4
#define CTOT 256
#define HW   128
#define CQ   32
#define NH   4
#define CHQ  8     // q/k channels per head
#define CHV  64    // v channels per head
#define NPIX (HW*HW)   // 16384

// ---------------- scratch (no allocations allowed) ----------------
__device__ float g_q [BATCH*CQ  *NPIX];
__device__ float g_k [BATCH*CQ  *NPIX];
__device__ float g_v [BATCH*CTOT*NPIX];
__device__ float g_qT[BATCH*CQ  *NPIX];
__device__ float g_kT[BATCH*CQ  *NPIX];
__device__ float g_vT[BATCH*CTOT*NPIX];
__device__ float g_oh[BATCH*CTOT*NPIX];

// ---------------- 1) QKV projection ----------------
// C[m,p] = sum_k W[m,k] * X[k,p] per batch, rows 0..31 -> q, 32..63 -> k, 64..319 -> v.
// BM=64, BN=128, BK=16; 16x16 threads, 4x8 per-thread tile.
__global__ __launch_bounds__(256) void proj_kernel(
    const float* __restrict__ x,
    const float* __restrict__ Wq, const float* __restrict__ bq,
    const float* __restrict__ Wk, const float* __restrict__ bk,
    const float* __restrict__ Wv, const float* __restrict__ bv)
{
    __shared__ float Ws[16][64];
    __shared__ float Xs[16][132];  // padded row stride; 132*4 % 16 == 0 (float4 ok)

    const int bb = blockIdx.z;
    const int m0 = blockIdx.y * 64;
    const int p0 = blockIdx.x * 128;
    const int tid = threadIdx.x;
    const int tx = tid & 15, ty = tid >> 4;

    const float* xb = x + (size_t)bb * CTOT * NPIX;

    float acc[4][8];
#pragma unroll
    for (int i = 0; i < 4; i++)
#pragma unroll
        for (int j = 0; j < 8; j++) acc[i][j] = 0.f;

    for (int k0 = 0; k0 < 256; k0 += 16) {
        // load W tile (64 x 16)
#pragma unroll
        for (int i = 0; i < 4; i++) {
            int e  = tid + i * 256;
            int m  = e >> 4, kk = e & 15;
            int r  = m0 + m;
            const float* wr;
            if (r < 32)      wr = Wq + (size_t)r * 256;
            else if (r < 64) wr = Wk + (size_t)(r - 32) * 256;
            else             wr = Wv + (size_t)(r - 64) * 256;
            Ws[kk][m] = wr[k0 + kk];
        }
        // load X tile (16 x 128)
#pragma unroll
        for (int i = 0; i < 8; i++) {
            int e  = tid + i * 256;
            int kk = e >> 7, pp = e & 127;
            Xs[kk][pp] = xb[(size_t)(k0 + kk) * NPIX + p0 + pp];
        }
        __syncthreads();
#pragma unroll
        for (int kk = 0; kk < 16; kk++) {
            float4 a4 = *(float4*)&Ws[kk][ty * 4];
            float4 b0 = *(float4*)&Xs[kk][tx * 8];
            float4 b1 = *(float4*)&Xs[kk][tx * 8 + 4];
            float ar[4] = {a4.x, a4.y, a4.z, a4.w};
            float br[8] = {b0.x, b0.y, b0.z, b0.w, b1.x, b1.y, b1.z, b1.w};
#pragma unroll
            for (int i = 0; i < 4; i++)
#pragma unroll
                for (int j = 0; j < 8; j++)
                    acc[i][j] += ar[i] * br[j];
        }
        __syncthreads();
    }

    // epilogue: route rows to q/k/v + bias
#pragma unroll
    for (int i = 0; i < 4; i++) {
        int r = m0 + ty * 4 + i;
        float bias;
        float* dst;
        if (r < 32)      { bias = bq[r];       dst = g_q + (size_t)(bb * CQ   + r)       * NPIX; }
        else if (r < 64) { bias = bk[r - 32];  dst = g_k + (size_t)(bb * CQ   + r - 32)  * NPIX; }
        else             { bias = bv[r - 64];  dst = g_v + (size_t)(bb * CTOT + r - 64)  * NPIX; }
#pragma unroll
        for (int j = 0; j < 8; j++)
            dst[p0 + tx * 8 + j] = acc[i][j] + bias;
    }
}

// ---------------- 2) per-plane 128x128 transpose ----------------
// planes: [0,128) q, [128,256) k, [256,1280) v
__global__ void transpose_kernel()
{
    __shared__ float tile[32][33];
    const int pz = blockIdx.z;
    const float* src;
    float* dst;
    if (pz < BATCH * CQ)              { src = g_q + (size_t)pz * NPIX;                 dst = g_qT + (size_t)pz * NPIX; }
    else if (pz < 2 * BATCH * CQ)     { int p = pz - BATCH * CQ;     src = g_k + (size_t)p * NPIX; dst = g_kT + (size_t)p * NPIX; }
    else                              { int p = pz - 2 * BATCH * CQ; src = g_v + (size_t)p * NPIX; dst = g_vT + (size_t)p * NPIX; }

    const int x0 = blockIdx.x * 32, y0 = blockIdx.y * 32;
    const int tx = threadIdx.x, ty = threadIdx.y;
#pragma unroll
    for (int j = ty; j < 32; j += 8)
        tile[j][tx] = src[(size_t)(y0 + j) * HW + x0 + tx];
    __syncthreads();
#pragma unroll
    for (int j = ty; j < 32; j += 8)
        dst[(size_t)(x0 + j) * HW + y0 + tx] = tile[tx][j];
}

// ---------------- 3/4) attention (shared code for H and V) ----------------
// Per CTA (line = h or w, bh = b*4+head):
//   E[p][g]   = sum_c qs[c][p] * ks[c][g]     (stored transposed: As[g][p])
//   A         = softmax over g (per p)
//   O[c][p]   = sum_g As[g][p] * Vs[c][g]
// horizontal: write O -> g_oh[b, head*64+c, line, p]
// vertical:   out[b, head*64+c, line, p] = gamma*(g_oh + O) + x
__global__ __launch_bounds__(256, 2) void attn_kernel(
    int vertical, const float* __restrict__ x,
    const float* __restrict__ gamma, float* __restrict__ out)
{
    extern __shared__ float sm[];
    float* qs = sm;                      // 8*128
    float* ks = sm + 1024;               // 8*128
    float* As = sm + 2048;               // 128*128
    float* Vs = sm + 2048 + 16384;       // 64*132 (padded)

    const int line = blockIdx.x;
    const int bh   = blockIdx.y;
    const int bb = bh >> 2, head = bh & 3;
    const int tid = threadIdx.x;

    const float* qb = vertical ? g_qT : g_q;
    const float* kb = vertical ? g_kT : g_k;
    const float* vb = vertical ? g_vT : g_v;

    // load q,k rows (8x128 each), one float4 per thread per array
    {
        int c = tid >> 5, p4 = (tid & 31) << 2;
        size_t off = ((size_t)(bb * CQ + head * CHQ + c) * NPIX) + (size_t)line * HW + p4;
        *(float4*)&qs[c * HW + p4] = *(const float4*)&qb[off];
        *(float4*)&ks[c * HW + p4] = *(const float4*)&kb[off];
    }
    // load V rows (64x128)
#pragma unroll
    for (int i = 0; i < 8; i++) {
        int e = tid + (i << 8);
        int c = e >> 5, p4 = (e & 31) << 2;
        size_t off = ((size_t)(bb * CTOT + head * CHV + c) * NPIX) + (size_t)line * HW + p4;
        *(float4*)&Vs[c * 132 + p4] = *(const float4*)&vb[off];
    }
    __syncthreads();

    const int tx = tid & 15, ty = tid >> 4;

    // ---- energies: As[g][p] = sum_c ks[c][g] * qs[c][p], 8x8 per thread ----
    {
        const int p0 = tx << 3, g0 = ty << 3;
        float acc[8][8];
#pragma unroll
        for (int i = 0; i < 8; i++)
#pragma unroll
            for (int j = 0; j < 8; j++) acc[i][j] = 0.f;
#pragma unroll
        for (int c = 0; c < 8; c++) {
            float4 qa = *(float4*)&qs[c * HW + p0];
            float4 qc = *(float4*)&qs[c * HW + p0 + 4];
            float4 ka = *(float4*)&ks[c * HW + g0];
            float4 kc = *(float4*)&ks[c * HW + g0 + 4];
            float qr[8] = {qa.x, qa.y, qa.z, qa.w, qc.x, qc.y, qc.z, qc.w};
            float kr[8] = {ka.x, ka.y, ka.z, ka.w, kc.x, kc.y, kc.z, kc.w};
#pragma unroll
            for (int i = 0; i < 8; i++)
#pragma unroll
                for (int j = 0; j < 8; j++)
                    acc[i][j] += kr[i] * qr[j];
        }
#pragma unroll
        for (int i = 0; i < 8; i++) {
            *(float4*)&As[(g0 + i) * HW + p0]     = make_float4(acc[i][0], acc[i][1], acc[i][2], acc[i][3]);
            *(float4*)&As[(g0 + i) * HW + p0 + 4] = make_float4(acc[i][4], acc[i][5], acc[i][6], acc[i][7]);
        }
    }
    __syncthreads();

    // ---- softmax over g for column p = tid (threads 0..127) ----
    if (tid < HW) {
        float m = -1e30f;
#pragma unroll 4
        for (int g = 0; g < HW; g++) m = fmaxf(m, As[g * HW + tid]);
        float s = 0.f;
#pragma unroll 4
        for (int g = 0; g < HW; g++) {
            float e = __expf(As[g * HW + tid] - m);
            As[g * HW + tid] = e;
            s += e;
        }
        float inv = 1.f / s;
#pragma unroll 4
        for (int g = 0; g < HW; g++) As[g * HW + tid] *= inv;
    }
    __syncthreads();

    // ---- O[c][p] = sum_g As[g][p] * Vs[c][g], 4x8 per thread ----
    const int c0 = ty << 2, p0 = tx << 3;
    float o[4][8];
#pragma unroll
    for (int i = 0; i < 4; i++)
#pragma unroll
        for (int j = 0; j < 8; j++) o[i][j] = 0.f;

#pragma unroll 4
    for (int g = 0; g < HW; g++) {
        float4 aa = *(float4*)&As[g * HW + p0];
        float4 ab = *(float4*)&As[g * HW + p0 + 4];
        float ar[8] = {aa.x, aa.y, aa.z, aa.w, ab.x, ab.y, ab.z, ab.w};
        float vr[4];
#pragma unroll
        for (int i = 0; i < 4; i++) vr[i] = Vs[(c0 + i) * 132 + g];
#pragma unroll
        for (int i = 0; i < 4; i++)
#pragma unroll
            for (int j = 0; j < 8; j++)
                o[i][j] += vr[i] * ar[j];
    }

    // ---- epilogue ----
    if (!vertical) {
#pragma unroll
        for (int i = 0; i < 4; i++) {
            size_t base = ((size_t)(bb * CTOT + head * CHV + c0 + i) * HW + line) * HW + p0;
            *(float4*)&g_oh[base]     = make_float4(o[i][0], o[i][1], o[i][2], o[i][3]);
            *(float4*)&g_oh[base + 4] = make_float4(o[i][4], o[i][5], o[i][6], o[i][7]);
        }
    } else {
        const float g = gamma[0];
#pragma unroll
        for (int i = 0; i < 4; i++) {
            size_t base = ((size_t)(bb * CTOT + head * CHV + c0 + i) * HW + line) * HW + p0;
#pragma unroll
            for (int j = 0; j < 8; j++)
                out[base + j] = g * (g_oh[base + j] + o[i][j]) + x[base + j];
        }
    }
}

// ---------------- launch ----------------
extern "C" void kernel_launch(void* const* d_in, const int* in_sizes, int n_in,
                              void* d_out, int out_size)
{
    const float* x     = (const float*)d_in[0];
    const float* Wq    = (const float*)d_in[1];
    const float* bq    = (const float*)d_in[2];
    const float* Wk    = (const float*)d_in[3];
    const float* bk    = (const float*)d_in[4];
    const float* Wv    = (const float*)d_in[5];
    const float* bv    = (const float*)d_in[6];
    const float* gamma = (const float*)d_in[7];
    float* out = (float*)d_out;

    // 1) projection: grid (pixels/128, 320/64, B)
    proj_kernel<<<dim3(128, 5, 4), 256>>>(x, Wq, bq, Wk, bk, Wv, bv);

    // 2) transpose q,k,v planes: 128+128+1024 planes
    transpose_kernel<<<dim3(4, 4, 1280), dim3(32, 8)>>>();

    // 3/4) attention passes
    const size_t SMEM = (size_t)(2048 + 16384 + 64 * 132) * sizeof(float); // 107520 B
    cudaFuncSetAttribute(attn_kernel, cudaFuncAttributeMaxDynamicSharedMemorySize, (int)SMEM);
    attn_kernel<<<dim3(HW, 16), 256, SMEM>>>(0, x, gamma, out);
    attn_kernel<<<dim3(HW, 16), 256, SMEM>>>(1, x, gamma, out);
}

// round 2
// speedup vs baseline: 1.4011x; 1.4011x over previous
#include <cuda_runtime.h>
#include <cuda_fp16.h>
#include <cstdint>

// CrissCrossAttention — R2: tensor-core (mma.sync fp16 + hi/lo split) attention.
// B=4, C=256, H=W=128, Cq=32, 4 heads (c_q=8/head, c_v=64/head).
//
//   1) proj_kernel  : fused QKV 1x1-conv SGEMM (fp32, unchanged from R1)
//   2) transpose    : per-plane 128x128 transposes for the vertical pass
//   3) attn_mma x2  : per-(bh,line) attention on tensor cores
//        E = QtK   : fp16 hi/lo 4-term split (exact to ~2^-22), K=32, mma m16n8k16
//        softmax   : fully in registers (C-frag == A-frag layout identity)
//        O = A*Vt  : A fp16 (unnormalized exp), V hi/lo split (2 passes), /sum at end

#define BATCH 4
#define CTOT 256
#define HW   128
#define CQ   32
#define CHQ  8
#define CHV  64
#define NPIX (HW*HW)

// ---------------- scratch ----------------
__device__ float g_q [BATCH*CQ  *NPIX];
__device__ float g_k [BATCH*CQ  *NPIX];
__device__ float g_v [BATCH*CTOT*NPIX];
__device__ float g_qT[BATCH*CQ  *NPIX];
__device__ float g_kT[BATCH*CQ  *NPIX];
__device__ float g_vT[BATCH*CTOT*NPIX];
__device__ float g_oh[BATCH*CTOT*NPIX];

// ---------------- 1) QKV projection (fp32, unchanged) ----------------
__global__ __launch_bounds__(256) void proj_kernel(
    const float* __restrict__ x,
    const float* __restrict__ Wq, const float* __restrict__ bq,
    const float* __restrict__ Wk, const float* __restrict__ bk,
    const float* __restrict__ Wv, const float* __restrict__ bv)
{
    __shared__ float Ws[16][64];
    __shared__ float Xs[16][132];

    const int bb = blockIdx.z;
    const int m0 = blockIdx.y * 64;
    const int p0 = blockIdx.x * 128;
    const int tid = threadIdx.x;
    const int tx = tid & 15, ty = tid >> 4;

    const float* xb = x + (size_t)bb * CTOT * NPIX;

    float acc[4][8];
#pragma unroll
    for (int i = 0; i < 4; i++)
#pragma unroll
        for (int j = 0; j < 8; j++) acc[i][j] = 0.f;

    for (int k0 = 0; k0 < 256; k0 += 16) {
#pragma unroll
        for (int i = 0; i < 4; i++) {
            int e  = tid + i * 256;
            int m  = e >> 4, kk = e & 15;
            int r  = m0 + m;
            const float* wr;
            if (r < 32)      wr = Wq + (size_t)r * 256;
            else if (r < 64) wr = Wk + (size_t)(r - 32) * 256;
            else             wr = Wv + (size_t)(r - 64) * 256;
            Ws[kk][m] = wr[k0 + kk];
        }
#pragma unroll
        for (int i = 0; i < 8; i++) {
            int e  = tid + i * 256;
            int kk = e >> 7, pp = e & 127;
            Xs[kk][pp] = xb[(size_t)(k0 + kk) * NPIX + p0 + pp];
        }
        __syncthreads();
#pragma unroll
        for (int kk = 0; kk < 16; kk++) {
            float4 a4 = *(float4*)&Ws[kk][ty * 4];
            float4 b0 = *(float4*)&Xs[kk][tx * 8];
            float4 b1 = *(float4*)&Xs[kk][tx * 8 + 4];
            float ar[4] = {a4.x, a4.y, a4.z, a4.w};
            float br[8] = {b0.x, b0.y, b0.z, b0.w, b1.x, b1.y, b1.z, b1.w};
#pragma unroll
            for (int i = 0; i < 4; i++)
#pragma unroll
                for (int j = 0; j < 8; j++)
                    acc[i][j] += ar[i] * br[j];
        }
        __syncthreads();
    }

#pragma unroll
    for (int i = 0; i < 4; i++) {
        int r = m0 + ty * 4 + i;
        float bias;
        float* dst;
        if (r < 32)      { bias = bq[r];       dst = g_q + (size_t)(bb * CQ   + r)       * NPIX; }
        else if (r < 64) { bias = bk[r - 32];  dst = g_k + (size_t)(bb * CQ   + r - 32)  * NPIX; }
        else             { bias = bv[r - 64];  dst = g_v + (size_t)(bb * CTOT + r - 64)  * NPIX; }
#pragma unroll
        for (int j = 0; j < 8; j++)
            dst[p0 + tx * 8 + j] = acc[i][j] + bias;
    }
}

// ---------------- 2) per-plane 128x128 transpose ----------------
__global__ void transpose_kernel()
{
    __shared__ float tile[32][33];
    const int pz = blockIdx.z;
    const float* src;
    float* dst;
    if (pz < BATCH * CQ)          { src = g_q + (size_t)pz * NPIX;                 dst = g_qT + (size_t)pz * NPIX; }
    else if (pz < 2 * BATCH * CQ) { int p = pz - BATCH * CQ;     src = g_k + (size_t)p * NPIX; dst = g_kT + (size_t)p * NPIX; }
    else                          { int p = pz - 2 * BATCH * CQ; src = g_v + (size_t)p * NPIX; dst = g_vT + (size_t)p * NPIX; }

    const int x0 = blockIdx.x * 32, y0 = blockIdx.y * 32;
    const int tx = threadIdx.x, ty = threadIdx.y;
#pragma unroll
    for (int j = ty; j < 32; j += 8)
        tile[j][tx] = src[(size_t)(y0 + j) * HW + x0 + tx];
    __syncthreads();
#pragma unroll
    for (int j = ty; j < 32; j += 8)
        dst[(size_t)(x0 + j) * HW + y0 + tx] = tile[tx][j];
}

// ---------------- mma helper ----------------
__device__ __forceinline__ void mma16816(float* d, const uint32_t* a, uint32_t b0, uint32_t b1)
{
    asm volatile(
        "mma.sync.aligned.m16n8k16.row.col.f32.f16.f16.f32 "
        "{%0,%1,%2,%3},{%4,%5,%6,%7},{%8,%9},{%0,%1,%2,%3};"
        : "+f"(d[0]), "+f"(d[1]), "+f"(d[2]), "+f"(d[3])
        : "r"(a[0]), "r"(a[1]), "r"(a[2]), "r"(a[3]), "r"(b0), "r"(b1));
}

// ---------------- 3/4) attention on tensor cores ----------------
// smem layout (bytes):
//   Q2  : 128 x 40 half  = 10240   (k2: [0,8)=hi [8,16)=hi [16,24)=lo [24,32)=lo)
//   K2  : 128 x 40 half  = 10240   (k2: [0,8)=hi [8,16)=lo [16,24)=hi [24,32)=lo)
//   Vhi : 64 x 136 half  = 17408
//   Vlo : 64 x 136 half  = 17408
//   Osm : 64 x 132 float = 33792
#define SM_Q2   0
#define SM_K2   10240
#define SM_VHI  20480
#define SM_VLO  37888
#define SM_OSM  55296
#define SM_TOTAL 89088

__global__ __launch_bounds__(256, 2) void attn_mma(
    int vertical, const float* __restrict__ x,
    const float* __restrict__ gamma, float* __restrict__ out)
{
    extern __shared__ char sm[];
    __half* Q2  = (__half*)(sm + SM_Q2);
    __half* K2  = (__half*)(sm + SM_K2);
    __half* Vhi = (__half*)(sm + SM_VHI);
    __half* Vlo = (__half*)(sm + SM_VLO);
    float*  Osm = (float*)(sm + SM_OSM);

    const int line = blockIdx.x;
    const int bh   = blockIdx.y;
    const int bb = bh >> 2, head = bh & 3;
    const int tid  = threadIdx.x;
    const int wid  = tid >> 5;
    const int lane = tid & 31;

    const float* qb = vertical ? g_qT : g_q;
    const float* kb = vertical ? g_kT : g_k;
    const float* vb = vertical ? g_vT : g_v;

    // ---- load q,k; build fp16 hi/lo split tables ----
    {
        int c = tid >> 5, p4 = (tid & 31) << 2;
        size_t off = ((size_t)(bb * CQ + head * CHQ + c) * NPIX) + (size_t)line * HW + p4;
        float4 qv = *(const float4*)&qb[off];
        float4 kv = *(const float4*)&kb[off];
        float qa[4] = {qv.x, qv.y, qv.z, qv.w};
        float ka[4] = {kv.x, kv.y, kv.z, kv.w};
#pragma unroll
        for (int j = 0; j < 4; j++) {
            int p = p4 + j;
            __half qh = __float2half_rn(qa[j]);
            __half ql = __float2half_rn(qa[j] - __half2float(qh));
            __half kh = __float2half_rn(ka[j]);
            __half kl = __float2half_rn(ka[j] - __half2float(kh));
            // Q pattern: hi hi lo lo ; K pattern: hi lo hi lo
            Q2[p * 40 + c]      = qh;
            Q2[p * 40 + c + 8]  = qh;
            Q2[p * 40 + c + 16] = ql;
            Q2[p * 40 + c + 24] = ql;
            K2[p * 40 + c]      = kh;
            K2[p * 40 + c + 8]  = kl;
            K2[p * 40 + c + 16] = kh;
            K2[p * 40 + c + 24] = kl;
        }
    }
    // ---- load V, split hi/lo ----
#pragma unroll
    for (int i = 0; i < 8; i++) {
        int e = tid + (i << 8);
        int c = e >> 5, p4 = (e & 31) << 2;
        size_t off = ((size_t)(bb * CTOT + head * CHV + c) * NPIX) + (size_t)line * HW + p4;
        float4 vv = *(const float4*)&vb[off];
        float va[4] = {vv.x, vv.y, vv.z, vv.w};
#pragma unroll
        for (int j = 0; j < 4; j++) {
            __half vh = __float2half_rn(va[j]);
            __half vl = __float2half_rn(va[j] - __half2float(vh));
            Vhi[c * 136 + p4 + j] = vh;
            Vlo[c * 136 + p4 + j] = vl;
        }
    }
    __syncthreads();

    // ---- E = Qt*K  (M=128 p, N=128 g, K=32 split-channels) ----
    // warp w owns p-rows [16w, 16w+16)
    const int qr  = lane >> 2;        // 0..7
    const int qq  = lane & 3;         // 0..3
    float acc[16][4];
#pragma unroll
    for (int nt = 0; nt < 16; nt++)
#pragma unroll
        for (int j = 0; j < 4; j++) acc[nt][j] = 0.f;

    uint32_t afr[2][4];
#pragma unroll
    for (int kt = 0; kt < 2; kt++) {
        int base = (wid * 16 + qr) * 40 + 2 * qq + 16 * kt;
        afr[kt][0] = *(const uint32_t*)&Q2[base];
        afr[kt][1] = *(const uint32_t*)&Q2[base + 8 * 40];
        afr[kt][2] = *(const uint32_t*)&Q2[base + 8];
        afr[kt][3] = *(const uint32_t*)&Q2[base + 8 * 40 + 8];
    }
#pragma unroll
    for (int nt = 0; nt < 16; nt++) {
#pragma unroll
        for (int kt = 0; kt < 2; kt++) {
            int gb = (8 * nt + qr) * 40 + 2 * qq + 16 * kt;
            uint32_t b0 = *(const uint32_t*)&K2[gb];
            uint32_t b1 = *(const uint32_t*)&K2[gb + 8];
            mma16816(acc[nt], afr[kt], b0, b1);
        }
    }

    // ---- softmax in registers (rows r = 16*wid+qr and r+8) ----
    float mr = -1e30f, mr8 = -1e30f;
#pragma unroll
    for (int nt = 0; nt < 16; nt++) {
        mr  = fmaxf(mr,  fmaxf(acc[nt][0], acc[nt][1]));
        mr8 = fmaxf(mr8, fmaxf(acc[nt][2], acc[nt][3]));
    }
    mr  = fmaxf(mr,  __shfl_xor_sync(0xffffffffu, mr, 1));
    mr  = fmaxf(mr,  __shfl_xor_sync(0xffffffffu, mr, 2));
    mr8 = fmaxf(mr8, __shfl_xor_sync(0xffffffffu, mr8, 1));
    mr8 = fmaxf(mr8, __shfl_xor_sync(0xffffffffu, mr8, 2));

    float sr = 0.f, sr8 = 0.f;
#pragma unroll
    for (int nt = 0; nt < 16; nt++) {
        acc[nt][0] = __expf(acc[nt][0] - mr);
        acc[nt][1] = __expf(acc[nt][1] - mr);
        acc[nt][2] = __expf(acc[nt][2] - mr8);
        acc[nt][3] = __expf(acc[nt][3] - mr8);
        sr  += acc[nt][0] + acc[nt][1];
        sr8 += acc[nt][2] + acc[nt][3];
    }
    sr  += __shfl_xor_sync(0xffffffffu, sr, 1);
    sr  += __shfl_xor_sync(0xffffffffu, sr, 2);
    sr8 += __shfl_xor_sync(0xffffffffu, sr8, 1);
    sr8 += __shfl_xor_sync(0xffffffffu, sr8, 2);

    // ---- repack exp(E) C-frags directly as A-frags of the O GEMM ----
    uint32_t Af[8][4];
#pragma unroll
    for (int kt = 0; kt < 8; kt++) {
        __half2 h0 = __floats2half2_rn(acc[2 * kt][0],     acc[2 * kt][1]);
        __half2 h1 = __floats2half2_rn(acc[2 * kt][2],     acc[2 * kt][3]);
        __half2 h2 = __floats2half2_rn(acc[2 * kt + 1][0], acc[2 * kt + 1][1]);
        __half2 h3 = __floats2half2_rn(acc[2 * kt + 1][2], acc[2 * kt + 1][3]);
        Af[kt][0] = *(uint32_t*)&h0;
        Af[kt][1] = *(uint32_t*)&h1;
        Af[kt][2] = *(uint32_t*)&h2;
        Af[kt][3] = *(uint32_t*)&h3;
    }

    // ---- O = A * V^T  (M=128 p, N=64 c, K=128 g) with V hi+lo passes ----
    float oacc[8][4];
#pragma unroll
    for (int nt = 0; nt < 8; nt++)
#pragma unroll
        for (int j = 0; j < 4; j++) oacc[nt][j] = 0.f;

#pragma unroll
    for (int kt = 0; kt < 8; kt++) {
#pragma unroll
        for (int nt = 0; nt < 8; nt++) {
            int vb0 = (8 * nt + qr) * 136 + 16 * kt + 2 * qq;
            uint32_t bh0 = *(const uint32_t*)&Vhi[vb0];
            uint32_t bh1 = *(const uint32_t*)&Vhi[vb0 + 8];
            mma16816(oacc[nt], Af[kt], bh0, bh1);
            uint32_t bl0 = *(const uint32_t*)&Vlo[vb0];
            uint32_t bl1 = *(const uint32_t*)&Vlo[vb0 + 8];
            mma16816(oacc[nt], Af[kt], bl0, bl1);
        }
    }

    // ---- normalize + stage to smem (c-major rows for coalesced stores) ----
    const float inv_r  = 1.f / sr;
    const float inv_r8 = 1.f / sr8;
    const int   r  = wid * 16 + qr;
    const int   r8 = r + 8;
#pragma unroll
    for (int nt = 0; nt < 8; nt++) {
        int c0 = 8 * nt + 2 * qq;
        Osm[c0 * 132 + r]        = oacc[nt][0] * inv_r;
        Osm[(c0 + 1) * 132 + r]  = oacc[nt][1] * inv_r;
        Osm[c0 * 132 + r8]       = oacc[nt][2] * inv_r8;
        Osm[(c0 + 1) * 132 + r8] = oacc[nt][3] * inv_r8;
    }
    __syncthreads();

    // ---- coalesced global epilogue ----
    if (!vertical) {
#pragma unroll
        for (int i = 0; i < 8; i++) {
            int e = tid + (i << 8);
            int c = e >> 5, p4 = (e & 31) << 2;
            float4 v4 = *(const float4*)&Osm[c * 132 + p4];
            size_t off = ((size_t)(bb * CTOT + head * CHV + c) * HW + line) * HW + p4;
            *(float4*)&g_oh[off] = v4;
        }
    } else {
        const float g = gamma[0];
#pragma unroll
        for (int i = 0; i < 8; i++) {
            int e = tid + (i << 8);
            int c = e >> 5, p4 = (e & 31) << 2;
            float4 ov = *(const float4*)&Osm[c * 132 + p4];
            size_t off = ((size_t)(bb * CTOT + head * CHV + c) * HW + line) * HW + p4;
            float4 oh = *(const float4*)&g_oh[off];
            float4 xv = *(const float4*)&x[off];
            float4 r4;
            r4.x = g * (oh.x + ov.x) + xv.x;
            r4.y = g * (oh.y + ov.y) + xv.y;
            r4.z = g * (oh.z + ov.z) + xv.z;
            r4.w = g * (oh.w + ov.w) + xv.w;
            *(float4*)&out[off] = r4;
        }
    }
}

// ---------------- launch ----------------
extern "C" void kernel_launch(void* const* d_in, const int* in_sizes, int n_in,
                              void* d_out, int out_size)
{
    const float* x     = (const float*)d_in[0];
    const float* Wq    = (const float*)d_in[1];
    const float* bq    = (const float*)d_in[2];
    const float* Wk    = (const float*)d_in[3];
    const float* bk    = (const float*)d_in[4];
    const float* Wv    = (const float*)d_in[5];
    const float* bv    = (const float*)d_in[6];
    const float* gamma = (const float*)d_in[7];
    float* out = (float*)d_out;

    proj_kernel<<<dim3(128, 5, 4), 256>>>(x, Wq, bq, Wk, bk, Wv, bv);
    transpose_kernel<<<dim3(4, 4, 1280), dim3(32, 8)>>>();

    cudaFuncSetAttribute(attn_mma, cudaFuncAttributeMaxDynamicSharedMemorySize, SM_TOTAL);
    attn_mma<<<dim3(HW, 16), 256, SM_TOTAL>>>(0, x, gamma, out);
    attn_mma<<<dim3(HW, 16), 256, SM_TOTAL>>>(1, x, gamma, out);
}

// round 4
// speedup vs baseline: 2.4659x; 1.7600x over previous
#include <cuda_runtime.h>
#include <cuda_fp16.h>
#include <cstdint>

// CrissCrossAttention — R4 (= R3 resubmit after infra failure):
//   1) proj_mma   : QKV 1x1-conv on tensor cores, fp16 3-term split (error ~2^-22)
//   2) transpose  : per-plane 128x128 transposes (for the vertical pass)
//   3) attn_fused : ONE kernel; per (bh,line) CTA does horizontal attention
//                   (O_h staged in smem), then vertical attention, then
//                   out = gamma*(O_h+O_v)+x.  No g_oh global round-trip.

#define BATCH 4
#define CTOT 256
#define HW   128
#define CQ   32
#define CHQ  8
#define CHV  64
#define NPIX (HW*HW)

// ---------------- scratch ----------------
__device__ float g_q [BATCH*CQ  *NPIX];
__device__ float g_k [BATCH*CQ  *NPIX];
__device__ float g_v [BATCH*CTOT*NPIX];
__device__ float g_qT[BATCH*CQ  *NPIX];
__device__ float g_kT[BATCH*CQ  *NPIX];
__device__ float g_vT[BATCH*CTOT*NPIX];

// ---------------- mma helper ----------------
__device__ __forceinline__ void mma16816(float* d, const uint32_t* a, uint32_t b0, uint32_t b1)
{
    asm volatile(
        "mma.sync.aligned.m16n8k16.row.col.f32.f16.f16.f32 "
        "{%0,%1,%2,%3},{%4,%5,%6,%7},{%8,%9},{%0,%1,%2,%3};"
        : "+f"(d[0]), "+f"(d[1]), "+f"(d[2]), "+f"(d[3])
        : "r"(a[0]), "r"(a[1]), "r"(a[2]), "r"(a[3]), "r"(b0), "r"(b1));
}

// ---------------- 1) QKV projection on tensor cores ----------------
// D[m,p] = sum_k W[m,k] X[k,p] per batch; M=320 (5 tiles of 64), N=16384 px, K=256.
// fp16 split: W=Wh+Wl, X=Xh+Xl; D ~= Wh*Xh + Wh*Xl + Wl*Xh (err ~2^-22).
// CTA: 64 m x 128 p, BK=32. 8 warps in 2(m) x 4(p); warp tile 32m x 32p.
#define PJ_WH 0
#define PJ_WL 5120
#define PJ_XH 10240
#define PJ_XL 20480
#define PJ_SM 33792

__global__ __launch_bounds__(256) void proj_mma(
    const float* __restrict__ x,
    const float* __restrict__ Wq, const float* __restrict__ bq,
    const float* __restrict__ Wk, const float* __restrict__ bk,
    const float* __restrict__ Wv, const float* __restrict__ bv)
{
    extern __shared__ char sm[];
    __half*  Wh  = (__half*)(sm + PJ_WH);
    __half*  Wl  = (__half*)(sm + PJ_WL);
    __half2* Xh2 = (__half2*)(sm + PJ_XH);
    __half2* Xl2 = (__half2*)(sm + PJ_XL);
    float*   Osm = (float*)sm;

    const int bb = blockIdx.z;
    const int m0 = blockIdx.y * 64;
    const int p0 = blockIdx.x * 128;
    const int tid = threadIdx.x;
    const int wid = tid >> 5, lane = tid & 31;
    const int wm = wid & 1, wp = wid >> 1;
    const int gr = lane >> 2, gq = lane & 3;

    const float* xb = x + (size_t)bb * CTOT * NPIX;

    float acc[2][4][4];
#pragma unroll
    for (int mt = 0; mt < 2; mt++)
#pragma unroll
        for (int nt = 0; nt < 4; nt++)
#pragma unroll
            for (int j = 0; j < 4; j++) acc[mt][nt][j] = 0.f;

    for (int chunk = 0; chunk < 8; chunk++) {
        const int k0 = chunk * 32;
        // ---- W tile: 64 x 32 ----
#pragma unroll
        for (int i = 0; i < 8; i++) {
            int e = tid + i * 256;
            int m = e >> 5, k = e & 31;
            int r = m0 + m;
            const float* wr;
            if (r < 32)      wr = Wq + (size_t)r * 256;
            else if (r < 64) wr = Wk + (size_t)(r - 32) * 256;
            else             wr = Wv + (size_t)(r - 64) * 256;
            float w = wr[k0 + k];
            __half hh = __float2half_rn(w);
            Wh[m * 40 + k] = hh;
            Wl[m * 40 + k] = __float2half_rn(w - __half2float(hh));
        }
        // ---- X tile as k-pairs: Xh2[p][kq] = (X[2kq][p], X[2kq+1][p]) ----
#pragma unroll
        for (int i = 0; i < 8; i++) {
            int e = tid + i * 256;
            int p = e & 127, kq = e >> 7;
            float x0 = xb[(size_t)(k0 + 2 * kq)     * NPIX + p0 + p];
            float x1 = xb[(size_t)(k0 + 2 * kq + 1) * NPIX + p0 + p];
            __half h0 = __float2half_rn(x0);
            __half h1 = __float2half_rn(x1);
            __half l0 = __float2half_rn(x0 - __half2float(h0));
            __half l1 = __float2half_rn(x1 - __half2float(h1));
            Xh2[p * 20 + kq] = __halves2half2(h0, h1);
            Xl2[p * 20 + kq] = __halves2half2(l0, l1);
        }
        __syncthreads();

#pragma unroll
        for (int s = 0; s < 2; s++) {
            uint32_t Ah[2][4], Al[2][4];
#pragma unroll
            for (int mt = 0; mt < 2; mt++) {
                int base = (wm * 32 + mt * 16 + gr) * 40 + s * 16 + 2 * gq;
                Ah[mt][0] = *(const uint32_t*)&Wh[base];
                Ah[mt][1] = *(const uint32_t*)&Wh[base + 8 * 40];
                Ah[mt][2] = *(const uint32_t*)&Wh[base + 8];
                Ah[mt][3] = *(const uint32_t*)&Wh[base + 8 * 40 + 8];
                Al[mt][0] = *(const uint32_t*)&Wl[base];
                Al[mt][1] = *(const uint32_t*)&Wl[base + 8 * 40];
                Al[mt][2] = *(const uint32_t*)&Wl[base + 8];
                Al[mt][3] = *(const uint32_t*)&Wl[base + 8 * 40 + 8];
            }
#pragma unroll
            for (int nt = 0; nt < 4; nt++) {
                int pb = (wp * 32 + nt * 8 + gr) * 20 + s * 8 + gq;
                uint32_t bh0 = *(const uint32_t*)&Xh2[pb];
                uint32_t bh1 = *(const uint32_t*)&Xh2[pb + 4];
                uint32_t bl0 = *(const uint32_t*)&Xl2[pb];
                uint32_t bl1 = *(const uint32_t*)&Xl2[pb + 4];
#pragma unroll
                for (int mt = 0; mt < 2; mt++) {
                    mma16816(acc[mt][nt], Ah[mt], bh0, bh1);
                    mma16816(acc[mt][nt], Ah[mt], bl0, bl1);
                    mma16816(acc[mt][nt], Al[mt], bh0, bh1);
                }
            }
        }
        __syncthreads();
    }

    // ---- stage to smem, then coalesced routed global stores ----
#pragma unroll
    for (int mt = 0; mt < 2; mt++)
#pragma unroll
        for (int nt = 0; nt < 4; nt++) {
            int row = wm * 32 + mt * 16 + gr;
            int p   = wp * 32 + nt * 8 + 2 * gq;
            Osm[row * 132 + p]           = acc[mt][nt][0];
            Osm[row * 132 + p + 1]       = acc[mt][nt][1];
            Osm[(row + 8) * 132 + p]     = acc[mt][nt][2];
            Osm[(row + 8) * 132 + p + 1] = acc[mt][nt][3];
        }
    __syncthreads();

#pragma unroll
    for (int i = 0; i < 8; i++) {
        int e = tid + i * 256;
        int row = e >> 5, p4 = (e & 31) << 2;
        int r = m0 + row;
        float bias;
        float* dst;
        if (r < 32)      { bias = bq[r];      dst = g_q + (size_t)(bb * CQ   + r)      * NPIX; }
        else if (r < 64) { bias = bk[r - 32]; dst = g_k + (size_t)(bb * CQ   + r - 32) * NPIX; }
        else             { bias = bv[r - 64]; dst = g_v + (size_t)(bb * CTOT + r - 64) * NPIX; }
        float4 v4 = *(float4*)&Osm[row * 132 + p4];
        v4.x += bias; v4.y += bias; v4.z += bias; v4.w += bias;
        *(float4*)&dst[p0 + p4] = v4;
    }
}

// ---------------- 2) per-plane 128x128 transpose ----------------
__global__ void transpose_kernel()
{
    __shared__ float tile[32][33];
    const int pz = blockIdx.z;
    const float* src;
    float* dst;
    if (pz < BATCH * CQ)          { src = g_q + (size_t)pz * NPIX;                 dst = g_qT + (size_t)pz * NPIX; }
    else if (pz < 2 * BATCH * CQ) { int p = pz - BATCH * CQ;     src = g_k + (size_t)p * NPIX; dst = g_kT + (size_t)p * NPIX; }
    else                          { int p = pz - 2 * BATCH * CQ; src = g_v + (size_t)p * NPIX; dst = g_vT + (size_t)p * NPIX; }

    const int x0 = blockIdx.x * 32, y0 = blockIdx.y * 32;
    const int tx = threadIdx.x, ty = threadIdx.y;
#pragma unroll
    for (int j = ty; j < 32; j += 8)
        tile[j][tx] = src[(size_t)(y0 + j) * HW + x0 + tx];
    __syncthreads();
#pragma unroll
    for (int j = ty; j < 32; j += 8)
        dst[(size_t)(x0 + j) * HW + y0 + tx] = tile[tx][j];
}

// ---------------- 3) fused attention (H then V per CTA) ----------------
// smem: Q2 10240 | K2 10240 | Vhi 17408 | Vlo 17408 | OsmH 33792  = 89088 B
// O_v staged in two 32-channel chunks overlaid on Q2/K2 region.
#define SM_Q2   0
#define SM_K2   10240
#define SM_VHI  20480
#define SM_VLO  37888
#define SM_OSM  55296
#define SM_TOTAL 89088

__global__ __launch_bounds__(256, 2) void attn_fused(
    const float* __restrict__ x,
    const float* __restrict__ gamma, float* __restrict__ out)
{
    extern __shared__ char sm[];
    __half* Q2   = (__half*)(sm + SM_Q2);
    __half* K2   = (__half*)(sm + SM_K2);
    __half* Vhi  = (__half*)(sm + SM_VHI);
    __half* Vlo  = (__half*)(sm + SM_VLO);
    float*  OsmH = (float*)(sm + SM_OSM);
    float*  Ost  = (float*)(sm + SM_Q2);   // 32x132 fp32 = 16896 <= 20480

    const int line = blockIdx.x;
    const int bh   = blockIdx.y;
    const int bb = bh >> 2, head = bh & 3;
    const int tid  = threadIdx.x;
    const int wid  = tid >> 5;
    const int lane = tid & 31;
    const int qr   = lane >> 2;
    const int qq   = lane & 3;

    for (int phase = 0; phase < 2; phase++) {
        if (phase) __syncthreads();   // all reads of Q2/K2/V from phase 0 done
        const float* qb = phase ? g_qT : g_q;
        const float* kb = phase ? g_kT : g_k;
        const float* vb = phase ? g_vT : g_v;

        // ---- load q,k; fp16 hi/lo split tables ----
        {
            int c = tid >> 5, p4 = (tid & 31) << 2;
            size_t off = ((size_t)(bb * CQ + head * CHQ + c) * NPIX) + (size_t)line * HW + p4;
            float4 qv = *(const float4*)&qb[off];
            float4 kv = *(const float4*)&kb[off];
            float qa[4] = {qv.x, qv.y, qv.z, qv.w};
            float ka[4] = {kv.x, kv.y, kv.z, kv.w};
#pragma unroll
            for (int j = 0; j < 4; j++) {
                int p = p4 + j;
                __half qh = __float2half_rn(qa[j]);
                __half ql = __float2half_rn(qa[j] - __half2float(qh));
                __half kh = __float2half_rn(ka[j]);
                __half kl = __float2half_rn(ka[j] - __half2float(kh));
                Q2[p * 40 + c]      = qh;
                Q2[p * 40 + c + 8]  = qh;
                Q2[p * 40 + c + 16] = ql;
                Q2[p * 40 + c + 24] = ql;
                K2[p * 40 + c]      = kh;
                K2[p * 40 + c + 8]  = kl;
                K2[p * 40 + c + 16] = kh;
                K2[p * 40 + c + 24] = kl;
            }
        }
        // ---- load V, split hi/lo ----
#pragma unroll
        for (int i = 0; i < 8; i++) {
            int e = tid + (i << 8);
            int c = e >> 5, p4 = (e & 31) << 2;
            size_t off = ((size_t)(bb * CTOT + head * CHV + c) * NPIX) + (size_t)line * HW + p4;
            float4 vv = *(const float4*)&vb[off];
            float va[4] = {vv.x, vv.y, vv.z, vv.w};
#pragma unroll
            for (int j = 0; j < 4; j++) {
                __half vh = __float2half_rn(va[j]);
                __half vl = __float2half_rn(va[j] - __half2float(vh));
                Vhi[c * 136 + p4 + j] = vh;
                Vlo[c * 136 + p4 + j] = vl;
            }
        }
        __syncthreads();

        // ---- E = Qt*K (M=128 p, N=128 g, K=32 split) ----
        float acc[16][4];
#pragma unroll
        for (int nt = 0; nt < 16; nt++)
#pragma unroll
            for (int j = 0; j < 4; j++) acc[nt][j] = 0.f;

        uint32_t afr[2][4];
#pragma unroll
        for (int kt = 0; kt < 2; kt++) {
            int base = (wid * 16 + qr) * 40 + 2 * qq + 16 * kt;
            afr[kt][0] = *(const uint32_t*)&Q2[base];
            afr[kt][1] = *(const uint32_t*)&Q2[base + 8 * 40];
            afr[kt][2] = *(const uint32_t*)&Q2[base + 8];
            afr[kt][3] = *(const uint32_t*)&Q2[base + 8 * 40 + 8];
        }
#pragma unroll
        for (int nt = 0; nt < 16; nt++) {
#pragma unroll
            for (int kt = 0; kt < 2; kt++) {
                int gb = (8 * nt + qr) * 40 + 2 * qq + 16 * kt;
                uint32_t b0 = *(const uint32_t*)&K2[gb];
                uint32_t b1 = *(const uint32_t*)&K2[gb + 8];
                mma16816(acc[nt], afr[kt], b0, b1);
            }
        }

        // ---- softmax in registers ----
        float mr = -1e30f, mr8 = -1e30f;
#pragma unroll
        for (int nt = 0; nt < 16; nt++) {
            mr  = fmaxf(mr,  fmaxf(acc[nt][0], acc[nt][1]));
            mr8 = fmaxf(mr8, fmaxf(acc[nt][2], acc[nt][3]));
        }
        mr  = fmaxf(mr,  __shfl_xor_sync(0xffffffffu, mr, 1));
        mr  = fmaxf(mr,  __shfl_xor_sync(0xffffffffu, mr, 2));
        mr8 = fmaxf(mr8, __shfl_xor_sync(0xffffffffu, mr8, 1));
        mr8 = fmaxf(mr8, __shfl_xor_sync(0xffffffffu, mr8, 2));

        float sr = 0.f, sr8 = 0.f;
#pragma unroll
        for (int nt = 0; nt < 16; nt++) {
            acc[nt][0] = __expf(acc[nt][0] - mr);
            acc[nt][1] = __expf(acc[nt][1] - mr);
            acc[nt][2] = __expf(acc[nt][2] - mr8);
            acc[nt][3] = __expf(acc[nt][3] - mr8);
            sr  += acc[nt][0] + acc[nt][1];
            sr8 += acc[nt][2] + acc[nt][3];
        }
        sr  += __shfl_xor_sync(0xffffffffu, sr, 1);
        sr  += __shfl_xor_sync(0xffffffffu, sr, 2);
        sr8 += __shfl_xor_sync(0xffffffffu, sr8, 1);
        sr8 += __shfl_xor_sync(0xffffffffu, sr8, 2);

        // ---- repack exp(E) C-frags as A-frags ----
        uint32_t Af[8][4];
#pragma unroll
        for (int kt = 0; kt < 8; kt++) {
            __half2 h0 = __floats2half2_rn(acc[2 * kt][0],     acc[2 * kt][1]);
            __half2 h1 = __floats2half2_rn(acc[2 * kt][2],     acc[2 * kt][3]);
            __half2 h2 = __floats2half2_rn(acc[2 * kt + 1][0], acc[2 * kt + 1][1]);
            __half2 h3 = __floats2half2_rn(acc[2 * kt + 1][2], acc[2 * kt + 1][3]);
            Af[kt][0] = *(uint32_t*)&h0;
            Af[kt][1] = *(uint32_t*)&h1;
            Af[kt][2] = *(uint32_t*)&h2;
            Af[kt][3] = *(uint32_t*)&h3;
        }

        // ---- O = A * V^T (V hi + lo passes) ----
        float oacc[8][4];
#pragma unroll
        for (int nt = 0; nt < 8; nt++)
#pragma unroll
            for (int j = 0; j < 4; j++) oacc[nt][j] = 0.f;

#pragma unroll
        for (int kt = 0; kt < 8; kt++) {
#pragma unroll
            for (int nt = 0; nt < 8; nt++) {
                int vb0 = (8 * nt + qr) * 136 + 16 * kt + 2 * qq;
                uint32_t bh0 = *(const uint32_t*)&Vhi[vb0];
                uint32_t bh1 = *(const uint32_t*)&Vhi[vb0 + 8];
                mma16816(oacc[nt], Af[kt], bh0, bh1);
                uint32_t bl0 = *(const uint32_t*)&Vlo[vb0];
                uint32_t bl1 = *(const uint32_t*)&Vlo[vb0 + 8];
                mma16816(oacc[nt], Af[kt], bl0, bl1);
            }
        }

        const float inv_r  = 1.f / sr;
        const float inv_r8 = 1.f / sr8;
        const int   r  = wid * 16 + qr;
        const int   r8 = r + 8;

        if (phase == 0) {
            // stage normalized O_h (c-major) in persistent OsmH
#pragma unroll
            for (int nt = 0; nt < 8; nt++) {
                int c0 = 8 * nt + 2 * qq;
                OsmH[c0 * 132 + r]        = oacc[nt][0] * inv_r;
                OsmH[(c0 + 1) * 132 + r]  = oacc[nt][1] * inv_r;
                OsmH[c0 * 132 + r8]       = oacc[nt][2] * inv_r8;
                OsmH[(c0 + 1) * 132 + r8] = oacc[nt][3] * inv_r8;
            }
            // no sync needed here: phase-1 top syncthreads orders everything
        } else {
            const float g = gamma[0];
#pragma unroll
            for (int half = 0; half < 2; half++) {
                __syncthreads();   // Ost region (Q2/K2) free for staging
#pragma unroll
                for (int nt = half * 4; nt < half * 4 + 4; nt++) {
                    int cg = 8 * nt + 2 * qq;
                    int cl = cg - 32 * half;
                    Ost[cl * 132 + r]        = oacc[nt][0] * inv_r;
                    Ost[(cl + 1) * 132 + r]  = oacc[nt][1] * inv_r;
                    Ost[cl * 132 + r8]       = oacc[nt][2] * inv_r8;
                    Ost[(cl + 1) * 132 + r8] = oacc[nt][3] * inv_r8;
                }
                __syncthreads();
#pragma unroll
                for (int i = 0; i < 4; i++) {
                    int e = tid + (i << 8);
                    int c = e >> 5, p4 = (e & 31) << 2;
                    int cg = c + 32 * half;
                    size_t off = ((size_t)(bb * CTOT + head * CHV + cg) * HW + line) * HW + p4;
                    float4 ov = *(float4*)&Ost[c * 132 + p4];
                    float4 oh = *(float4*)&OsmH[cg * 132 + p4];
                    float4 xv = *(const float4*)&x[off];
                    float4 r4;
                    r4.x = g * (oh.x + ov.x) + xv.x;
                    r4.y = g * (oh.y + ov.y) + xv.y;
                    r4.z = g * (oh.z + ov.z) + xv.z;
                    r4.w = g * (oh.w + ov.w) + xv.w;
                    *(float4*)&out[off] = r4;
                }
            }
        }
    }
}

// ---------------- launch ----------------
extern "C" void kernel_launch(void* const* d_in, const int* in_sizes, int n_in,
                              void* d_out, int out_size)
{
    const float* x     = (const float*)d_in[0];
    const float* Wq    = (const float*)d_in[1];
    const float* bq    = (const float*)d_in[2];
    const float* Wk    = (const float*)d_in[3];
    const float* bk    = (const float*)d_in[4];
    const float* Wv    = (const float*)d_in[5];
    const float* bv    = (const float*)d_in[6];
    const float* gamma = (const float*)d_in[7];
    float* out = (float*)d_out;

    proj_mma<<<dim3(128, 5, 4), 256, PJ_SM>>>(x, Wq, bq, Wk, bk, Wv, bv);
    transpose_kernel<<<dim3(4, 4, 1280), dim3(32, 8)>>>();

    cudaFuncSetAttribute(attn_fused, cudaFuncAttributeMaxDynamicSharedMemorySize, SM_TOTAL);
    attn_fused<<<dim3(HW, 16), 256, SM_TOTAL>>>(x, gamma, out);
}

// round 5
// speedup vs baseline: 2.9407x; 1.1925x over previous
#include <cuda_runtime.h>
#include <cuda_fp16.h>
#include <cstdint>

// CrissCrossAttention — R5:
//   0) convert_w / convert_x : pre-split W and X into fp16 (hi,lo) k-paired words
//   1) proj_mma   : QKV projection, pure copy+HMMA mainloop (no cvt in loop)
//                   epilogue writes q/k as packed (hi,lo) words, v as fp16
//   2) transpose_qk (uint32) + transpose_v (half) for the vertical pass
//   3) attn_fused : H then V attention per CTA; V fp16 (single pass);
//                   E exact 4-term split from packed q/k; out = g*(Oh+Ov)+x

#define BATCH 4
#define CTOT 256
#define HW   128
#define CQ   32
#define CHQ  8
#define CHV  64
#define NPIX (HW*HW)

// ---------------- scratch ----------------
__device__ uint32_t g_q  [BATCH*CQ*NPIX];    // packed (hi,lo)
__device__ uint32_t g_k  [BATCH*CQ*NPIX];
__device__ uint32_t g_qT [BATCH*CQ*NPIX];
__device__ uint32_t g_kT [BATCH*CQ*NPIX];
__device__ __half   g_v  [BATCH*CTOT*NPIX];  // fp16 hi only
__device__ __half   g_vT [BATCH*CTOT*NPIX];
__device__ uint32_t g_xhp[BATCH*128*NPIX];   // (hi_k, hi_{k+1}) pairs
__device__ uint32_t g_xlp[BATCH*128*NPIX];   // (lo_k, lo_{k+1}) pairs
__device__ uint32_t g_whp[320*128];
__device__ uint32_t g_wlp[320*128];

__device__ __forceinline__ uint32_t pack2(__half a, __half b)
{
    __half2 t = __halves2half2(a, b);
    return *(uint32_t*)&t;
}

__device__ __forceinline__ void mma16816(float* d, const uint32_t* a, uint32_t b0, uint32_t b1)
{
    asm volatile(
        "mma.sync.aligned.m16n8k16.row.col.f32.f16.f16.f32 "
        "{%0,%1,%2,%3},{%4,%5,%6,%7},{%8,%9},{%0,%1,%2,%3};"
        : "+f"(d[0]), "+f"(d[1]), "+f"(d[2]), "+f"(d[3])
        : "r"(a[0]), "r"(a[1]), "r"(a[2]), "r"(a[3]), "r"(b0), "r"(b1));
}

// ---------------- 0a) W split/pack ----------------
__global__ void convert_w(const float* __restrict__ Wq,
                          const float* __restrict__ Wk,
                          const float* __restrict__ Wv)
{
    int idx = blockIdx.x * 256 + threadIdx.x;   // m*128 + kq
    if (idx >= 320 * 128) return;
    int m = idx >> 7, kq = idx & 127;
    const float* wr;
    if (m < 32)      wr = Wq + (size_t)m * 256;
    else if (m < 64) wr = Wk + (size_t)(m - 32) * 256;
    else             wr = Wv + (size_t)(m - 64) * 256;
    float w0 = wr[2 * kq], w1 = wr[2 * kq + 1];
    __half h0 = __float2half_rn(w0), h1 = __float2half_rn(w1);
    __half l0 = __float2half_rn(w0 - __half2float(h0));
    __half l1 = __float2half_rn(w1 - __half2float(h1));
    g_whp[idx] = pack2(h0, h1);
    g_wlp[idx] = pack2(l0, l1);
}

// ---------------- 0b) X split/pack ----------------
// g_xhp[b][kq][p] = (hi(x[2kq][p]), hi(x[2kq+1][p])); same for lo.
__global__ __launch_bounds__(256) void convert_x(const float* __restrict__ x)
{
    const int bb = blockIdx.z, kq = blockIdx.y;
    const int p4 = (blockIdx.x * 256 + threadIdx.x) * 4;
    const float* r0 = x + ((size_t)(bb * CTOT + 2 * kq) * NPIX) + p4;
    const float* r1 = r0 + NPIX;
    float4 a = *(const float4*)r0;
    float4 b = *(const float4*)r1;
    float av[4] = {a.x, a.y, a.z, a.w};
    float bv[4] = {b.x, b.y, b.z, b.w};
    uint32_t hw[4], lw[4];
#pragma unroll
    for (int j = 0; j < 4; j++) {
        __half h0 = __float2half_rn(av[j]), h1 = __float2half_rn(bv[j]);
        __half l0 = __float2half_rn(av[j] - __half2float(h0));
        __half l1 = __float2half_rn(bv[j] - __half2float(h1));
        hw[j] = pack2(h0, h1);
        lw[j] = pack2(l0, l1);
    }
    size_t off = (size_t)(bb * 128 + kq) * NPIX + p4;
    *(uint4*)&g_xhp[off] = make_uint4(hw[0], hw[1], hw[2], hw[3]);
    *(uint4*)&g_xlp[off] = make_uint4(lw[0], lw[1], lw[2], lw[3]);
}

// ---------------- 1) QKV projection, copy+HMMA mainloop ----------------
// smem (uint32 words): Wh2s[64][20]=5120B, Wl2s=5120, Xh2s[16][136]=8704, Xl2s=8704
// epilogue overlay Osm[64][132] float = 33792
#define PJ_WH 0
#define PJ_WL 5120
#define PJ_XH 10240
#define PJ_XL 18944
#define PJ_SM 33792

__global__ __launch_bounds__(256) void proj_mma(
    const float* __restrict__ bq, const float* __restrict__ bk,
    const float* __restrict__ bv)
{
    extern __shared__ char sm[];
    uint32_t* Wh2s = (uint32_t*)(sm + PJ_WH);
    uint32_t* Wl2s = (uint32_t*)(sm + PJ_WL);
    uint32_t* Xh2s = (uint32_t*)(sm + PJ_XH);
    uint32_t* Xl2s = (uint32_t*)(sm + PJ_XL);
    float*    Osm  = (float*)sm;

    const int bb = blockIdx.z;
    const int m0 = blockIdx.y * 64;
    const int p0 = blockIdx.x * 128;
    const int tid = threadIdx.x;
    const int wid = tid >> 5, lane = tid & 31;
    const int wm = wid & 1, wp = wid >> 1;
    const int gr = lane >> 2, gq = lane & 3;

    float acc[2][4][4];
#pragma unroll
    for (int mt = 0; mt < 2; mt++)
#pragma unroll
        for (int nt = 0; nt < 4; nt++)
#pragma unroll
            for (int j = 0; j < 4; j++) acc[mt][nt][j] = 0.f;

    for (int chunk = 0; chunk < 8; chunk++) {
        const int kq0 = chunk * 16;
        // W tiles: 64 x 16 words each
#pragma unroll
        for (int i = 0; i < 4; i++) {
            int e = tid + i * 256;
            int m = e >> 4, kq = e & 15;
            size_t goff = (size_t)(m0 + m) * 128 + kq0 + kq;
            Wh2s[m * 20 + kq] = g_whp[goff];
            Wl2s[m * 20 + kq] = g_wlp[goff];
        }
        // X tiles: 16 x 128 words each
#pragma unroll
        for (int i = 0; i < 8; i++) {
            int e = tid + i * 256;
            int kq = e >> 7, p = e & 127;
            size_t goff = (size_t)(bb * 128 + kq0 + kq) * NPIX + p0 + p;
            Xh2s[kq * 136 + p] = g_xhp[goff];
            Xl2s[kq * 136 + p] = g_xlp[goff];
        }
        __syncthreads();

#pragma unroll
        for (int s = 0; s < 2; s++) {
            uint32_t Ah[2][4], Al[2][4];
#pragma unroll
            for (int mt = 0; mt < 2; mt++) {
                int base = (wm * 32 + mt * 16 + gr) * 20 + s * 8 + gq;
                Ah[mt][0] = Wh2s[base];
                Ah[mt][1] = Wh2s[base + 8 * 20];
                Ah[mt][2] = Wh2s[base + 4];
                Ah[mt][3] = Wh2s[base + 8 * 20 + 4];
                Al[mt][0] = Wl2s[base];
                Al[mt][1] = Wl2s[base + 8 * 20];
                Al[mt][2] = Wl2s[base + 4];
                Al[mt][3] = Wl2s[base + 8 * 20 + 4];
            }
#pragma unroll
            for (int nt = 0; nt < 4; nt++) {
                int p  = wp * 32 + nt * 8 + gr;
                int xb = (s * 8 + gq) * 136 + p;
                uint32_t bh0 = Xh2s[xb];
                uint32_t bh1 = Xh2s[xb + 4 * 136];
                uint32_t bl0 = Xl2s[xb];
                uint32_t bl1 = Xl2s[xb + 4 * 136];
#pragma unroll
                for (int mt = 0; mt < 2; mt++) {
                    mma16816(acc[mt][nt], Ah[mt], bh0, bh1);
                    mma16816(acc[mt][nt], Ah[mt], bl0, bl1);
                    mma16816(acc[mt][nt], Al[mt], bh0, bh1);
                }
            }
        }
        __syncthreads();
    }

    // stage to smem
#pragma unroll
    for (int mt = 0; mt < 2; mt++)
#pragma unroll
        for (int nt = 0; nt < 4; nt++) {
            int row = wm * 32 + mt * 16 + gr;
            int p   = wp * 32 + nt * 8 + 2 * gq;
            Osm[row * 132 + p]           = acc[mt][nt][0];
            Osm[row * 132 + p + 1]       = acc[mt][nt][1];
            Osm[(row + 8) * 132 + p]     = acc[mt][nt][2];
            Osm[(row + 8) * 132 + p + 1] = acc[mt][nt][3];
        }
    __syncthreads();

    // routed stores: q/k packed (hi,lo) words, v fp16
#pragma unroll
    for (int i = 0; i < 8; i++) {
        int e = tid + i * 256;
        int row = e >> 5, p4 = (e & 31) << 2;
        int r = m0 + row;
        float4 v4 = *(float4*)&Osm[row * 132 + p4];
        if (r < 64) {
            float bias = (r < 32) ? bq[r] : bk[r - 32];
            uint32_t* dst = (r < 32) ? g_q + (size_t)(bb * CQ + r) * NPIX
                                     : g_k + (size_t)(bb * CQ + r - 32) * NPIX;
            float vv[4] = {v4.x + bias, v4.y + bias, v4.z + bias, v4.w + bias};
            uint32_t w[4];
#pragma unroll
            for (int j = 0; j < 4; j++) {
                __half h = __float2half_rn(vv[j]);
                __half l = __float2half_rn(vv[j] - __half2float(h));
                w[j] = pack2(h, l);
            }
            *(uint4*)&dst[p0 + p4] = make_uint4(w[0], w[1], w[2], w[3]);
        } else {
            float bias = bv[r - 64];
            __half* dst = g_v + (size_t)(bb * CTOT + r - 64) * NPIX;
            __half2 h01 = __floats2half2_rn(v4.x + bias, v4.y + bias);
            __half2 h23 = __floats2half2_rn(v4.z + bias, v4.w + bias);
            uint2 w2 = make_uint2(*(uint32_t*)&h01, *(uint32_t*)&h23);
            *(uint2*)&dst[p0 + p4] = w2;
        }
    }
}

// ---------------- 2a) q/k transpose (uint32 planes) ----------------
__global__ void transpose_qk()
{
    __shared__ uint32_t tile[32][33];
    const int pz = blockIdx.z;   // 0..255
    const uint32_t* src;
    uint32_t* dst;
    if (pz < BATCH * CQ) { src = g_q + (size_t)pz * NPIX; dst = g_qT + (size_t)pz * NPIX; }
    else { int p = pz - BATCH * CQ; src = g_k + (size_t)p * NPIX; dst = g_kT + (size_t)p * NPIX; }

    const int x0 = blockIdx.x * 32, y0 = blockIdx.y * 32;
    const int tx = threadIdx.x, ty = threadIdx.y;
#pragma unroll
    for (int j = ty; j < 32; j += 8)
        tile[j][tx] = src[(size_t)(y0 + j) * HW + x0 + tx];
    __syncthreads();
#pragma unroll
    for (int j = ty; j < 32; j += 8)
        dst[(size_t)(x0 + j) * HW + y0 + tx] = tile[tx][j];
}

// ---------------- 2b) v transpose (half planes, 64x64 tiles) ----------------
__global__ void transpose_v()
{
    __shared__ ushort tile[64][65];
    const int pz = blockIdx.z;   // 0..1023
    const __half* src = g_v  + (size_t)pz * NPIX;
    __half*       dst = g_vT + (size_t)pz * NPIX;
    const int x0 = blockIdx.x * 64, y0 = blockIdx.y * 64;
    const int tx = threadIdx.x, ty = threadIdx.y;

#pragma unroll
    for (int row = ty; row < 64; row += 8) {
        uint32_t w = *(const uint32_t*)&src[(size_t)(y0 + row) * HW + x0 + 2 * tx];
        tile[row][2 * tx]     = (ushort)(w & 0xffff);
        tile[row][2 * tx + 1] = (ushort)(w >> 16);
    }
    __syncthreads();
#pragma unroll
    for (int xo = ty; xo < 64; xo += 8) {
        uint32_t w = (uint32_t)tile[2 * tx][xo] | ((uint32_t)tile[2 * tx + 1][xo] << 16);
        *(uint32_t*)&dst[(size_t)(x0 + xo) * HW + y0 + 2 * tx] = w;
    }
}

// ---------------- 3) fused attention ----------------
// smem: Q2 10240 | K2 10240 | Vhi 17408 | OsmH 33792 = 71680
#define SM_Q2   0
#define SM_K2   10240
#define SM_VHI  20480
#define SM_OSM  37888
#define SM_TOTAL 71680

__global__ __launch_bounds__(256, 2) void attn_fused(
    const float* __restrict__ x,
    const float* __restrict__ gamma, float* __restrict__ out)
{
    extern __shared__ char sm[];
    ushort* Q2u  = (ushort*)(sm + SM_Q2);
    ushort* K2u  = (ushort*)(sm + SM_K2);
    __half* Q2   = (__half*)(sm + SM_Q2);
    __half* K2   = (__half*)(sm + SM_K2);
    __half* Vhi  = (__half*)(sm + SM_VHI);
    float*  OsmH = (float*)(sm + SM_OSM);
    float*  Ost  = (float*)(sm + SM_Q2);   // 32x132 fp32 = 16896 <= 20480

    const int line = blockIdx.x;
    const int bh   = blockIdx.y;
    const int bb = bh >> 2, head = bh & 3;
    const int tid  = threadIdx.x;
    const int wid  = tid >> 5;
    const int lane = tid & 31;
    const int qr   = lane >> 2;
    const int qq   = lane & 3;

    for (int phase = 0; phase < 2; phase++) {
        if (phase) __syncthreads();
        const uint32_t* qb = phase ? g_qT : g_q;
        const uint32_t* kb = phase ? g_kT : g_k;
        const __half*   vb = phase ? g_vT : g_v;

        // ---- q,k staging from packed words (no cvt) ----
        {
            int c = tid >> 5, p4 = (tid & 31) << 2;
            size_t off = ((size_t)(bb * CQ + head * CHQ + c) * NPIX) + (size_t)line * HW + p4;
            uint4 qw = *(const uint4*)&qb[off];
            uint4 kw = *(const uint4*)&kb[off];
            uint32_t qa[4] = {qw.x, qw.y, qw.z, qw.w};
            uint32_t ka[4] = {kw.x, kw.y, kw.z, kw.w};
#pragma unroll
            for (int j = 0; j < 4; j++) {
                int p = p4 + j;
                ushort qh = (ushort)(qa[j] & 0xffff), ql = (ushort)(qa[j] >> 16);
                ushort kh = (ushort)(ka[j] & 0xffff), kl = (ushort)(ka[j] >> 16);
                Q2u[p * 40 + c]      = qh;
                Q2u[p * 40 + c + 8]  = qh;
                Q2u[p * 40 + c + 16] = ql;
                Q2u[p * 40 + c + 24] = ql;
                K2u[p * 40 + c]      = kh;
                K2u[p * 40 + c + 8]  = kl;
                K2u[p * 40 + c + 16] = kh;
                K2u[p * 40 + c + 24] = kl;
            }
        }
        // ---- V staging: straight fp16 copies ----
#pragma unroll
        for (int i = 0; i < 4; i++) {
            int e = tid + (i << 8);
            int c = e >> 4, p8 = (e & 15) << 3;
            size_t off = ((size_t)(bb * CTOT + head * CHV + c) * NPIX) + (size_t)line * HW + p8;
            *(uint4*)&Vhi[c * 136 + p8] = *(const uint4*)&vb[off];
        }
        __syncthreads();

        // ---- E = Qt*K (M=128 p, N=128 g, K=32 split; exact 4-term) ----
        float acc[16][4];
#pragma unroll
        for (int nt = 0; nt < 16; nt++)
#pragma unroll
            for (int j = 0; j < 4; j++) acc[nt][j] = 0.f;

        uint32_t afr[2][4];
#pragma unroll
        for (int kt = 0; kt < 2; kt++) {
            int base = (wid * 16 + qr) * 40 + 2 * qq + 16 * kt;
            afr[kt][0] = *(const uint32_t*)&Q2[base];
            afr[kt][1] = *(const uint32_t*)&Q2[base + 8 * 40];
            afr[kt][2] = *(const uint32_t*)&Q2[base + 8];
            afr[kt][3] = *(const uint32_t*)&Q2[base + 8 * 40 + 8];
        }
#pragma unroll
        for (int nt = 0; nt < 16; nt++) {
#pragma unroll
            for (int kt = 0; kt < 2; kt++) {
                int gb = (8 * nt + qr) * 40 + 2 * qq + 16 * kt;
                uint32_t b0 = *(const uint32_t*)&K2[gb];
                uint32_t b1 = *(const uint32_t*)&K2[gb + 8];
                mma16816(acc[nt], afr[kt], b0, b1);
            }
        }

        // ---- softmax in registers ----
        float mr = -1e30f, mr8 = -1e30f;
#pragma unroll
        for (int nt = 0; nt < 16; nt++) {
            mr  = fmaxf(mr,  fmaxf(acc[nt][0], acc[nt][1]));
            mr8 = fmaxf(mr8, fmaxf(acc[nt][2], acc[nt][3]));
        }
        mr  = fmaxf(mr,  __shfl_xor_sync(0xffffffffu, mr, 1));
        mr  = fmaxf(mr,  __shfl_xor_sync(0xffffffffu, mr, 2));
        mr8 = fmaxf(mr8, __shfl_xor_sync(0xffffffffu, mr8, 1));
        mr8 = fmaxf(mr8, __shfl_xor_sync(0xffffffffu, mr8, 2));

        float sr = 0.f, sr8 = 0.f;
#pragma unroll
        for (int nt = 0; nt < 16; nt++) {
            acc[nt][0] = __expf(acc[nt][0] - mr);
            acc[nt][1] = __expf(acc[nt][1] - mr);
            acc[nt][2] = __expf(acc[nt][2] - mr8);
            acc[nt][3] = __expf(acc[nt][3] - mr8);
            sr  += acc[nt][0] + acc[nt][1];
            sr8 += acc[nt][2] + acc[nt][3];
        }
        sr  += __shfl_xor_sync(0xffffffffu, sr, 1);
        sr  += __shfl_xor_sync(0xffffffffu, sr, 2);
        sr8 += __shfl_xor_sync(0xffffffffu, sr8, 1);
        sr8 += __shfl_xor_sync(0xffffffffu, sr8, 2);

        // ---- repack exp(E) C-frags as A-frags ----
        uint32_t Af[8][4];
#pragma unroll
        for (int kt = 0; kt < 8; kt++) {
            __half2 h0 = __floats2half2_rn(acc[2 * kt][0],     acc[2 * kt][1]);
            __half2 h1 = __floats2half2_rn(acc[2 * kt][2],     acc[2 * kt][3]);
            __half2 h2 = __floats2half2_rn(acc[2 * kt + 1][0], acc[2 * kt + 1][1]);
            __half2 h3 = __floats2half2_rn(acc[2 * kt + 1][2], acc[2 * kt + 1][3]);
            Af[kt][0] = *(uint32_t*)&h0;
            Af[kt][1] = *(uint32_t*)&h1;
            Af[kt][2] = *(uint32_t*)&h2;
            Af[kt][3] = *(uint32_t*)&h3;
        }

        // ---- O = A * V^T (V fp16, single pass) ----
        float oacc[8][4];
#pragma unroll
        for (int nt = 0; nt < 8; nt++)
#pragma unroll
            for (int j = 0; j < 4; j++) oacc[nt][j] = 0.f;

#pragma unroll
        for (int kt = 0; kt < 8; kt++) {
#pragma unroll
            for (int nt = 0; nt < 8; nt++) {
                int vb0 = (8 * nt + qr) * 136 + 16 * kt + 2 * qq;
                uint32_t bh0 = *(const uint32_t*)&Vhi[vb0];
                uint32_t bh1 = *(const uint32_t*)&Vhi[vb0 + 8];
                mma16816(oacc[nt], Af[kt], bh0, bh1);
            }
        }

        const float inv_r  = 1.f / sr;
        const float inv_r8 = 1.f / sr8;
        const int   r  = wid * 16 + qr;
        const int   r8 = r + 8;

        if (phase == 0) {
#pragma unroll
            for (int nt = 0; nt < 8; nt++) {
                int c0 = 8 * nt + 2 * qq;
                OsmH[c0 * 132 + r]        = oacc[nt][0] * inv_r;
                OsmH[(c0 + 1) * 132 + r]  = oacc[nt][1] * inv_r;
                OsmH[c0 * 132 + r8]       = oacc[nt][2] * inv_r8;
                OsmH[(c0 + 1) * 132 + r8] = oacc[nt][3] * inv_r8;
            }
        } else {
            const float g = gamma[0];
#pragma unroll
            for (int half = 0; half < 2; half++) {
                __syncthreads();
#pragma unroll
                for (int nt = half * 4; nt < half * 4 + 4; nt++) {
                    int cg = 8 * nt + 2 * qq;
                    int cl = cg - 32 * half;
                    Ost[cl * 132 + r]        = oacc[nt][0] * inv_r;
                    Ost[(cl + 1) * 132 + r]  = oacc[nt][1] * inv_r;
                    Ost[cl * 132 + r8]       = oacc[nt][2] * inv_r8;
                    Ost[(cl + 1) * 132 + r8] = oacc[nt][3] * inv_r8;
                }
                __syncthreads();
#pragma unroll
                for (int i = 0; i < 4; i++) {
                    int e = tid + (i << 8);
                    int c = e >> 5, p4 = (e & 31) << 2;
                    int cg = c + 32 * half;
                    size_t off = ((size_t)(bb * CTOT + head * CHV + cg) * HW + line) * HW + p4;
                    float4 ov = *(float4*)&Ost[c * 132 + p4];
                    float4 oh = *(float4*)&OsmH[cg * 132 + p4];
                    float4 xv = *(const float4*)&x[off];
                    float4 r4;
                    r4.x = g * (oh.x + ov.x) + xv.x;
                    r4.y = g * (oh.y + ov.y) + xv.y;
                    r4.z = g * (oh.z + ov.z) + xv.z;
                    r4.w = g * (oh.w + ov.w) + xv.w;
                    *(float4*)&out[off] = r4;
                }
            }
        }
    }
}

// ---------------- launch ----------------
extern "C" void kernel_launch(void* const* d_in, const int* in_sizes, int n_in,
                              void* d_out, int out_size)
{
    const float* x     = (const float*)d_in[0];
    const float* Wq    = (const float*)d_in[1];
    const float* bq    = (const float*)d_in[2];
    const float* Wk    = (const float*)d_in[3];
    const float* bk    = (const float*)d_in[4];
    const float* Wv    = (const float*)d_in[5];
    const float* bv    = (const float*)d_in[6];
    const float* gamma = (const float*)d_in[7];
    float* out = (float*)d_out;

    convert_w<<<160, 256>>>(Wq, Wk, Wv);
    convert_x<<<dim3(16, 128, 4), 256>>>(x);
    proj_mma<<<dim3(128, 5, 4), 256, PJ_SM>>>(bq, bk, bv);
    transpose_qk<<<dim3(4, 4, 256), dim3(32, 8)>>>();
    transpose_v<<<dim3(2, 2, 1024), dim3(32, 8)>>>();

    cudaFuncSetAttribute(attn_fused, cudaFuncAttributeMaxDynamicSharedMemorySize, SM_TOTAL);
    attn_fused<<<dim3(HW, 16), 256, SM_TOTAL>>>(x, gamma, out);
}

// round 7
// speedup vs baseline: 2.9541x; 1.0046x over previous
#include <cuda_runtime.h>
#include <cuda_fp16.h>
#include <cstdint>

// CrissCrossAttention — R6:
//   0) convert_w / convert_x : pre-split W and X into fp16 (hi,lo) k-paired words
//   1) proj_mma   : QKV projection; q/k tiles use exact 3-term fp16 split,
//                   V tiles use hi*hi only (v is stored fp16 anyway)
//   2) transpose_qk (uint32) + transpose_v (half)
//   3) attn_fused : H then V attention per CTA; phase-1 q/k globals prefetched
//                   into registers during phase-0 compute.

#define BATCH 4
#define CTOT 256
#define HW   128
#define CQ   32
#define CHQ  8
#define CHV  64
#define NPIX (HW*HW)

// ---------------- scratch ----------------
__device__ uint32_t g_q  [BATCH*CQ*NPIX];    // packed (hi,lo)
__device__ uint32_t g_k  [BATCH*CQ*NPIX];
__device__ uint32_t g_qT [BATCH*CQ*NPIX];
__device__ uint32_t g_kT [BATCH*CQ*NPIX];
__device__ __half   g_v  [BATCH*CTOT*NPIX];  // fp16 hi only
__device__ __half   g_vT [BATCH*CTOT*NPIX];
__device__ uint32_t g_xhp[BATCH*128*NPIX];   // (hi_k, hi_{k+1}) pairs
__device__ uint32_t g_xlp[BATCH*128*NPIX];   // (lo_k, lo_{k+1}) pairs
__device__ uint32_t g_whp[320*128];
__device__ uint32_t g_wlp[320*128];

__device__ __forceinline__ uint32_t pack2(__half a, __half b)
{
    __half2 t = __halves2half2(a, b);
    return *(uint32_t*)&t;
}

__device__ __forceinline__ void mma16816(float* d, const uint32_t* a, uint32_t b0, uint32_t b1)
{
    asm volatile(
        "mma.sync.aligned.m16n8k16.row.col.f32.f16.f16.f32 "
        "{%0,%1,%2,%3},{%4,%5,%6,%7},{%8,%9},{%0,%1,%2,%3};"
        : "+f"(d[0]), "+f"(d[1]), "+f"(d[2]), "+f"(d[3])
        : "r"(a[0]), "r"(a[1]), "r"(a[2]), "r"(a[3]), "r"(b0), "r"(b1));
}

// ---------------- 0a) W split/pack ----------------
__global__ void convert_w(const float* __restrict__ Wq,
                          const float* __restrict__ Wk,
                          const float* __restrict__ Wv)
{
    int idx = blockIdx.x * 256 + threadIdx.x;   // m*128 + kq
    if (idx >= 320 * 128) return;
    int m = idx >> 7, kq = idx & 127;
    const float* wr;
    if (m < 32)      wr = Wq + (size_t)m * 256;
    else if (m < 64) wr = Wk + (size_t)(m - 32) * 256;
    else             wr = Wv + (size_t)(m - 64) * 256;
    float w0 = wr[2 * kq], w1 = wr[2 * kq + 1];
    __half h0 = __float2half_rn(w0), h1 = __float2half_rn(w1);
    __half l0 = __float2half_rn(w0 - __half2float(h0));
    __half l1 = __float2half_rn(w1 - __half2float(h1));
    g_whp[idx] = pack2(h0, h1);
    g_wlp[idx] = pack2(l0, l1);
}

// ---------------- 0b) X split/pack ----------------
__global__ __launch_bounds__(256) void convert_x(const float* __restrict__ x)
{
    const int bb = blockIdx.z, kq = blockIdx.y;
    const int p4 = (blockIdx.x * 256 + threadIdx.x) * 4;
    const float* r0 = x + ((size_t)(bb * CTOT + 2 * kq) * NPIX) + p4;
    const float* r1 = r0 + NPIX;
    float4 a = *(const float4*)r0;
    float4 b = *(const float4*)r1;
    float av[4] = {a.x, a.y, a.z, a.w};
    float bv[4] = {b.x, b.y, b.z, b.w};
    uint32_t hw[4], lw[4];
#pragma unroll
    for (int j = 0; j < 4; j++) {
        __half h0 = __float2half_rn(av[j]), h1 = __float2half_rn(bv[j]);
        __half l0 = __float2half_rn(av[j] - __half2float(h0));
        __half l1 = __float2half_rn(bv[j] - __half2float(h1));
        hw[j] = pack2(h0, h1);
        lw[j] = pack2(l0, l1);
    }
    size_t off = (size_t)(bb * 128 + kq) * NPIX + p4;
    *(uint4*)&g_xhp[off] = make_uint4(hw[0], hw[1], hw[2], hw[3]);
    *(uint4*)&g_xlp[off] = make_uint4(lw[0], lw[1], lw[2], lw[3]);
}

// ---------------- 1) QKV projection ----------------
// q/k tile (blockIdx.y==0): 3-term split.  V tiles: hi*hi only.
#define PJ_WH 0
#define PJ_WL 5120
#define PJ_XH 10240
#define PJ_XL 18944
#define PJ_SM 33792

__global__ __launch_bounds__(256) void proj_mma(
    const float* __restrict__ bq, const float* __restrict__ bk,
    const float* __restrict__ bv)
{
    extern __shared__ char sm[];
    uint32_t* Wh2s = (uint32_t*)(sm + PJ_WH);
    uint32_t* Wl2s = (uint32_t*)(sm + PJ_WL);
    uint32_t* Xh2s = (uint32_t*)(sm + PJ_XH);
    uint32_t* Xl2s = (uint32_t*)(sm + PJ_XL);
    float*    Osm  = (float*)sm;

    const int bb = blockIdx.z;
    const int m0 = blockIdx.y * 64;
    const int p0 = blockIdx.x * 128;
    const bool qk_tile = (blockIdx.y == 0);
    const int tid = threadIdx.x;
    const int wid = tid >> 5, lane = tid & 31;
    const int wm = wid & 1, wp = wid >> 1;
    const int gr = lane >> 2, gq = lane & 3;

    float acc[2][4][4];
#pragma unroll
    for (int mt = 0; mt < 2; mt++)
#pragma unroll
        for (int nt = 0; nt < 4; nt++)
#pragma unroll
            for (int j = 0; j < 4; j++) acc[mt][nt][j] = 0.f;

    for (int chunk = 0; chunk < 8; chunk++) {
        const int kq0 = chunk * 16;
        // W tiles: 64 x 16 words
#pragma unroll
        for (int i = 0; i < 4; i++) {
            int e = tid + i * 256;
            int m = e >> 4, kq = e & 15;
            size_t goff = (size_t)(m0 + m) * 128 + kq0 + kq;
            Wh2s[m * 20 + kq] = g_whp[goff];
            if (qk_tile) Wl2s[m * 20 + kq] = g_wlp[goff];
        }
        // X tiles: 16 x 128 words
#pragma unroll
        for (int i = 0; i < 8; i++) {
            int e = tid + i * 256;
            int kq = e >> 7, p = e & 127;
            size_t goff = (size_t)(bb * 128 + kq0 + kq) * NPIX + p0 + p;
            Xh2s[kq * 136 + p] = g_xhp[goff];
            if (qk_tile) Xl2s[kq * 136 + p] = g_xlp[goff];
        }
        __syncthreads();

#pragma unroll
        for (int s = 0; s < 2; s++) {
            uint32_t Ah[2][4], Al[2][4];
#pragma unroll
            for (int mt = 0; mt < 2; mt++) {
                int base = (wm * 32 + mt * 16 + gr) * 20 + s * 8 + gq;
                Ah[mt][0] = Wh2s[base];
                Ah[mt][1] = Wh2s[base + 8 * 20];
                Ah[mt][2] = Wh2s[base + 4];
                Ah[mt][3] = Wh2s[base + 8 * 20 + 4];
                if (qk_tile) {
                    Al[mt][0] = Wl2s[base];
                    Al[mt][1] = Wl2s[base + 8 * 20];
                    Al[mt][2] = Wl2s[base + 4];
                    Al[mt][3] = Wl2s[base + 8 * 20 + 4];
                }
            }
#pragma unroll
            for (int nt = 0; nt < 4; nt++) {
                int p  = wp * 32 + nt * 8 + gr;
                int xb = (s * 8 + gq) * 136 + p;
                uint32_t bh0 = Xh2s[xb];
                uint32_t bh1 = Xh2s[xb + 4 * 136];
#pragma unroll
                for (int mt = 0; mt < 2; mt++)
                    mma16816(acc[mt][nt], Ah[mt], bh0, bh1);
                if (qk_tile) {
                    uint32_t bl0 = Xl2s[xb];
                    uint32_t bl1 = Xl2s[xb + 4 * 136];
#pragma unroll
                    for (int mt = 0; mt < 2; mt++) {
                        mma16816(acc[mt][nt], Ah[mt], bl0, bl1);
                        mma16816(acc[mt][nt], Al[mt], bh0, bh1);
                    }
                }
            }
        }
        __syncthreads();
    }

    // stage to smem
#pragma unroll
    for (int mt = 0; mt < 2; mt++)
#pragma unroll
        for (int nt = 0; nt < 4; nt++) {
            int row = wm * 32 + mt * 16 + gr;
            int p   = wp * 32 + nt * 8 + 2 * gq;
            Osm[row * 132 + p]           = acc[mt][nt][0];
            Osm[row * 132 + p + 1]       = acc[mt][nt][1];
            Osm[(row + 8) * 132 + p]     = acc[mt][nt][2];
            Osm[(row + 8) * 132 + p + 1] = acc[mt][nt][3];
        }
    __syncthreads();

    // routed stores
#pragma unroll
    for (int i = 0; i < 8; i++) {
        int e = tid + i * 256;
        int row = e >> 5, p4 = (e & 31) << 2;
        int r = m0 + row;
        float4 v4 = *(float4*)&Osm[row * 132 + p4];
        if (r < 64) {
            float bias = (r < 32) ? bq[r] : bk[r - 32];
            uint32_t* dst = (r < 32) ? g_q + (size_t)(bb * CQ + r) * NPIX
                                     : g_k + (size_t)(bb * CQ + r - 32) * NPIX;
            float vv[4] = {v4.x + bias, v4.y + bias, v4.z + bias, v4.w + bias};
            uint32_t w[4];
#pragma unroll
            for (int j = 0; j < 4; j++) {
                __half h = __float2half_rn(vv[j]);
                __half l = __float2half_rn(vv[j] - __half2float(h));
                w[j] = pack2(h, l);
            }
            *(uint4*)&dst[p0 + p4] = make_uint4(w[0], w[1], w[2], w[3]);
        } else {
            float bias = bv[r - 64];
            __half* dst = g_v + (size_t)(bb * CTOT + r - 64) * NPIX;
            __half2 h01 = __floats2half2_rn(v4.x + bias, v4.y + bias);
            __half2 h23 = __floats2half2_rn(v4.z + bias, v4.w + bias);
            uint2 w2 = make_uint2(*(uint32_t*)&h01, *(uint32_t*)&h23);
            *(uint2*)&dst[p0 + p4] = w2;
        }
    }
}

// ---------------- 2a) q/k transpose ----------------
__global__ void transpose_qk()
{
    __shared__ uint32_t tile[32][33];
    const int pz = blockIdx.z;
    const uint32_t* src;
    uint32_t* dst;
    if (pz < BATCH * CQ) { src = g_q + (size_t)pz * NPIX; dst = g_qT + (size_t)pz * NPIX; }
    else { int p = pz - BATCH * CQ; src = g_k + (size_t)p * NPIX; dst = g_kT + (size_t)p * NPIX; }

    const int x0 = blockIdx.x * 32, y0 = blockIdx.y * 32;
    const int tx = threadIdx.x, ty = threadIdx.y;
#pragma unroll
    for (int j = ty; j < 32; j += 8)
        tile[j][tx] = src[(size_t)(y0 + j) * HW + x0 + tx];
    __syncthreads();
#pragma unroll
    for (int j = ty; j < 32; j += 8)
        dst[(size_t)(x0 + j) * HW + y0 + tx] = tile[tx][j];
}

// ---------------- 2b) v transpose ----------------
__global__ void transpose_v()
{
    __shared__ ushort tile[64][65];
    const int pz = blockIdx.z;
    const __half* src = g_v  + (size_t)pz * NPIX;
    __half*       dst = g_vT + (size_t)pz * NPIX;
    const int x0 = blockIdx.x * 64, y0 = blockIdx.y * 64;
    const int tx = threadIdx.x, ty = threadIdx.y;

#pragma unroll
    for (int row = ty; row < 64; row += 8) {
        uint32_t w = *(const uint32_t*)&src[(size_t)(y0 + row) * HW + x0 + 2 * tx];
        tile[row][2 * tx]     = (ushort)(w & 0xffff);
        tile[row][2 * tx + 1] = (ushort)(w >> 16);
    }
    __syncthreads();
#pragma unroll
    for (int xo = ty; xo < 64; xo += 8) {
        uint32_t w = (uint32_t)tile[2 * tx][xo] | ((uint32_t)tile[2 * tx + 1][xo] << 16);
        *(uint32_t*)&dst[(size_t)(x0 + xo) * HW + y0 + 2 * tx] = w;
    }
}

// ---------------- 3) fused attention ----------------
#define SM_Q2   0
#define SM_K2   10240
#define SM_VHI  20480
#define SM_OSM  37888
#define SM_TOTAL 71680

__global__ __launch_bounds__(256, 2) void attn_fused(
    const float* __restrict__ x,
    const float* __restrict__ gamma, float* __restrict__ out)
{
    extern __shared__ char sm[];
    ushort* Q2u  = (ushort*)(sm + SM_Q2);
    ushort* K2u  = (ushort*)(sm + SM_K2);
    __half* Q2   = (__half*)(sm + SM_Q2);
    __half* K2   = (__half*)(sm + SM_K2);
    __half* Vhi  = (__half*)(sm + SM_VHI);
    float*  OsmH = (float*)(sm + SM_OSM);
    float*  Ost  = (float*)(sm + SM_Q2);

    const int line = blockIdx.x;
    const int bh   = blockIdx.y;
    const int bb = bh >> 2, head = bh & 3;
    const int tid  = threadIdx.x;
    const int wid  = tid >> 5;
    const int lane = tid & 31;
    const int qr   = lane >> 2;
    const int qq   = lane & 3;

    // q/k element owned by this thread (same index both phases)
    const int c_qk = tid >> 5, p4_qk = (tid & 31) << 2;
    const size_t qkoff = ((size_t)(bb * CQ + head * CHQ + c_qk) * NPIX) + (size_t)line * HW + p4_qk;

    // phase-0 q/k global loads
    uint4 qw = *(const uint4*)&g_q[qkoff];
    uint4 kw = *(const uint4*)&g_k[qkoff];

    for (int phase = 0; phase < 2; phase++) {
        if (phase) __syncthreads();
        const __half* vb = phase ? g_vT : g_v;

        // ---- stage q/k from regs ----
        {
            uint32_t qa[4] = {qw.x, qw.y, qw.z, qw.w};
            uint32_t ka[4] = {kw.x, kw.y, kw.z, kw.w};
#pragma unroll
            for (int j = 0; j < 4; j++) {
                int p = p4_qk + j;
                ushort qh = (ushort)(qa[j] & 0xffff), ql = (ushort)(qa[j] >> 16);
                ushort kh = (ushort)(ka[j] & 0xffff), kl = (ushort)(ka[j] >> 16);
                Q2u[p * 40 + c_qk]      = qh;
                Q2u[p * 40 + c_qk + 8]  = qh;
                Q2u[p * 40 + c_qk + 16] = ql;
                Q2u[p * 40 + c_qk + 24] = ql;
                K2u[p * 40 + c_qk]      = kh;
                K2u[p * 40 + c_qk + 8]  = kl;
                K2u[p * 40 + c_qk + 16] = kh;
                K2u[p * 40 + c_qk + 24] = kl;
            }
        }
        // ---- stage V ----
#pragma unroll
        for (int i = 0; i < 4; i++) {
            int e = tid + (i << 8);
            int c = e >> 4, p8 = (e & 15) << 3;
            size_t off = ((size_t)(bb * CTOT + head * CHV + c) * NPIX) + (size_t)line * HW + p8;
            *(uint4*)&Vhi[c * 136 + p8] = *(const uint4*)&vb[off];
        }
        __syncthreads();

        // ---- prefetch phase-1 q/k during phase-0 compute ----
        if (phase == 0) {
            qw = *(const uint4*)&g_qT[qkoff];
            kw = *(const uint4*)&g_kT[qkoff];
        }

        // ---- E = Qt*K ----
        float acc[16][4];
#pragma unroll
        for (int nt = 0; nt < 16; nt++)
#pragma unroll
            for (int j = 0; j < 4; j++) acc[nt][j] = 0.f;

        uint32_t afr[2][4];
#pragma unroll
        for (int kt = 0; kt < 2; kt++) {
            int base = (wid * 16 + qr) * 40 + 2 * qq + 16 * kt;
            afr[kt][0] = *(const uint32_t*)&Q2[base];
            afr[kt][1] = *(const uint32_t*)&Q2[base + 8 * 40];
            afr[kt][2] = *(const uint32_t*)&Q2[base + 8];
            afr[kt][3] = *(const uint32_t*)&Q2[base + 8 * 40 + 8];
        }
#pragma unroll
        for (int nt = 0; nt < 16; nt++) {
#pragma unroll
            for (int kt = 0; kt < 2; kt++) {
                int gb = (8 * nt + qr) * 40 + 2 * qq + 16 * kt;
                uint32_t b0 = *(const uint32_t*)&K2[gb];
                uint32_t b1 = *(const uint32_t*)&K2[gb + 8];
                mma16816(acc[nt], afr[kt], b0, b1);
            }
        }

        // ---- softmax in registers ----
        float mr = -1e30f, mr8 = -1e30f;
#pragma unroll
        for (int nt = 0; nt < 16; nt++) {
            mr  = fmaxf(mr,  fmaxf(acc[nt][0], acc[nt][1]));
            mr8 = fmaxf(mr8, fmaxf(acc[nt][2], acc[nt][3]));
        }
        mr  = fmaxf(mr,  __shfl_xor_sync(0xffffffffu, mr, 1));
        mr  = fmaxf(mr,  __shfl_xor_sync(0xffffffffu, mr, 2));
        mr8 = fmaxf(mr8, __shfl_xor_sync(0xffffffffu, mr8, 1));
        mr8 = fmaxf(mr8, __shfl_xor_sync(0xffffffffu, mr8, 2));

        float sr = 0.f, sr8 = 0.f;
#pragma unroll
        for (int nt = 0; nt < 16; nt++) {
            acc[nt][0] = __expf(acc[nt][0] - mr);
            acc[nt][1] = __expf(acc[nt][1] - mr);
            acc[nt][2] = __expf(acc[nt][2] - mr8);
            acc[nt][3] = __expf(acc[nt][3] - mr8);
            sr  += acc[nt][0] + acc[nt][1];
            sr8 += acc[nt][2] + acc[nt][3];
        }
        sr  += __shfl_xor_sync(0xffffffffu, sr, 1);
        sr  += __shfl_xor_sync(0xffffffffu, sr, 2);
        sr8 += __shfl_xor_sync(0xffffffffu, sr8, 1);
        sr8 += __shfl_xor_sync(0xffffffffu, sr8, 2);

        // ---- repack exp(E) C-frags as A-frags ----
        uint32_t Af[8][4];
#pragma unroll
        for (int kt = 0; kt < 8; kt++) {
            __half2 h0 = __floats2half2_rn(acc[2 * kt][0],     acc[2 * kt][1]);
            __half2 h1 = __floats2half2_rn(acc[2 * kt][2],     acc[2 * kt][3]);
            __half2 h2 = __floats2half2_rn(acc[2 * kt + 1][0], acc[2 * kt + 1][1]);
            __half2 h3 = __floats2half2_rn(acc[2 * kt + 1][2], acc[2 * kt + 1][3]);
            Af[kt][0] = *(uint32_t*)&h0;
            Af[kt][1] = *(uint32_t*)&h1;
            Af[kt][2] = *(uint32_t*)&h2;
            Af[kt][3] = *(uint32_t*)&h3;
        }

        // ---- O = A * V^T (fp16 single pass) ----
        float oacc[8][4];
#pragma unroll
        for (int nt = 0; nt < 8; nt++)
#pragma unroll
            for (int j = 0; j < 4; j++) oacc[nt][j] = 0.f;

#pragma unroll
        for (int kt = 0; kt < 8; kt++) {
#pragma unroll
            for (int nt = 0; nt < 8; nt++) {
                int vb0 = (8 * nt + qr) * 136 + 16 * kt + 2 * qq;
                uint32_t bh0 = *(const uint32_t*)&Vhi[vb0];
                uint32_t bh1 = *(const uint32_t*)&Vhi[vb0 + 8];
                mma16816(oacc[nt], Af[kt], bh0, bh1);
            }
        }

        const float inv_r  = 1.f / sr;
        const float inv_r8 = 1.f / sr8;
        const int   r  = wid * 16 + qr;
        const int   r8 = r + 8;

        if (phase == 0) {
#pragma unroll
            for (int nt = 0; nt < 8; nt++) {
                int c0 = 8 * nt + 2 * qq;
                OsmH[c0 * 132 + r]        = oacc[nt][0] * inv_r;
                OsmH[(c0 + 1) * 132 + r]  = oacc[nt][1] * inv_r;
                OsmH[c0 * 132 + r8]       = oacc[nt][2] * inv_r8;
                OsmH[(c0 + 1) * 132 + r8] = oacc[nt][3] * inv_r8;
            }
        } else {
            const float g = gamma[0];
#pragma unroll
            for (int half = 0; half < 2; half++) {
                __syncthreads();
#pragma unroll
                for (int nt = half * 4; nt < half * 4 + 4; nt++) {
                    int cg = 8 * nt + 2 * qq;
                    int cl = cg - 32 * half;
                    Ost[cl * 132 + r]        = oacc[nt][0] * inv_r;
                    Ost[(cl + 1) * 132 + r]  = oacc[nt][1] * inv_r;
                    Ost[cl * 132 + r8]       = oacc[nt][2] * inv_r8;
                    Ost[(cl + 1) * 132 + r8] = oacc[nt][3] * inv_r8;
                }
                __syncthreads();
#pragma unroll
                for (int i = 0; i < 4; i++) {
                    int e = tid + (i << 8);
                    int c = e >> 5, p4 = (e & 31) << 2;
                    int cg = c + 32 * half;
                    size_t off = ((size_t)(bb * CTOT + head * CHV + cg) * HW + line) * HW + p4;
                    float4 ov = *(float4*)&Ost[c * 132 + p4];
                    float4 oh = *(float4*)&OsmH[cg * 132 + p4];
                    float4 xv = *(const float4*)&x[off];
                    float4 r4;
                    r4.x = g * (oh.x + ov.x) + xv.x;
                    r4.y = g * (oh.y + ov.y) + xv.y;
                    r4.z = g * (oh.z + ov.z) + xv.z;
                    r4.w = g * (oh.w + ov.w) + xv.w;
                    *(float4*)&out[off] = r4;
                }
            }
        }
    }
}

// ---------------- launch ----------------
extern "C" void kernel_launch(void* const* d_in, const int* in_sizes, int n_in,
                              void* d_out, int out_size)
{
    const float* x     = (const float*)d_in[0];
    const float* Wq    = (const float*)d_in[1];
    const float* bq    = (const float*)d_in[2];
    const float* Wk    = (const float*)d_in[3];
    const float* bk    = (const float*)d_in[4];
    const float* Wv    = (const float*)d_in[5];
    const float* bv    = (const float*)d_in[6];
    const float* gamma = (const float*)d_in[7];
    float* out = (float*)d_out;

    convert_w<<<160, 256>>>(Wq, Wk, Wv);
    convert_x<<<dim3(16, 128, 4), 256>>>(x);
    proj_mma<<<dim3(128, 5, 4), 256, PJ_SM>>>(bq, bk, bv);
    transpose_qk<<<dim3(4, 4, 256), dim3(32, 8)>>>();
    transpose_v<<<dim3(2, 2, 1024), dim3(32, 8)>>>();

    cudaFuncSetAttribute(attn_fused, cudaFuncAttributeMaxDynamicSharedMemorySize, SM_TOTAL);
    attn_fused<<<dim3(HW, 16), 256, SM_TOTAL>>>(x, gamma, out);
}

// round 9
// speedup vs baseline: 3.4779x; 1.1773x over previous
#include <cuda_runtime.h>
#include <cuda_fp16.h>
#include <cstdint>

// CrissCrossAttention — R9 (= R8 + fixed quad-shfl reduction of softmax sums):
//   1) convert_all : W and X fp16 hi/lo split+pack (one kernel)
//   2) proj_mma    : QKV projection (q/k 3-term split, v hi-only)
//   3) transpose_all: qk(u32) + v(half) plane transposes (one kernel)
//   4) attn_fused  : 3-CTA/SM design — online softmax over 2 g-chunks
//                    (acc 32 regs), compact k8 Qh/Ql/Kh/Kl layout.

#define BATCH 4
#define CTOT 256
#define HW   128
#define CQ   32
#define CHQ  8
#define CHV  64
#define NPIX (HW*HW)

// ---------------- scratch ----------------
__device__ uint32_t g_q  [BATCH*CQ*NPIX];    // packed (hi,lo)
__device__ uint32_t g_k  [BATCH*CQ*NPIX];
__device__ uint32_t g_qT [BATCH*CQ*NPIX];
__device__ uint32_t g_kT [BATCH*CQ*NPIX];
__device__ __half   g_v  [BATCH*CTOT*NPIX];  // fp16 hi only
__device__ __half   g_vT [BATCH*CTOT*NPIX];
__device__ uint32_t g_xhp[BATCH*128*NPIX];
__device__ uint32_t g_xlp[BATCH*128*NPIX];
__device__ uint32_t g_whp[320*128];
__device__ uint32_t g_wlp[320*128];

__device__ __forceinline__ uint32_t pack2(__half a, __half b)
{
    __half2 t = __halves2half2(a, b);
    return *(uint32_t*)&t;
}

__device__ __forceinline__ void mma16816(float* d, const uint32_t* a, uint32_t b0, uint32_t b1)
{
    asm volatile(
        "mma.sync.aligned.m16n8k16.row.col.f32.f16.f16.f32 "
        "{%0,%1,%2,%3},{%4,%5,%6,%7},{%8,%9},{%0,%1,%2,%3};"
        : "+f"(d[0]), "+f"(d[1]), "+f"(d[2]), "+f"(d[3])
        : "r"(a[0]), "r"(a[1]), "r"(a[2]), "r"(a[3]), "r"(b0), "r"(b1));
}

__device__ __forceinline__ void mma1688(float* d, uint32_t a0, uint32_t a1, uint32_t b0)
{
    asm volatile(
        "mma.sync.aligned.m16n8k8.row.col.f32.f16.f16.f32 "
        "{%0,%1,%2,%3},{%4,%5},{%6},{%0,%1,%2,%3};"
        : "+f"(d[0]), "+f"(d[1]), "+f"(d[2]), "+f"(d[3])
        : "r"(a0), "r"(a1), "r"(b0));
}

// ---------------- 1) merged convert (X part + W part) ----------------
__global__ __launch_bounds__(256) void convert_all(
    const float* __restrict__ x,
    const float* __restrict__ Wq, const float* __restrict__ Wk,
    const float* __restrict__ Wv)
{
    const int gid = blockIdx.x;
    if (gid < 8192) {
        const int bb = gid >> 11;
        const int kq = (gid >> 4) & 127;
        const int px = gid & 15;
        const int p4 = (px * 256 + threadIdx.x) * 4;
        const float* r0 = x + ((size_t)(bb * CTOT + 2 * kq) * NPIX) + p4;
        const float* r1 = r0 + NPIX;
        float4 a = *(const float4*)r0;
        float4 b = *(const float4*)r1;
        float av[4] = {a.x, a.y, a.z, a.w};
        float bv[4] = {b.x, b.y, b.z, b.w};
        uint32_t hw[4], lw[4];
#pragma unroll
        for (int j = 0; j < 4; j++) {
            __half h0 = __float2half_rn(av[j]), h1 = __float2half_rn(bv[j]);
            __half l0 = __float2half_rn(av[j] - __half2float(h0));
            __half l1 = __float2half_rn(bv[j] - __half2float(h1));
            hw[j] = pack2(h0, h1);
            lw[j] = pack2(l0, l1);
        }
        size_t off = (size_t)(bb * 128 + kq) * NPIX + p4;
        *(uint4*)&g_xhp[off] = make_uint4(hw[0], hw[1], hw[2], hw[3]);
        *(uint4*)&g_xlp[off] = make_uint4(lw[0], lw[1], lw[2], lw[3]);
    } else {
        int idx = (gid - 8192) * 256 + threadIdx.x;
        if (idx >= 320 * 128) return;
        int m = idx >> 7, kq = idx & 127;
        const float* wr;
        if (m < 32)      wr = Wq + (size_t)m * 256;
        else if (m < 64) wr = Wk + (size_t)(m - 32) * 256;
        else             wr = Wv + (size_t)(m - 64) * 256;
        float w0 = wr[2 * kq], w1 = wr[2 * kq + 1];
        __half h0 = __float2half_rn(w0), h1 = __float2half_rn(w1);
        __half l0 = __float2half_rn(w0 - __half2float(h0));
        __half l1 = __float2half_rn(w1 - __half2float(h1));
        g_whp[idx] = pack2(h0, h1);
        g_wlp[idx] = pack2(l0, l1);
    }
}

// ---------------- 2) QKV projection ----------------
#define PJ_WH 0
#define PJ_WL 5120
#define PJ_XH 10240
#define PJ_XL 18944
#define PJ_SM 33792

__global__ __launch_bounds__(256) void proj_mma(
    const float* __restrict__ bq, const float* __restrict__ bk,
    const float* __restrict__ bv)
{
    extern __shared__ char sm[];
    uint32_t* Wh2s = (uint32_t*)(sm + PJ_WH);
    uint32_t* Wl2s = (uint32_t*)(sm + PJ_WL);
    uint32_t* Xh2s = (uint32_t*)(sm + PJ_XH);
    uint32_t* Xl2s = (uint32_t*)(sm + PJ_XL);
    float*    Osm  = (float*)sm;

    const int bb = blockIdx.z;
    const int m0 = blockIdx.y * 64;
    const int p0 = blockIdx.x * 128;
    const bool qk_tile = (blockIdx.y == 0);
    const int tid = threadIdx.x;
    const int wid = tid >> 5, lane = tid & 31;
    const int wm = wid & 1, wp = wid >> 1;
    const int gr = lane >> 2, gq = lane & 3;

    float acc[2][4][4];
#pragma unroll
    for (int mt = 0; mt < 2; mt++)
#pragma unroll
        for (int nt = 0; nt < 4; nt++)
#pragma unroll
            for (int j = 0; j < 4; j++) acc[mt][nt][j] = 0.f;

    for (int chunk = 0; chunk < 8; chunk++) {
        const int kq0 = chunk * 16;
#pragma unroll
        for (int i = 0; i < 4; i++) {
            int e = tid + i * 256;
            int m = e >> 4, kq = e & 15;
            size_t goff = (size_t)(m0 + m) * 128 + kq0 + kq;
            Wh2s[m * 20 + kq] = g_whp[goff];
            if (qk_tile) Wl2s[m * 20 + kq] = g_wlp[goff];
        }
#pragma unroll
        for (int i = 0; i < 8; i++) {
            int e = tid + i * 256;
            int kq = e >> 7, p = e & 127;
            size_t goff = (size_t)(bb * 128 + kq0 + kq) * NPIX + p0 + p;
            Xh2s[kq * 136 + p] = g_xhp[goff];
            if (qk_tile) Xl2s[kq * 136 + p] = g_xlp[goff];
        }
        __syncthreads();

#pragma unroll
        for (int s = 0; s < 2; s++) {
            uint32_t Ah[2][4], Al[2][4];
#pragma unroll
            for (int mt = 0; mt < 2; mt++) {
                int base = (wm * 32 + mt * 16 + gr) * 20 + s * 8 + gq;
                Ah[mt][0] = Wh2s[base];
                Ah[mt][1] = Wh2s[base + 8 * 20];
                Ah[mt][2] = Wh2s[base + 4];
                Ah[mt][3] = Wh2s[base + 8 * 20 + 4];
                if (qk_tile) {
                    Al[mt][0] = Wl2s[base];
                    Al[mt][1] = Wl2s[base + 8 * 20];
                    Al[mt][2] = Wl2s[base + 4];
                    Al[mt][3] = Wl2s[base + 8 * 20 + 4];
                }
            }
#pragma unroll
            for (int nt = 0; nt < 4; nt++) {
                int p  = wp * 32 + nt * 8 + gr;
                int xb = (s * 8 + gq) * 136 + p;
                uint32_t bh0 = Xh2s[xb];
                uint32_t bh1 = Xh2s[xb + 4 * 136];
#pragma unroll
                for (int mt = 0; mt < 2; mt++)
                    mma16816(acc[mt][nt], Ah[mt], bh0, bh1);
                if (qk_tile) {
                    uint32_t bl0 = Xl2s[xb];
                    uint32_t bl1 = Xl2s[xb + 4 * 136];
#pragma unroll
                    for (int mt = 0; mt < 2; mt++) {
                        mma16816(acc[mt][nt], Ah[mt], bl0, bl1);
                        mma16816(acc[mt][nt], Al[mt], bh0, bh1);
                    }
                }
            }
        }
        __syncthreads();
    }

#pragma unroll
    for (int mt = 0; mt < 2; mt++)
#pragma unroll
        for (int nt = 0; nt < 4; nt++) {
            int row = wm * 32 + mt * 16 + gr;
            int p   = wp * 32 + nt * 8 + 2 * gq;
            Osm[row * 132 + p]           = acc[mt][nt][0];
            Osm[row * 132 + p + 1]       = acc[mt][nt][1];
            Osm[(row + 8) * 132 + p]     = acc[mt][nt][2];
            Osm[(row + 8) * 132 + p + 1] = acc[mt][nt][3];
        }
    __syncthreads();

#pragma unroll
    for (int i = 0; i < 8; i++) {
        int e = tid + i * 256;
        int row = e >> 5, p4 = (e & 31) << 2;
        int r = m0 + row;
        float4 v4 = *(float4*)&Osm[row * 132 + p4];
        if (r < 64) {
            float bias = (r < 32) ? bq[r] : bk[r - 32];
            uint32_t* dst = (r < 32) ? g_q + (size_t)(bb * CQ + r) * NPIX
                                     : g_k + (size_t)(bb * CQ + r - 32) * NPIX;
            float vv[4] = {v4.x + bias, v4.y + bias, v4.z + bias, v4.w + bias};
            uint32_t w[4];
#pragma unroll
            for (int j = 0; j < 4; j++) {
                __half h = __float2half_rn(vv[j]);
                __half l = __float2half_rn(vv[j] - __half2float(h));
                w[j] = pack2(h, l);
            }
            *(uint4*)&dst[p0 + p4] = make_uint4(w[0], w[1], w[2], w[3]);
        } else {
            float bias = bv[r - 64];
            __half* dst = g_v + (size_t)(bb * CTOT + r - 64) * NPIX;
            __half2 h01 = __floats2half2_rn(v4.x + bias, v4.y + bias);
            __half2 h23 = __floats2half2_rn(v4.z + bias, v4.w + bias);
            uint2 w2 = make_uint2(*(uint32_t*)&h01, *(uint32_t*)&h23);
            *(uint2*)&dst[p0 + p4] = w2;
        }
    }
}

// ---------------- 3) merged transposes ----------------
__global__ void transpose_all()
{
    __shared__ char sbuf[64 * 65 * 2];
    const int z = blockIdx.z;
    const int tx = threadIdx.x, ty = threadIdx.y;

    if (z < 256) {
        uint32_t (*tile)[33] = (uint32_t(*)[33])sbuf;
        const uint32_t* src;
        uint32_t* dst;
        if (z < BATCH * CQ) { src = g_q + (size_t)z * NPIX; dst = g_qT + (size_t)z * NPIX; }
        else { int p = z - BATCH * CQ; src = g_k + (size_t)p * NPIX; dst = g_kT + (size_t)p * NPIX; }
        const int x0 = blockIdx.x * 32, y0 = blockIdx.y * 32;
#pragma unroll
        for (int j = ty; j < 32; j += 8)
            tile[j][tx] = src[(size_t)(y0 + j) * HW + x0 + tx];
        __syncthreads();
#pragma unroll
        for (int j = ty; j < 32; j += 8)
            dst[(size_t)(x0 + j) * HW + y0 + tx] = tile[tx][j];
    } else {
        if (blockIdx.x >= 2 || blockIdx.y >= 2) return;
        ushort (*tile)[65] = (ushort(*)[65])sbuf;
        const int pz = z - 256;
        const __half* src = g_v  + (size_t)pz * NPIX;
        __half*       dst = g_vT + (size_t)pz * NPIX;
        const int x0 = blockIdx.x * 64, y0 = blockIdx.y * 64;
#pragma unroll
        for (int row = ty; row < 64; row += 8) {
            uint32_t w = *(const uint32_t*)&src[(size_t)(y0 + row) * HW + x0 + 2 * tx];
            tile[row][2 * tx]     = (ushort)(w & 0xffff);
            tile[row][2 * tx + 1] = (ushort)(w >> 16);
        }
        __syncthreads();
#pragma unroll
        for (int xo = ty; xo < 64; xo += 8) {
            uint32_t w = (uint32_t)tile[2 * tx][xo] | ((uint32_t)tile[2 * tx + 1][xo] << 16);
            *(uint32_t*)&dst[(size_t)(x0 + xo) * HW + y0 + 2 * tx] = w;
        }
    }
}

// ---------------- 4) fused attention, 3 CTA/SM ----------------
#define SM_QH  0
#define SM_QL  2048
#define SM_KH  4096
#define SM_KL  6144
#define SM_V   8192
#define SM_OSM 25600
#define SM_TOTAL 59392

__global__ __launch_bounds__(256, 3) void attn_fused(
    const float* __restrict__ x,
    const float* __restrict__ gamma, float* __restrict__ out)
{
    extern __shared__ char sm[];
    __half* sQh  = (__half*)(sm + SM_QH);
    __half* sQl  = (__half*)(sm + SM_QL);
    __half* sKh  = (__half*)(sm + SM_KH);
    __half* sKl  = (__half*)(sm + SM_KL);
    __half* Vhi  = (__half*)(sm + SM_V);
    float*  OsmH = (float*)(sm + SM_OSM);
    float*  Ost  = (float*)(sm + SM_V);

    const int line = blockIdx.x;
    const int bh   = blockIdx.y;
    const int bb = bh >> 2, head = bh & 3;
    const int tid  = threadIdx.x;
    const int wid  = tid >> 5;
    const int lane = tid & 31;
    const int qr   = lane >> 2;
    const int qq   = lane & 3;

    const int p_st = tid & 127;
    const int hc   = tid >> 7;

    for (int phase = 0; phase < 2; phase++) {
        if (phase) __syncthreads();
        const uint32_t* qb = phase ? g_qT : g_q;
        const uint32_t* kb = phase ? g_kT : g_k;
        const __half*   vb = phase ? g_vT : g_v;

        // ---- stage q/k into compact hi/lo arrays ----
        {
            size_t base = ((size_t)(bb * CQ + head * CHQ + 4 * hc) * NPIX)
                        + (size_t)line * HW + p_st;
            uint32_t qv[4], kv[4];
#pragma unroll
            for (int j = 0; j < 4; j++) {
                qv[j] = qb[base + (size_t)j * NPIX];
                kv[j] = kb[base + (size_t)j * NPIX];
            }
            uint2 qhi, qlo, khi, klo;
            qhi.x = (qv[0] & 0xffffu) | (qv[1] << 16);
            qhi.y = (qv[2] & 0xffffu) | (qv[3] << 16);
            qlo.x = (qv[0] >> 16) | (qv[1] & 0xffff0000u);
            qlo.y = (qv[2] >> 16) | (qv[3] & 0xffff0000u);
            khi.x = (kv[0] & 0xffffu) | (kv[1] << 16);
            khi.y = (kv[2] & 0xffffu) | (kv[3] << 16);
            klo.x = (kv[0] >> 16) | (kv[1] & 0xffff0000u);
            klo.y = (kv[2] >> 16) | (kv[3] & 0xffff0000u);
            int so = p_st * 8 + 4 * hc;
            *(uint2*)&sQh[so] = qhi;
            *(uint2*)&sQl[so] = qlo;
            *(uint2*)&sKh[so] = khi;
            *(uint2*)&sKl[so] = klo;
        }
        // ---- stage V ----
#pragma unroll
        for (int i = 0; i < 4; i++) {
            int e = tid + (i << 8);
            int c = e >> 4, p8 = (e & 15) << 3;
            size_t off = ((size_t)(bb * CTOT + head * CHV + c) * NPIX) + (size_t)line * HW + p8;
            *(uint4*)&Vhi[c * 136 + p8] = *(const uint4*)&vb[off];
        }
        __syncthreads();

        // ---- A-frags (k=8, whole channel dim) ----
        const int aoff = (wid * 16 + qr) * 8 + 2 * qq;
        uint32_t aQh0 = *(const uint32_t*)&sQh[aoff];
        uint32_t aQh1 = *(const uint32_t*)&sQh[aoff + 64];
        uint32_t aQl0 = *(const uint32_t*)&sQl[aoff];
        uint32_t aQl1 = *(const uint32_t*)&sQl[aoff + 64];

        float mr = -1e30f, mr8 = -1e30f, sr = 0.f, sr8 = 0.f;
        float oacc[8][4];
#pragma unroll
        for (int nt = 0; nt < 8; nt++)
#pragma unroll
            for (int j = 0; j < 4; j++) oacc[nt][j] = 0.f;

#pragma unroll
        for (int ch = 0; ch < 2; ch++) {
            // ---- E chunk ----
            float acc[8][4];
#pragma unroll
            for (int nt = 0; nt < 8; nt++)
#pragma unroll
                for (int j = 0; j < 4; j++) acc[nt][j] = 0.f;
#pragma unroll
            for (int nt = 0; nt < 8; nt++) {
                int kbx = (ch * 64 + nt * 8 + qr) * 8 + 2 * qq;
                uint32_t bhh = *(const uint32_t*)&sKh[kbx];
                uint32_t bll = *(const uint32_t*)&sKl[kbx];
                mma1688(acc[nt], aQh0, aQh1, bhh);
                mma1688(acc[nt], aQh0, aQh1, bll);
                mma1688(acc[nt], aQl0, aQl1, bhh);
            }

            // ---- online softmax update ----
            float cm = -1e30f, cm8 = -1e30f;
#pragma unroll
            for (int nt = 0; nt < 8; nt++) {
                cm  = fmaxf(cm,  fmaxf(acc[nt][0], acc[nt][1]));
                cm8 = fmaxf(cm8, fmaxf(acc[nt][2], acc[nt][3]));
            }
            cm  = fmaxf(cm,  __shfl_xor_sync(0xffffffffu, cm, 1));
            cm  = fmaxf(cm,  __shfl_xor_sync(0xffffffffu, cm, 2));
            cm8 = fmaxf(cm8, __shfl_xor_sync(0xffffffffu, cm8, 1));
            cm8 = fmaxf(cm8, __shfl_xor_sync(0xffffffffu, cm8, 2));

            float nm  = fmaxf(mr, cm);
            float nm8 = fmaxf(mr8, cm8);
            float sc  = __expf(mr - nm);
            float sc8 = __expf(mr8 - nm8);
            mr = nm; mr8 = nm8;
            sr *= sc; sr8 *= sc8;
#pragma unroll
            for (int nt = 0; nt < 8; nt++) {
                oacc[nt][0] *= sc;  oacc[nt][1] *= sc;
                oacc[nt][2] *= sc8; oacc[nt][3] *= sc8;
            }

            float cs = 0.f, cs8 = 0.f;
#pragma unroll
            for (int nt = 0; nt < 8; nt++) {
                acc[nt][0] = __expf(acc[nt][0] - nm);
                acc[nt][1] = __expf(acc[nt][1] - nm);
                acc[nt][2] = __expf(acc[nt][2] - nm8);
                acc[nt][3] = __expf(acc[nt][3] - nm8);
                cs  += acc[nt][0] + acc[nt][1];
                cs8 += acc[nt][2] + acc[nt][3];
            }
            // FIX (R8 bug): reduce partial sums across the quad
            cs  += __shfl_xor_sync(0xffffffffu, cs, 1);
            cs  += __shfl_xor_sync(0xffffffffu, cs, 2);
            cs8 += __shfl_xor_sync(0xffffffffu, cs8, 1);
            cs8 += __shfl_xor_sync(0xffffffffu, cs8, 2);
            sr  += cs;  sr8 += cs8;

            // ---- repack exp(E) as A-frags ----
            uint32_t Af[4][4];
#pragma unroll
            for (int kt = 0; kt < 4; kt++) {
                __half2 h0 = __floats2half2_rn(acc[2 * kt][0],     acc[2 * kt][1]);
                __half2 h1 = __floats2half2_rn(acc[2 * kt][2],     acc[2 * kt][3]);
                __half2 h2 = __floats2half2_rn(acc[2 * kt + 1][0], acc[2 * kt + 1][1]);
                __half2 h3 = __floats2half2_rn(acc[2 * kt + 1][2], acc[2 * kt + 1][3]);
                Af[kt][0] = *(uint32_t*)&h0;
                Af[kt][1] = *(uint32_t*)&h1;
                Af[kt][2] = *(uint32_t*)&h2;
                Af[kt][3] = *(uint32_t*)&h3;
            }

            // ---- accumulate O over this chunk ----
#pragma unroll
            for (int kt = 0; kt < 4; kt++) {
#pragma unroll
                for (int nt = 0; nt < 8; nt++) {
                    int vb0 = (8 * nt + qr) * 136 + ch * 64 + 16 * kt + 2 * qq;
                    uint32_t bh0 = *(const uint32_t*)&Vhi[vb0];
                    uint32_t bh1 = *(const uint32_t*)&Vhi[vb0 + 8];
                    mma16816(oacc[nt], Af[kt], bh0, bh1);
                }
            }
        }

        const float inv_r  = 1.f / sr;
        const float inv_r8 = 1.f / sr8;
        const int   r  = wid * 16 + qr;
        const int   r8 = r + 8;

        if (phase == 0) {
#pragma unroll
            for (int nt = 0; nt < 8; nt++) {
                int c0 = 8 * nt + 2 * qq;
                OsmH[c0 * 132 + r]        = oacc[nt][0] * inv_r;
                OsmH[(c0 + 1) * 132 + r]  = oacc[nt][1] * inv_r;
                OsmH[c0 * 132 + r8]       = oacc[nt][2] * inv_r8;
                OsmH[(c0 + 1) * 132 + r8] = oacc[nt][3] * inv_r8;
            }
        } else {
            const float g = gamma[0];
#pragma unroll
            for (int half = 0; half < 2; half++) {
                __syncthreads();
#pragma unroll
                for (int nt = half * 4; nt < half * 4 + 4; nt++) {
                    int cg = 8 * nt + 2 * qq;
                    int cl = cg - 32 * half;
                    Ost[cl * 132 + r]        = oacc[nt][0] * inv_r;
                    Ost[(cl + 1) * 132 + r]  = oacc[nt][1] * inv_r;
                    Ost[cl * 132 + r8]       = oacc[nt][2] * inv_r8;
                    Ost[(cl + 1) * 132 + r8] = oacc[nt][3] * inv_r8;
                }
                __syncthreads();
#pragma unroll
                for (int i = 0; i < 4; i++) {
                    int e = tid + (i << 8);
                    int c = e >> 5, p4 = (e & 31) << 2;
                    int cg = c + 32 * half;
                    size_t off = ((size_t)(bb * CTOT + head * CHV + cg) * HW + line) * HW + p4;
                    float4 ov = *(float4*)&Ost[c * 132 + p4];
                    float4 oh = *(float4*)&OsmH[cg * 132 + p4];
                    float4 xv = *(const float4*)&x[off];
                    float4 r4;
                    r4.x = g * (oh.x + ov.x) + xv.x;
                    r4.y = g * (oh.y + ov.y) + xv.y;
                    r4.z = g * (oh.z + ov.z) + xv.z;
                    r4.w = g * (oh.w + ov.w) + xv.w;
                    *(float4*)&out[off] = r4;
                }
            }
        }
    }
}

// ---------------- launch ----------------
extern "C" void kernel_launch(void* const* d_in, const int* in_sizes, int n_in,
                              void* d_out, int out_size)
{
    const float* x     = (const float*)d_in[0];
    const float* Wq    = (const float*)d_in[1];
    const float* bq    = (const float*)d_in[2];
    const float* Wk    = (const float*)d_in[3];
    const float* bk    = (const float*)d_in[4];
    const float* Wv    = (const float*)d_in[5];
    const float* bv    = (const float*)d_in[6];
    const float* gamma = (const float*)d_in[7];
    float* out = (float*)d_out;

    convert_all<<<8352, 256>>>(x, Wq, Wk, Wv);
    proj_mma<<<dim3(128, 5, 4), 256, PJ_SM>>>(bq, bk, bv);
    transpose_all<<<dim3(4, 4, 1280), dim3(32, 8)>>>();

    cudaFuncSetAttribute(attn_fused, cudaFuncAttributeMaxDynamicSharedMemorySize, SM_TOTAL);
    attn_fused<<<dim3(HW, 16), 256, SM_TOTAL>>>(x, gamma, out);
}

// round 10
// speedup vs baseline: 4.3268x; 1.2441x over previous
#include <cuda_runtime.h>
#include <cuda_fp16.h>
#include <cstdint>

// CrissCrossAttention — R10:
//   1) convert_all : W and X fp16 hi/lo split+pack
//   2) proj_qk     : q/k rows, exact 3-term split, register-prefetch pipeline
//      proj_v      : v rows, hi-only 1-term, prefetch + 3 CTA/SM
//   3) transpose_all: fat tiles (qk 64x128 u32 / v full-plane half)
//   4) attn_fused  : unchanged R9 (3 CTA/SM online-softmax design)

#define BATCH 4
#define CTOT 256
#define HW   128
#define CQ   32
#define CHQ  8
#define CHV  64
#define NPIX (HW*HW)

// ---------------- scratch ----------------
__device__ uint32_t g_q  [BATCH*CQ*NPIX];    // packed (hi,lo)
__device__ uint32_t g_k  [BATCH*CQ*NPIX];
__device__ uint32_t g_qT [BATCH*CQ*NPIX];
__device__ uint32_t g_kT [BATCH*CQ*NPIX];
__device__ __half   g_v  [BATCH*CTOT*NPIX];  // fp16 hi only
__device__ __half   g_vT [BATCH*CTOT*NPIX];
__device__ uint32_t g_xhp[BATCH*128*NPIX];
__device__ uint32_t g_xlp[BATCH*128*NPIX];
__device__ uint32_t g_whp[320*128];
__device__ uint32_t g_wlp[320*128];

__device__ __forceinline__ uint32_t pack2(__half a, __half b)
{
    __half2 t = __halves2half2(a, b);
    return *(uint32_t*)&t;
}

__device__ __forceinline__ void mma16816(float* d, const uint32_t* a, uint32_t b0, uint32_t b1)
{
    asm volatile(
        "mma.sync.aligned.m16n8k16.row.col.f32.f16.f16.f32 "
        "{%0,%1,%2,%3},{%4,%5,%6,%7},{%8,%9},{%0,%1,%2,%3};"
        : "+f"(d[0]), "+f"(d[1]), "+f"(d[2]), "+f"(d[3])
        : "r"(a[0]), "r"(a[1]), "r"(a[2]), "r"(a[3]), "r"(b0), "r"(b1));
}

__device__ __forceinline__ void mma1688(float* d, uint32_t a0, uint32_t a1, uint32_t b0)
{
    asm volatile(
        "mma.sync.aligned.m16n8k8.row.col.f32.f16.f16.f32 "
        "{%0,%1,%2,%3},{%4,%5},{%6},{%0,%1,%2,%3};"
        : "+f"(d[0]), "+f"(d[1]), "+f"(d[2]), "+f"(d[3])
        : "r"(a0), "r"(a1), "r"(b0));
}

// ---------------- 1) merged convert ----------------
__global__ __launch_bounds__(256) void convert_all(
    const float* __restrict__ x,
    const float* __restrict__ Wq, const float* __restrict__ Wk,
    const float* __restrict__ Wv)
{
    const int gid = blockIdx.x;
    if (gid < 8192) {
        const int bb = gid >> 11;
        const int kq = (gid >> 4) & 127;
        const int px = gid & 15;
        const int p4 = (px * 256 + threadIdx.x) * 4;
        const float* r0 = x + ((size_t)(bb * CTOT + 2 * kq) * NPIX) + p4;
        const float* r1 = r0 + NPIX;
        float4 a = *(const float4*)r0;
        float4 b = *(const float4*)r1;
        float av[4] = {a.x, a.y, a.z, a.w};
        float bv[4] = {b.x, b.y, b.z, b.w};
        uint32_t hw[4], lw[4];
#pragma unroll
        for (int j = 0; j < 4; j++) {
            __half h0 = __float2half_rn(av[j]), h1 = __float2half_rn(bv[j]);
            __half l0 = __float2half_rn(av[j] - __half2float(h0));
            __half l1 = __float2half_rn(bv[j] - __half2float(h1));
            hw[j] = pack2(h0, h1);
            lw[j] = pack2(l0, l1);
        }
        size_t off = (size_t)(bb * 128 + kq) * NPIX + p4;
        *(uint4*)&g_xhp[off] = make_uint4(hw[0], hw[1], hw[2], hw[3]);
        *(uint4*)&g_xlp[off] = make_uint4(lw[0], lw[1], lw[2], lw[3]);
    } else {
        int idx = (gid - 8192) * 256 + threadIdx.x;
        if (idx >= 320 * 128) return;
        int m = idx >> 7, kq = idx & 127;
        const float* wr;
        if (m < 32)      wr = Wq + (size_t)m * 256;
        else if (m < 64) wr = Wk + (size_t)(m - 32) * 256;
        else             wr = Wv + (size_t)(m - 64) * 256;
        float w0 = wr[2 * kq], w1 = wr[2 * kq + 1];
        __half h0 = __float2half_rn(w0), h1 = __float2half_rn(w1);
        __half l0 = __float2half_rn(w0 - __half2float(h0));
        __half l1 = __float2half_rn(w1 - __half2float(h1));
        g_whp[idx] = pack2(h0, h1);
        g_wlp[idx] = pack2(l0, l1);
    }
}

// ---------------- 2a) q/k projection (3-term, prefetch pipeline) ----------------
// smem: Wh 5120 | Wl 5120 | Xh 8704 | Xl 8704 ; epilogue Osm overlay 33792
#define PJ_SM 33792

__global__ __launch_bounds__(256) void proj_qk(
    const float* __restrict__ bq, const float* __restrict__ bk)
{
    extern __shared__ char sm[];
    uint32_t* Wh2s = (uint32_t*)(sm);
    uint32_t* Wl2s = (uint32_t*)(sm + 5120);
    uint32_t* Xh2s = (uint32_t*)(sm + 10240);
    uint32_t* Xl2s = (uint32_t*)(sm + 18944);
    float*    Osm  = (float*)sm;

    const int bb = blockIdx.z;
    const int p0 = blockIdx.x * 128;
    const int tid = threadIdx.x;
    const int wid = tid >> 5, lane = tid & 31;
    const int wm = wid & 1, wp = wid >> 1;
    const int gr = lane >> 2, gq = lane & 3;

    float acc[2][4][4];
#pragma unroll
    for (int mt = 0; mt < 2; mt++)
#pragma unroll
        for (int nt = 0; nt < 4; nt++)
#pragma unroll
            for (int j = 0; j < 4; j++) acc[mt][nt][j] = 0.f;

    uint32_t pwh[4], pwl[4], pxh[8], pxl[8];

    // prologue: chunk 0
#pragma unroll
    for (int i = 0; i < 4; i++) {
        int e = tid + i * 256;
        size_t goff = (size_t)(e >> 4) * 128 + (e & 15);
        pwh[i] = g_whp[goff];
        pwl[i] = g_wlp[goff];
    }
#pragma unroll
    for (int i = 0; i < 8; i++) {
        int e = tid + i * 256;
        size_t goff = (size_t)(bb * 128 + (e >> 7)) * NPIX + p0 + (e & 127);
        pxh[i] = g_xhp[goff];
        pxl[i] = g_xlp[goff];
    }

    for (int chunk = 0; chunk < 8; chunk++) {
        // store current chunk
#pragma unroll
        for (int i = 0; i < 4; i++) {
            int e = tid + i * 256;
            int m = e >> 4, kq = e & 15;
            Wh2s[m * 20 + kq] = pwh[i];
            Wl2s[m * 20 + kq] = pwl[i];
        }
#pragma unroll
        for (int i = 0; i < 8; i++) {
            int e = tid + i * 256;
            int kq = e >> 7, p = e & 127;
            Xh2s[kq * 136 + p] = pxh[i];
            Xl2s[kq * 136 + p] = pxl[i];
        }
        __syncthreads();

        // prefetch next chunk (overlaps with compute)
        if (chunk < 7) {
            const int kq0 = (chunk + 1) * 16;
#pragma unroll
            for (int i = 0; i < 4; i++) {
                int e = tid + i * 256;
                size_t goff = (size_t)(e >> 4) * 128 + kq0 + (e & 15);
                pwh[i] = g_whp[goff];
                pwl[i] = g_wlp[goff];
            }
#pragma unroll
            for (int i = 0; i < 8; i++) {
                int e = tid + i * 256;
                size_t goff = (size_t)(bb * 128 + kq0 + (e >> 7)) * NPIX + p0 + (e & 127);
                pxh[i] = g_xhp[goff];
                pxl[i] = g_xlp[goff];
            }
        }

#pragma unroll
        for (int s = 0; s < 2; s++) {
            uint32_t Ah[2][4], Al[2][4];
#pragma unroll
            for (int mt = 0; mt < 2; mt++) {
                int base = (wm * 32 + mt * 16 + gr) * 20 + s * 8 + gq;
                Ah[mt][0] = Wh2s[base];
                Ah[mt][1] = Wh2s[base + 8 * 20];
                Ah[mt][2] = Wh2s[base + 4];
                Ah[mt][3] = Wh2s[base + 8 * 20 + 4];
                Al[mt][0] = Wl2s[base];
                Al[mt][1] = Wl2s[base + 8 * 20];
                Al[mt][2] = Wl2s[base + 4];
                Al[mt][3] = Wl2s[base + 8 * 20 + 4];
            }
#pragma unroll
            for (int nt = 0; nt < 4; nt++) {
                int p  = wp * 32 + nt * 8 + gr;
                int xb = (s * 8 + gq) * 136 + p;
                uint32_t bh0 = Xh2s[xb];
                uint32_t bh1 = Xh2s[xb + 4 * 136];
                uint32_t bl0 = Xl2s[xb];
                uint32_t bl1 = Xl2s[xb + 4 * 136];
#pragma unroll
                for (int mt = 0; mt < 2; mt++) {
                    mma16816(acc[mt][nt], Ah[mt], bh0, bh1);
                    mma16816(acc[mt][nt], Ah[mt], bl0, bl1);
                    mma16816(acc[mt][nt], Al[mt], bh0, bh1);
                }
            }
        }
        __syncthreads();
    }

#pragma unroll
    for (int mt = 0; mt < 2; mt++)
#pragma unroll
        for (int nt = 0; nt < 4; nt++) {
            int row = wm * 32 + mt * 16 + gr;
            int p   = wp * 32 + nt * 8 + 2 * gq;
            Osm[row * 132 + p]           = acc[mt][nt][0];
            Osm[row * 132 + p + 1]       = acc[mt][nt][1];
            Osm[(row + 8) * 132 + p]     = acc[mt][nt][2];
            Osm[(row + 8) * 132 + p + 1] = acc[mt][nt][3];
        }
    __syncthreads();

#pragma unroll
    for (int i = 0; i < 8; i++) {
        int e = tid + i * 256;
        int r = e >> 5, p4 = (e & 31) << 2;
        float bias = (r < 32) ? bq[r] : bk[r - 32];
        uint32_t* dst = (r < 32) ? g_q + (size_t)(bb * CQ + r) * NPIX
                                 : g_k + (size_t)(bb * CQ + r - 32) * NPIX;
        float4 v4 = *(float4*)&Osm[r * 132 + p4];
        float vv[4] = {v4.x + bias, v4.y + bias, v4.z + bias, v4.w + bias};
        uint32_t w[4];
#pragma unroll
        for (int j = 0; j < 4; j++) {
            __half h = __float2half_rn(vv[j]);
            __half l = __float2half_rn(vv[j] - __half2float(h));
            w[j] = pack2(h, l);
        }
        *(uint4*)&dst[p0 + p4] = make_uint4(w[0], w[1], w[2], w[3]);
    }
}

// ---------------- 2b) v projection (hi-only, prefetch, 3 CTA/SM) ----------------
__global__ __launch_bounds__(256, 3) void proj_v(const float* __restrict__ bv)
{
    extern __shared__ char sm[];
    uint32_t* Wh2s = (uint32_t*)(sm);           // 5120
    uint32_t* Xh2s = (uint32_t*)(sm + 5120);    // 8704
    float*    Osm  = (float*)sm;                // overlay 33792

    const int bb = blockIdx.z;
    const int m0 = 64 + blockIdx.y * 64;
    const int p0 = blockIdx.x * 128;
    const int tid = threadIdx.x;
    const int wid = tid >> 5, lane = tid & 31;
    const int wm = wid & 1, wp = wid >> 1;
    const int gr = lane >> 2, gq = lane & 3;

    float acc[2][4][4];
#pragma unroll
    for (int mt = 0; mt < 2; mt++)
#pragma unroll
        for (int nt = 0; nt < 4; nt++)
#pragma unroll
            for (int j = 0; j < 4; j++) acc[mt][nt][j] = 0.f;

    uint32_t pwh[4], pxh[8];
#pragma unroll
    for (int i = 0; i < 4; i++) {
        int e = tid + i * 256;
        pwh[i] = g_whp[(size_t)(m0 + (e >> 4)) * 128 + (e & 15)];
    }
#pragma unroll
    for (int i = 0; i < 8; i++) {
        int e = tid + i * 256;
        pxh[i] = g_xhp[(size_t)(bb * 128 + (e >> 7)) * NPIX + p0 + (e & 127)];
    }

    for (int chunk = 0; chunk < 8; chunk++) {
#pragma unroll
        for (int i = 0; i < 4; i++) {
            int e = tid + i * 256;
            Wh2s[(e >> 4) * 20 + (e & 15)] = pwh[i];
        }
#pragma unroll
        for (int i = 0; i < 8; i++) {
            int e = tid + i * 256;
            Xh2s[(e >> 7) * 136 + (e & 127)] = pxh[i];
        }
        __syncthreads();

        if (chunk < 7) {
            const int kq0 = (chunk + 1) * 16;
#pragma unroll
            for (int i = 0; i < 4; i++) {
                int e = tid + i * 256;
                pwh[i] = g_whp[(size_t)(m0 + (e >> 4)) * 128 + kq0 + (e & 15)];
            }
#pragma unroll
            for (int i = 0; i < 8; i++) {
                int e = tid + i * 256;
                pxh[i] = g_xhp[(size_t)(bb * 128 + kq0 + (e >> 7)) * NPIX + p0 + (e & 127)];
            }
        }

#pragma unroll
        for (int s = 0; s < 2; s++) {
            uint32_t Ah[2][4];
#pragma unroll
            for (int mt = 0; mt < 2; mt++) {
                int base = (wm * 32 + mt * 16 + gr) * 20 + s * 8 + gq;
                Ah[mt][0] = Wh2s[base];
                Ah[mt][1] = Wh2s[base + 8 * 20];
                Ah[mt][2] = Wh2s[base + 4];
                Ah[mt][3] = Wh2s[base + 8 * 20 + 4];
            }
#pragma unroll
            for (int nt = 0; nt < 4; nt++) {
                int p  = wp * 32 + nt * 8 + gr;
                int xb = (s * 8 + gq) * 136 + p;
                uint32_t bh0 = Xh2s[xb];
                uint32_t bh1 = Xh2s[xb + 4 * 136];
#pragma unroll
                for (int mt = 0; mt < 2; mt++)
                    mma16816(acc[mt][nt], Ah[mt], bh0, bh1);
            }
        }
        __syncthreads();
    }

#pragma unroll
    for (int mt = 0; mt < 2; mt++)
#pragma unroll
        for (int nt = 0; nt < 4; nt++) {
            int row = wm * 32 + mt * 16 + gr;
            int p   = wp * 32 + nt * 8 + 2 * gq;
            Osm[row * 132 + p]           = acc[mt][nt][0];
            Osm[row * 132 + p + 1]       = acc[mt][nt][1];
            Osm[(row + 8) * 132 + p]     = acc[mt][nt][2];
            Osm[(row + 8) * 132 + p + 1] = acc[mt][nt][3];
        }
    __syncthreads();

#pragma unroll
    for (int i = 0; i < 8; i++) {
        int e = tid + i * 256;
        int row = e >> 5, p4 = (e & 31) << 2;
        int r = m0 + row;           // always a v row
        float bias = bv[r - 64];
        __half* dst = g_v + (size_t)(bb * CTOT + r - 64) * NPIX;
        float4 v4 = *(float4*)&Osm[row * 132 + p4];
        __half2 h01 = __floats2half2_rn(v4.x + bias, v4.y + bias);
        __half2 h23 = __floats2half2_rn(v4.z + bias, v4.w + bias);
        uint2 w2 = make_uint2(*(uint32_t*)&h01, *(uint32_t*)&h23);
        *(uint2*)&dst[p0 + p4] = w2;
    }
}

// ---------------- 3) transposes (fat tiles) ----------------
// id<512  : q/k, 64x128 u32 tile per CTA (plane=id>>1, y0=(id&1)*64)
// id>=512 : v,  full 128x128 half plane per CTA
__global__ __launch_bounds__(256) void transpose_all()
{
    __shared__ char sbuf[35072];
    const int id = blockIdx.x;
    const int tid = threadIdx.x;

    if (id < 512) {
        uint32_t (*tile)[129] = (uint32_t(*)[129])sbuf;
        const int plane = id >> 1;
        const int y0 = (id & 1) * 64;
        const uint32_t* src;
        uint32_t* dst;
        if (plane < BATCH * CQ) { src = g_q + (size_t)plane * NPIX; dst = g_qT + (size_t)plane * NPIX; }
        else { int p = plane - BATCH * CQ; src = g_k + (size_t)p * NPIX; dst = g_kT + (size_t)p * NPIX; }
#pragma unroll
        for (int it = 0; it < 32; it++) {
            int idx = tid + it * 256;
            int row = idx >> 7, col = idx & 127;
            tile[row][col] = src[(size_t)(y0 + row) * HW + col];
        }
        __syncthreads();
#pragma unroll
        for (int it = 0; it < 32; it++) {
            int idx = tid + it * 256;
            int orow = idx >> 6, r = idx & 63;
            dst[(size_t)orow * HW + y0 + r] = tile[r][orow];
        }
    } else {
        ushort (*tile)[137] = (ushort(*)[137])sbuf;
        const int plane = id - 512;
        const uint32_t* src = (const uint32_t*)(g_v + (size_t)plane * NPIX);
        uint32_t*       dst = (uint32_t*)(g_vT + (size_t)plane * NPIX);
#pragma unroll
        for (int it = 0; it < 32; it++) {
            int idx = tid + it * 256;
            int row = idx >> 6, cu = idx & 63;
            uint32_t w = src[row * 64 + cu];
            tile[row][2 * cu]     = (ushort)(w & 0xffff);
            tile[row][2 * cu + 1] = (ushort)(w >> 16);
        }
        __syncthreads();
#pragma unroll
        for (int it = 0; it < 32; it++) {
            int idx = tid + it * 256;
            int oc = idx >> 6, ru = idx & 63;
            uint32_t w = (uint32_t)tile[2 * ru][oc] | ((uint32_t)tile[2 * ru + 1][oc] << 16);
            dst[oc * 64 + ru] = w;
        }
    }
}

// ---------------- 4) fused attention (unchanged R9) ----------------
#define SM_QH  0
#define SM_QL  2048
#define SM_KH  4096
#define SM_KL  6144
#define SM_V   8192
#define SM_OSM 25600
#define SM_TOTAL 59392

__global__ __launch_bounds__(256, 3) void attn_fused(
    const float* __restrict__ x,
    const float* __restrict__ gamma, float* __restrict__ out)
{
    extern __shared__ char sm[];
    __half* sQh  = (__half*)(sm + SM_QH);
    __half* sQl  = (__half*)(sm + SM_QL);
    __half* sKh  = (__half*)(sm + SM_KH);
    __half* sKl  = (__half*)(sm + SM_KL);
    __half* Vhi  = (__half*)(sm + SM_V);
    float*  OsmH = (float*)(sm + SM_OSM);
    float*  Ost  = (float*)(sm + SM_V);

    const int line = blockIdx.x;
    const int bh   = blockIdx.y;
    const int bb = bh >> 2, head = bh & 3;
    const int tid  = threadIdx.x;
    const int wid  = tid >> 5;
    const int lane = tid & 31;
    const int qr   = lane >> 2;
    const int qq   = lane & 3;

    const int p_st = tid & 127;
    const int hc   = tid >> 7;

    for (int phase = 0; phase < 2; phase++) {
        if (phase) __syncthreads();
        const uint32_t* qb = phase ? g_qT : g_q;
        const uint32_t* kb = phase ? g_kT : g_k;
        const __half*   vb = phase ? g_vT : g_v;

        // ---- stage q/k into compact hi/lo arrays ----
        {
            size_t base = ((size_t)(bb * CQ + head * CHQ + 4 * hc) * NPIX)
                        + (size_t)line * HW + p_st;
            uint32_t qv[4], kv[4];
#pragma unroll
            for (int j = 0; j < 4; j++) {
                qv[j] = qb[base + (size_t)j * NPIX];
                kv[j] = kb[base + (size_t)j * NPIX];
            }
            uint2 qhi, qlo, khi, klo;
            qhi.x = (qv[0] & 0xffffu) | (qv[1] << 16);
            qhi.y = (qv[2] & 0xffffu) | (qv[3] << 16);
            qlo.x = (qv[0] >> 16) | (qv[1] & 0xffff0000u);
            qlo.y = (qv[2] >> 16) | (qv[3] & 0xffff0000u);
            khi.x = (kv[0] & 0xffffu) | (kv[1] << 16);
            khi.y = (kv[2] & 0xffffu) | (kv[3] << 16);
            klo.x = (kv[0] >> 16) | (kv[1] & 0xffff0000u);
            klo.y = (kv[2] >> 16) | (kv[3] & 0xffff0000u);
            int so = p_st * 8 + 4 * hc;
            *(uint2*)&sQh[so] = qhi;
            *(uint2*)&sQl[so] = qlo;
            *(uint2*)&sKh[so] = khi;
            *(uint2*)&sKl[so] = klo;
        }
        // ---- stage V ----
#pragma unroll
        for (int i = 0; i < 4; i++) {
            int e = tid + (i << 8);
            int c = e >> 4, p8 = (e & 15) << 3;
            size_t off = ((size_t)(bb * CTOT + head * CHV + c) * NPIX) + (size_t)line * HW + p8;
            *(uint4*)&Vhi[c * 136 + p8] = *(const uint4*)&vb[off];
        }
        __syncthreads();

        const int aoff = (wid * 16 + qr) * 8 + 2 * qq;
        uint32_t aQh0 = *(const uint32_t*)&sQh[aoff];
        uint32_t aQh1 = *(const uint32_t*)&sQh[aoff + 64];
        uint32_t aQl0 = *(const uint32_t*)&sQl[aoff];
        uint32_t aQl1 = *(const uint32_t*)&sQl[aoff + 64];

        float mr = -1e30f, mr8 = -1e30f, sr = 0.f, sr8 = 0.f;
        float oacc[8][4];
#pragma unroll
        for (int nt = 0; nt < 8; nt++)
#pragma unroll
            for (int j = 0; j < 4; j++) oacc[nt][j] = 0.f;

#pragma unroll
        for (int ch = 0; ch < 2; ch++) {
            float acc[8][4];
#pragma unroll
            for (int nt = 0; nt < 8; nt++)
#pragma unroll
                for (int j = 0; j < 4; j++) acc[nt][j] = 0.f;
#pragma unroll
            for (int nt = 0; nt < 8; nt++) {
                int kbx = (ch * 64 + nt * 8 + qr) * 8 + 2 * qq;
                uint32_t bhh = *(const uint32_t*)&sKh[kbx];
                uint32_t bll = *(const uint32_t*)&sKl[kbx];
                mma1688(acc[nt], aQh0, aQh1, bhh);
                mma1688(acc[nt], aQh0, aQh1, bll);
                mma1688(acc[nt], aQl0, aQl1, bhh);
            }

            float cm = -1e30f, cm8 = -1e30f;
#pragma unroll
            for (int nt = 0; nt < 8; nt++) {
                cm  = fmaxf(cm,  fmaxf(acc[nt][0], acc[nt][1]));
                cm8 = fmaxf(cm8, fmaxf(acc[nt][2], acc[nt][3]));
            }
            cm  = fmaxf(cm,  __shfl_xor_sync(0xffffffffu, cm, 1));
            cm  = fmaxf(cm,  __shfl_xor_sync(0xffffffffu, cm, 2));
            cm8 = fmaxf(cm8, __shfl_xor_sync(0xffffffffu, cm8, 1));
            cm8 = fmaxf(cm8, __shfl_xor_sync(0xffffffffu, cm8, 2));

            float nm  = fmaxf(mr, cm);
            float nm8 = fmaxf(mr8, cm8);
            float sc  = __expf(mr - nm);
            float sc8 = __expf(mr8 - nm8);
            mr = nm; mr8 = nm8;
            sr *= sc; sr8 *= sc8;
#pragma unroll
            for (int nt = 0; nt < 8; nt++) {
                oacc[nt][0] *= sc;  oacc[nt][1] *= sc;
                oacc[nt][2] *= sc8; oacc[nt][3] *= sc8;
            }

            float cs = 0.f, cs8 = 0.f;
#pragma unroll
            for (int nt = 0; nt < 8; nt++) {
                acc[nt][0] = __expf(acc[nt][0] - nm);
                acc[nt][1] = __expf(acc[nt][1] - nm);
                acc[nt][2] = __expf(acc[nt][2] - nm8);
                acc[nt][3] = __expf(acc[nt][3] - nm8);
                cs  += acc[nt][0] + acc[nt][1];
                cs8 += acc[nt][2] + acc[nt][3];
            }
            cs  += __shfl_xor_sync(0xffffffffu, cs, 1);
            cs  += __shfl_xor_sync(0xffffffffu, cs, 2);
            cs8 += __shfl_xor_sync(0xffffffffu, cs8, 1);
            cs8 += __shfl_xor_sync(0xffffffffu, cs8, 2);
            sr  += cs;  sr8 += cs8;

            uint32_t Af[4][4];
#pragma unroll
            for (int kt = 0; kt < 4; kt++) {
                __half2 h0 = __floats2half2_rn(acc[2 * kt][0],     acc[2 * kt][1]);
                __half2 h1 = __floats2half2_rn(acc[2 * kt][2],     acc[2 * kt][3]);
                __half2 h2 = __floats2half2_rn(acc[2 * kt + 1][0], acc[2 * kt + 1][1]);
                __half2 h3 = __floats2half2_rn(acc[2 * kt + 1][2], acc[2 * kt + 1][3]);
                Af[kt][0] = *(uint32_t*)&h0;
                Af[kt][1] = *(uint32_t*)&h1;
                Af[kt][2] = *(uint32_t*)&h2;
                Af[kt][3] = *(uint32_t*)&h3;
            }

#pragma unroll
            for (int kt = 0; kt < 4; kt++) {
#pragma unroll
                for (int nt = 0; nt < 8; nt++) {
                    int vb0 = (8 * nt + qr) * 136 + ch * 64 + 16 * kt + 2 * qq;
                    uint32_t bh0 = *(const uint32_t*)&Vhi[vb0];
                    uint32_t bh1 = *(const uint32_t*)&Vhi[vb0 + 8];
                    mma16816(oacc[nt], Af[kt], bh0, bh1);
                }
            }
        }

        const float inv_r  = 1.f / sr;
        const float inv_r8 = 1.f / sr8;
        const int   r  = wid * 16 + qr;
        const int   r8 = r + 8;

        if (phase == 0) {
#pragma unroll
            for (int nt = 0; nt < 8; nt++) {
                int c0 = 8 * nt + 2 * qq;
                OsmH[c0 * 132 + r]        = oacc[nt][0] * inv_r;
                OsmH[(c0 + 1) * 132 + r]  = oacc[nt][1] * inv_r;
                OsmH[c0 * 132 + r8]       = oacc[nt][2] * inv_r8;
                OsmH[(c0 + 1) * 132 + r8] = oacc[nt][3] * inv_r8;
            }
        } else {
            const float g = gamma[0];
#pragma unroll
            for (int half = 0; half < 2; half++) {
                __syncthreads();
#pragma unroll
                for (int nt = half * 4; nt < half * 4 + 4; nt++) {
                    int cg = 8 * nt + 2 * qq;
                    int cl = cg - 32 * half;
                    Ost[cl * 132 + r]        = oacc[nt][0] * inv_r;
                    Ost[(cl + 1) * 132 + r]  = oacc[nt][1] * inv_r;
                    Ost[cl * 132 + r8]       = oacc[nt][2] * inv_r8;
                    Ost[(cl + 1) * 132 + r8] = oacc[nt][3] * inv_r8;
                }
                __syncthreads();
#pragma unroll
                for (int i = 0; i < 4; i++) {
                    int e = tid + (i << 8);
                    int c = e >> 5, p4 = (e & 31) << 2;
                    int cg = c + 32 * half;
                    size_t off = ((size_t)(bb * CTOT + head * CHV + cg) * HW + line) * HW + p4;
                    float4 ov = *(float4*)&Ost[c * 132 + p4];
                    float4 oh = *(float4*)&OsmH[cg * 132 + p4];
                    float4 xv = *(const float4*)&x[off];
                    float4 r4;
                    r4.x = g * (oh.x + ov.x) + xv.x;
                    r4.y = g * (oh.y + ov.y) + xv.y;
                    r4.z = g * (oh.z + ov.z) + xv.z;
                    r4.w = g * (oh.w + ov.w) + xv.w;
                    *(float4*)&out[off] = r4;
                }
            }
        }
    }
}

// ---------------- launch ----------------
extern "C" void kernel_launch(void* const* d_in, const int* in_sizes, int n_in,
                              void* d_out, int out_size)
{
    const float* x     = (const float*)d_in[0];
    const float* Wq    = (const float*)d_in[1];
    const float* bq    = (const float*)d_in[2];
    const float* Wk    = (const float*)d_in[3];
    const float* bk    = (const float*)d_in[4];
    const float* Wv    = (const float*)d_in[5];
    const float* bv    = (const float*)d_in[6];
    const float* gamma = (const float*)d_in[7];
    float* out = (float*)d_out;

    convert_all<<<8352, 256>>>(x, Wq, Wk, Wv);
    proj_qk<<<dim3(128, 1, 4), 256, PJ_SM>>>(bq, bk);
    proj_v<<<dim3(128, 4, 4), 256, PJ_SM>>>(bv);
    transpose_all<<<1536, 256>>>();

    cudaFuncSetAttribute(attn_fused, cudaFuncAttributeMaxDynamicSharedMemorySize, SM_TOTAL);
    attn_fused<<<dim3(HW, 16), 256, SM_TOTAL>>>(x, gamma, out);
}

// round 11
// speedup vs baseline: 4.3274x; 1.0001x over previous
#include <cuda_runtime.h>
#include <cuda_fp16.h>
#include <cstdint>

// CrissCrossAttention — R11:
//   1) convert_all : W and X fp16 hi/lo split+pack            (unchanged R10)
//   2) proj_qk / proj_v : pipelined tensor-core projections   (unchanged R10)
//   3) transpose_all : fat-tile plane transposes              (unchanged R10)
//   4) attn_fused  : cp.async double-buffered V (phase-1 V prefetched during
//                    phase-0 compute), OsmH stored fp16 to fit 3 CTA/SM.

#define BATCH 4
#define CTOT 256
#define HW   128
#define CQ   32
#define CHQ  8
#define CHV  64
#define NPIX (HW*HW)

// ---------------- scratch ----------------
__device__ uint32_t g_q  [BATCH*CQ*NPIX];    // packed (hi,lo)
__device__ uint32_t g_k  [BATCH*CQ*NPIX];
__device__ uint32_t g_qT [BATCH*CQ*NPIX];
__device__ uint32_t g_kT [BATCH*CQ*NPIX];
__device__ __half   g_v  [BATCH*CTOT*NPIX];  // fp16 hi only
__device__ __half   g_vT [BATCH*CTOT*NPIX];
__device__ uint32_t g_xhp[BATCH*128*NPIX];
__device__ uint32_t g_xlp[BATCH*128*NPIX];
__device__ uint32_t g_whp[320*128];
__device__ uint32_t g_wlp[320*128];

__device__ __forceinline__ uint32_t pack2(__half a, __half b)
{
    __half2 t = __halves2half2(a, b);
    return *(uint32_t*)&t;
}

__device__ __forceinline__ void mma16816(float* d, const uint32_t* a, uint32_t b0, uint32_t b1)
{
    asm volatile(
        "mma.sync.aligned.m16n8k16.row.col.f32.f16.f16.f32 "
        "{%0,%1,%2,%3},{%4,%5,%6,%7},{%8,%9},{%0,%1,%2,%3};"
        : "+f"(d[0]), "+f"(d[1]), "+f"(d[2]), "+f"(d[3])
        : "r"(a[0]), "r"(a[1]), "r"(a[2]), "r"(a[3]), "r"(b0), "r"(b1));
}

__device__ __forceinline__ void mma1688(float* d, uint32_t a0, uint32_t a1, uint32_t b0)
{
    asm volatile(
        "mma.sync.aligned.m16n8k8.row.col.f32.f16.f16.f32 "
        "{%0,%1,%2,%3},{%4,%5},{%6},{%0,%1,%2,%3};"
        : "+f"(d[0]), "+f"(d[1]), "+f"(d[2]), "+f"(d[3])
        : "r"(a0), "r"(a1), "r"(b0));
}

__device__ __forceinline__ void cp_async16(uint32_t saddr, const void* gptr)
{
    asm volatile("cp.async.cg.shared.global [%0], [%1], 16;" :: "r"(saddr), "l"(gptr));
}

// ---------------- 1) merged convert ----------------
__global__ __launch_bounds__(256) void convert_all(
    const float* __restrict__ x,
    const float* __restrict__ Wq, const float* __restrict__ Wk,
    const float* __restrict__ Wv)
{
    const int gid = blockIdx.x;
    if (gid < 8192) {
        const int bb = gid >> 11;
        const int kq = (gid >> 4) & 127;
        const int px = gid & 15;
        const int p4 = (px * 256 + threadIdx.x) * 4;
        const float* r0 = x + ((size_t)(bb * CTOT + 2 * kq) * NPIX) + p4;
        const float* r1 = r0 + NPIX;
        float4 a = *(const float4*)r0;
        float4 b = *(const float4*)r1;
        float av[4] = {a.x, a.y, a.z, a.w};
        float bv[4] = {b.x, b.y, b.z, b.w};
        uint32_t hw[4], lw[4];
#pragma unroll
        for (int j = 0; j < 4; j++) {
            __half h0 = __float2half_rn(av[j]), h1 = __float2half_rn(bv[j]);
            __half l0 = __float2half_rn(av[j] - __half2float(h0));
            __half l1 = __float2half_rn(bv[j] - __half2float(h1));
            hw[j] = pack2(h0, h1);
            lw[j] = pack2(l0, l1);
        }
        size_t off = (size_t)(bb * 128 + kq) * NPIX + p4;
        *(uint4*)&g_xhp[off] = make_uint4(hw[0], hw[1], hw[2], hw[3]);
        *(uint4*)&g_xlp[off] = make_uint4(lw[0], lw[1], lw[2], lw[3]);
    } else {
        int idx = (gid - 8192) * 256 + threadIdx.x;
        if (idx >= 320 * 128) return;
        int m = idx >> 7, kq = idx & 127;
        const float* wr;
        if (m < 32)      wr = Wq + (size_t)m * 256;
        else if (m < 64) wr = Wk + (size_t)(m - 32) * 256;
        else             wr = Wv + (size_t)(m - 64) * 256;
        float w0 = wr[2 * kq], w1 = wr[2 * kq + 1];
        __half h0 = __float2half_rn(w0), h1 = __float2half_rn(w1);
        __half l0 = __float2half_rn(w0 - __half2float(h0));
        __half l1 = __float2half_rn(w1 - __half2float(h1));
        g_whp[idx] = pack2(h0, h1);
        g_wlp[idx] = pack2(l0, l1);
    }
}

// ---------------- 2a) q/k projection (3-term, prefetch pipeline) ----------------
#define PJ_SM 33792

__global__ __launch_bounds__(256) void proj_qk(
    const float* __restrict__ bq, const float* __restrict__ bk)
{
    extern __shared__ char sm[];
    uint32_t* Wh2s = (uint32_t*)(sm);
    uint32_t* Wl2s = (uint32_t*)(sm + 5120);
    uint32_t* Xh2s = (uint32_t*)(sm + 10240);
    uint32_t* Xl2s = (uint32_t*)(sm + 18944);
    float*    Osm  = (float*)sm;

    const int bb = blockIdx.z;
    const int p0 = blockIdx.x * 128;
    const int tid = threadIdx.x;
    const int wid = tid >> 5, lane = tid & 31;
    const int wm = wid & 1, wp = wid >> 1;
    const int gr = lane >> 2, gq = lane & 3;

    float acc[2][4][4];
#pragma unroll
    for (int mt = 0; mt < 2; mt++)
#pragma unroll
        for (int nt = 0; nt < 4; nt++)
#pragma unroll
            for (int j = 0; j < 4; j++) acc[mt][nt][j] = 0.f;

    uint32_t pwh[4], pwl[4], pxh[8], pxl[8];

#pragma unroll
    for (int i = 0; i < 4; i++) {
        int e = tid + i * 256;
        size_t goff = (size_t)(e >> 4) * 128 + (e & 15);
        pwh[i] = g_whp[goff];
        pwl[i] = g_wlp[goff];
    }
#pragma unroll
    for (int i = 0; i < 8; i++) {
        int e = tid + i * 256;
        size_t goff = (size_t)(bb * 128 + (e >> 7)) * NPIX + p0 + (e & 127);
        pxh[i] = g_xhp[goff];
        pxl[i] = g_xlp[goff];
    }

    for (int chunk = 0; chunk < 8; chunk++) {
#pragma unroll
        for (int i = 0; i < 4; i++) {
            int e = tid + i * 256;
            Wh2s[(e >> 4) * 20 + (e & 15)] = pwh[i];
            Wl2s[(e >> 4) * 20 + (e & 15)] = pwl[i];
        }
#pragma unroll
        for (int i = 0; i < 8; i++) {
            int e = tid + i * 256;
            Xh2s[(e >> 7) * 136 + (e & 127)] = pxh[i];
            Xl2s[(e >> 7) * 136 + (e & 127)] = pxl[i];
        }
        __syncthreads();

        if (chunk < 7) {
            const int kq0 = (chunk + 1) * 16;
#pragma unroll
            for (int i = 0; i < 4; i++) {
                int e = tid + i * 256;
                size_t goff = (size_t)(e >> 4) * 128 + kq0 + (e & 15);
                pwh[i] = g_whp[goff];
                pwl[i] = g_wlp[goff];
            }
#pragma unroll
            for (int i = 0; i < 8; i++) {
                int e = tid + i * 256;
                size_t goff = (size_t)(bb * 128 + kq0 + (e >> 7)) * NPIX + p0 + (e & 127);
                pxh[i] = g_xhp[goff];
                pxl[i] = g_xlp[goff];
            }
        }

#pragma unroll
        for (int s = 0; s < 2; s++) {
            uint32_t Ah[2][4], Al[2][4];
#pragma unroll
            for (int mt = 0; mt < 2; mt++) {
                int base = (wm * 32 + mt * 16 + gr) * 20 + s * 8 + gq;
                Ah[mt][0] = Wh2s[base];
                Ah[mt][1] = Wh2s[base + 8 * 20];
                Ah[mt][2] = Wh2s[base + 4];
                Ah[mt][3] = Wh2s[base + 8 * 20 + 4];
                Al[mt][0] = Wl2s[base];
                Al[mt][1] = Wl2s[base + 8 * 20];
                Al[mt][2] = Wl2s[base + 4];
                Al[mt][3] = Wl2s[base + 8 * 20 + 4];
            }
#pragma unroll
            for (int nt = 0; nt < 4; nt++) {
                int p  = wp * 32 + nt * 8 + gr;
                int xb = (s * 8 + gq) * 136 + p;
                uint32_t bh0 = Xh2s[xb];
                uint32_t bh1 = Xh2s[xb + 4 * 136];
                uint32_t bl0 = Xl2s[xb];
                uint32_t bl1 = Xl2s[xb + 4 * 136];
#pragma unroll
                for (int mt = 0; mt < 2; mt++) {
                    mma16816(acc[mt][nt], Ah[mt], bh0, bh1);
                    mma16816(acc[mt][nt], Ah[mt], bl0, bl1);
                    mma16816(acc[mt][nt], Al[mt], bh0, bh1);
                }
            }
        }
        __syncthreads();
    }

#pragma unroll
    for (int mt = 0; mt < 2; mt++)
#pragma unroll
        for (int nt = 0; nt < 4; nt++) {
            int row = wm * 32 + mt * 16 + gr;
            int p   = wp * 32 + nt * 8 + 2 * gq;
            Osm[row * 132 + p]           = acc[mt][nt][0];
            Osm[row * 132 + p + 1]       = acc[mt][nt][1];
            Osm[(row + 8) * 132 + p]     = acc[mt][nt][2];
            Osm[(row + 8) * 132 + p + 1] = acc[mt][nt][3];
        }
    __syncthreads();

#pragma unroll
    for (int i = 0; i < 8; i++) {
        int e = tid + i * 256;
        int r = e >> 5, p4 = (e & 31) << 2;
        float bias = (r < 32) ? bq[r] : bk[r - 32];
        uint32_t* dst = (r < 32) ? g_q + (size_t)(bb * CQ + r) * NPIX
                                 : g_k + (size_t)(bb * CQ + r - 32) * NPIX;
        float4 v4 = *(float4*)&Osm[r * 132 + p4];
        float vv[4] = {v4.x + bias, v4.y + bias, v4.z + bias, v4.w + bias};
        uint32_t w[4];
#pragma unroll
        for (int j = 0; j < 4; j++) {
            __half h = __float2half_rn(vv[j]);
            __half l = __float2half_rn(vv[j] - __half2float(h));
            w[j] = pack2(h, l);
        }
        *(uint4*)&dst[p0 + p4] = make_uint4(w[0], w[1], w[2], w[3]);
    }
}

// ---------------- 2b) v projection (hi-only, prefetch, 3 CTA/SM) ----------------
__global__ __launch_bounds__(256, 3) void proj_v(const float* __restrict__ bv)
{
    extern __shared__ char sm[];
    uint32_t* Wh2s = (uint32_t*)(sm);
    uint32_t* Xh2s = (uint32_t*)(sm + 5120);
    float*    Osm  = (float*)sm;

    const int bb = blockIdx.z;
    const int m0 = 64 + blockIdx.y * 64;
    const int p0 = blockIdx.x * 128;
    const int tid = threadIdx.x;
    const int wid = tid >> 5, lane = tid & 31;
    const int wm = wid & 1, wp = wid >> 1;
    const int gr = lane >> 2, gq = lane & 3;

    float acc[2][4][4];
#pragma unroll
    for (int mt = 0; mt < 2; mt++)
#pragma unroll
        for (int nt = 0; nt < 4; nt++)
#pragma unroll
            for (int j = 0; j < 4; j++) acc[mt][nt][j] = 0.f;

    uint32_t pwh[4], pxh[8];
#pragma unroll
    for (int i = 0; i < 4; i++) {
        int e = tid + i * 256;
        pwh[i] = g_whp[(size_t)(m0 + (e >> 4)) * 128 + (e & 15)];
    }
#pragma unroll
    for (int i = 0; i < 8; i++) {
        int e = tid + i * 256;
        pxh[i] = g_xhp[(size_t)(bb * 128 + (e >> 7)) * NPIX + p0 + (e & 127)];
    }

    for (int chunk = 0; chunk < 8; chunk++) {
#pragma unroll
        for (int i = 0; i < 4; i++) {
            int e = tid + i * 256;
            Wh2s[(e >> 4) * 20 + (e & 15)] = pwh[i];
        }
#pragma unroll
        for (int i = 0; i < 8; i++) {
            int e = tid + i * 256;
            Xh2s[(e >> 7) * 136 + (e & 127)] = pxh[i];
        }
        __syncthreads();

        if (chunk < 7) {
            const int kq0 = (chunk + 1) * 16;
#pragma unroll
            for (int i = 0; i < 4; i++) {
                int e = tid + i * 256;
                pwh[i] = g_whp[(size_t)(m0 + (e >> 4)) * 128 + kq0 + (e & 15)];
            }
#pragma unroll
            for (int i = 0; i < 8; i++) {
                int e = tid + i * 256;
                pxh[i] = g_xhp[(size_t)(bb * 128 + kq0 + (e >> 7)) * NPIX + p0 + (e & 127)];
            }
        }

#pragma unroll
        for (int s = 0; s < 2; s++) {
            uint32_t Ah[2][4];
#pragma unroll
            for (int mt = 0; mt < 2; mt++) {
                int base = (wm * 32 + mt * 16 + gr) * 20 + s * 8 + gq;
                Ah[mt][0] = Wh2s[base];
                Ah[mt][1] = Wh2s[base + 8 * 20];
                Ah[mt][2] = Wh2s[base + 4];
                Ah[mt][3] = Wh2s[base + 8 * 20 + 4];
            }
#pragma unroll
            for (int nt = 0; nt < 4; nt++) {
                int p  = wp * 32 + nt * 8 + gr;
                int xb = (s * 8 + gq) * 136 + p;
                uint32_t bh0 = Xh2s[xb];
                uint32_t bh1 = Xh2s[xb + 4 * 136];
#pragma unroll
                for (int mt = 0; mt < 2; mt++)
                    mma16816(acc[mt][nt], Ah[mt], bh0, bh1);
            }
        }
        __syncthreads();
    }

#pragma unroll
    for (int mt = 0; mt < 2; mt++)
#pragma unroll
        for (int nt = 0; nt < 4; nt++) {
            int row = wm * 32 + mt * 16 + gr;
            int p   = wp * 32 + nt * 8 + 2 * gq;
            Osm[row * 132 + p]           = acc[mt][nt][0];
            Osm[row * 132 + p + 1]       = acc[mt][nt][1];
            Osm[(row + 8) * 132 + p]     = acc[mt][nt][2];
            Osm[(row + 8) * 132 + p + 1] = acc[mt][nt][3];
        }
    __syncthreads();

#pragma unroll
    for (int i = 0; i < 8; i++) {
        int e = tid + i * 256;
        int row = e >> 5, p4 = (e & 31) << 2;
        int r = m0 + row;
        float bias = bv[r - 64];
        __half* dst = g_v + (size_t)(bb * CTOT + r - 64) * NPIX;
        float4 v4 = *(float4*)&Osm[row * 132 + p4];
        __half2 h01 = __floats2half2_rn(v4.x + bias, v4.y + bias);
        __half2 h23 = __floats2half2_rn(v4.z + bias, v4.w + bias);
        uint2 w2 = make_uint2(*(uint32_t*)&h01, *(uint32_t*)&h23);
        *(uint2*)&dst[p0 + p4] = w2;
    }
}

// ---------------- 3) transposes (fat tiles) ----------------
__global__ __launch_bounds__(256) void transpose_all()
{
    __shared__ char sbuf[35072];
    const int id = blockIdx.x;
    const int tid = threadIdx.x;

    if (id < 512) {
        uint32_t (*tile)[129] = (uint32_t(*)[129])sbuf;
        const int plane = id >> 1;
        const int y0 = (id & 1) * 64;
        const uint32_t* src;
        uint32_t* dst;
        if (plane < BATCH * CQ) { src = g_q + (size_t)plane * NPIX; dst = g_qT + (size_t)plane * NPIX; }
        else { int p = plane - BATCH * CQ; src = g_k + (size_t)p * NPIX; dst = g_kT + (size_t)p * NPIX; }
#pragma unroll
        for (int it = 0; it < 32; it++) {
            int idx = tid + it * 256;
            int row = idx >> 7, col = idx & 127;
            tile[row][col] = src[(size_t)(y0 + row) * HW + col];
        }
        __syncthreads();
#pragma unroll
        for (int it = 0; it < 32; it++) {
            int idx = tid + it * 256;
            int orow = idx >> 6, r = idx & 63;
            dst[(size_t)orow * HW + y0 + r] = tile[r][orow];
        }
    } else {
        ushort (*tile)[137] = (ushort(*)[137])sbuf;
        const int plane = id - 512;
        const uint32_t* src = (const uint32_t*)(g_v + (size_t)plane * NPIX);
        uint32_t*       dst = (uint32_t*)(g_vT + (size_t)plane * NPIX);
#pragma unroll
        for (int it = 0; it < 32; it++) {
            int idx = tid + it * 256;
            int row = idx >> 6, cu = idx & 63;
            uint32_t w = src[row * 64 + cu];
            tile[row][2 * cu]     = (ushort)(w & 0xffff);
            tile[row][2 * cu + 1] = (ushort)(w >> 16);
        }
        __syncthreads();
#pragma unroll
        for (int it = 0; it < 32; it++) {
            int idx = tid + it * 256;
            int oc = idx >> 6, ru = idx & 63;
            uint32_t w = (uint32_t)tile[2 * ru][oc] | ((uint32_t)tile[2 * ru + 1][oc] << 16);
            dst[oc * 64 + ru] = w;
        }
    }
}

// ---------------- 4) fused attention, cp.async double-buffered V ----------------
// smem: Qh 2048 | Ql 2048 | Kh 2048 | Kl 2048 | V0 17408 | V1 17408 | OsmH(half) 17408
//       = 60416.  Ost (32x132 f32 = 16896) overlays V0 in the phase-1 epilogue.
#define SM_QH   0
#define SM_QL   2048
#define SM_KH   4096
#define SM_KL   6144
#define SM_V0   8192
#define SM_V1   25600
#define SM_OSMH 43008
#define SM_TOTAL 60416

__global__ __launch_bounds__(256, 3) void attn_fused(
    const float* __restrict__ x,
    const float* __restrict__ gamma, float* __restrict__ out)
{
    extern __shared__ char sm[];
    __half* sQh  = (__half*)(sm + SM_QH);
    __half* sQl  = (__half*)(sm + SM_QL);
    __half* sKh  = (__half*)(sm + SM_KH);
    __half* sKl  = (__half*)(sm + SM_KL);
    __half* V0   = (__half*)(sm + SM_V0);
    __half* V1   = (__half*)(sm + SM_V1);
    __half* OsmH = (__half*)(sm + SM_OSMH);
    float*  Ost  = (float*)(sm + SM_V0);

    const uint32_t smem_u32 = (uint32_t)__cvta_generic_to_shared(sm);

    const int line = blockIdx.x;
    const int bh   = blockIdx.y;
    const int bb = bh >> 2, head = bh & 3;
    const int tid  = threadIdx.x;
    const int wid  = tid >> 5;
    const int lane = tid & 31;
    const int qr   = lane >> 2;
    const int qq   = lane & 3;

    const int p_st = tid & 127;
    const int hc   = tid >> 7;

    for (int phase = 0; phase < 2; phase++) {
        if (phase) __syncthreads();
        const uint32_t* qb = phase ? g_qT : g_q;
        const uint32_t* kb = phase ? g_kT : g_k;

        // ---- stage q/k into compact hi/lo arrays ----
        {
            size_t base = ((size_t)(bb * CQ + head * CHQ + 4 * hc) * NPIX)
                        + (size_t)line * HW + p_st;
            uint32_t qv[4], kv[4];
#pragma unroll
            for (int j = 0; j < 4; j++) {
                qv[j] = qb[base + (size_t)j * NPIX];
                kv[j] = kb[base + (size_t)j * NPIX];
            }
            uint2 qhi, qlo, khi, klo;
            qhi.x = (qv[0] & 0xffffu) | (qv[1] << 16);
            qhi.y = (qv[2] & 0xffffu) | (qv[3] << 16);
            qlo.x = (qv[0] >> 16) | (qv[1] & 0xffff0000u);
            qlo.y = (qv[2] >> 16) | (qv[3] & 0xffff0000u);
            khi.x = (kv[0] & 0xffffu) | (kv[1] << 16);
            khi.y = (kv[2] & 0xffffu) | (kv[3] << 16);
            klo.x = (kv[0] >> 16) | (kv[1] & 0xffff0000u);
            klo.y = (kv[2] >> 16) | (kv[3] & 0xffff0000u);
            int so = p_st * 8 + 4 * hc;
            *(uint2*)&sQh[so] = qhi;
            *(uint2*)&sQl[so] = qlo;
            *(uint2*)&sKh[so] = khi;
            *(uint2*)&sKl[so] = klo;
        }

        // ---- phase 0: issue cp.async for BOTH V buffers ----
        if (phase == 0) {
#pragma unroll
            for (int i = 0; i < 4; i++) {
                int e = tid + (i << 8);
                int c = e >> 4, p8 = (e & 15) << 3;
                size_t off = ((size_t)(bb * CTOT + head * CHV + c) * NPIX) + (size_t)line * HW + p8;
                cp_async16(smem_u32 + SM_V0 + (uint32_t)(c * 272 + p8 * 2), &g_v[off]);
            }
            asm volatile("cp.async.commit_group;");
#pragma unroll
            for (int i = 0; i < 4; i++) {
                int e = tid + (i << 8);
                int c = e >> 4, p8 = (e & 15) << 3;
                size_t off = ((size_t)(bb * CTOT + head * CHV + c) * NPIX) + (size_t)line * HW + p8;
                cp_async16(smem_u32 + SM_V1 + (uint32_t)(c * 272 + p8 * 2), &g_vT[off]);
            }
            asm volatile("cp.async.commit_group;");
        }
        __syncthreads();   // q/k staged visible

        const __half* Vcur = phase ? V1 : V0;

        // ---- A-frags (k=8, whole channel dim) ----
        const int aoff = (wid * 16 + qr) * 8 + 2 * qq;
        uint32_t aQh0 = *(const uint32_t*)&sQh[aoff];
        uint32_t aQh1 = *(const uint32_t*)&sQh[aoff + 64];
        uint32_t aQl0 = *(const uint32_t*)&sQl[aoff];
        uint32_t aQl1 = *(const uint32_t*)&sQl[aoff + 64];

        float mr = -1e30f, mr8 = -1e30f, sr = 0.f, sr8 = 0.f;
        float oacc[8][4];
#pragma unroll
        for (int nt = 0; nt < 8; nt++)
#pragma unroll
            for (int j = 0; j < 4; j++) oacc[nt][j] = 0.f;

#pragma unroll
        for (int ch = 0; ch < 2; ch++) {
            float acc[8][4];
#pragma unroll
            for (int nt = 0; nt < 8; nt++)
#pragma unroll
                for (int j = 0; j < 4; j++) acc[nt][j] = 0.f;
#pragma unroll
            for (int nt = 0; nt < 8; nt++) {
                int kbx = (ch * 64 + nt * 8 + qr) * 8 + 2 * qq;
                uint32_t bhh = *(const uint32_t*)&sKh[kbx];
                uint32_t bll = *(const uint32_t*)&sKl[kbx];
                mma1688(acc[nt], aQh0, aQh1, bhh);
                mma1688(acc[nt], aQh0, aQh1, bll);
                mma1688(acc[nt], aQl0, aQl1, bhh);
            }

            float cm = -1e30f, cm8 = -1e30f;
#pragma unroll
            for (int nt = 0; nt < 8; nt++) {
                cm  = fmaxf(cm,  fmaxf(acc[nt][0], acc[nt][1]));
                cm8 = fmaxf(cm8, fmaxf(acc[nt][2], acc[nt][3]));
            }
            cm  = fmaxf(cm,  __shfl_xor_sync(0xffffffffu, cm, 1));
            cm  = fmaxf(cm,  __shfl_xor_sync(0xffffffffu, cm, 2));
            cm8 = fmaxf(cm8, __shfl_xor_sync(0xffffffffu, cm8, 1));
            cm8 = fmaxf(cm8, __shfl_xor_sync(0xffffffffu, cm8, 2));

            float nm  = fmaxf(mr, cm);
            float nm8 = fmaxf(mr8, cm8);
            float sc  = __expf(mr - nm);
            float sc8 = __expf(mr8 - nm8);
            mr = nm; mr8 = nm8;
            sr *= sc; sr8 *= sc8;
#pragma unroll
            for (int nt = 0; nt < 8; nt++) {
                oacc[nt][0] *= sc;  oacc[nt][1] *= sc;
                oacc[nt][2] *= sc8; oacc[nt][3] *= sc8;
            }

            float cs = 0.f, cs8 = 0.f;
#pragma unroll
            for (int nt = 0; nt < 8; nt++) {
                acc[nt][0] = __expf(acc[nt][0] - nm);
                acc[nt][1] = __expf(acc[nt][1] - nm);
                acc[nt][2] = __expf(acc[nt][2] - nm8);
                acc[nt][3] = __expf(acc[nt][3] - nm8);
                cs  += acc[nt][0] + acc[nt][1];
                cs8 += acc[nt][2] + acc[nt][3];
            }
            cs  += __shfl_xor_sync(0xffffffffu, cs, 1);
            cs  += __shfl_xor_sync(0xffffffffu, cs, 2);
            cs8 += __shfl_xor_sync(0xffffffffu, cs8, 1);
            cs8 += __shfl_xor_sync(0xffffffffu, cs8, 2);
            sr  += cs;  sr8 += cs8;

            uint32_t Af[4][4];
#pragma unroll
            for (int kt = 0; kt < 4; kt++) {
                __half2 h0 = __floats2half2_rn(acc[2 * kt][0],     acc[2 * kt][1]);
                __half2 h1 = __floats2half2_rn(acc[2 * kt][2],     acc[2 * kt][3]);
                __half2 h2 = __floats2half2_rn(acc[2 * kt + 1][0], acc[2 * kt + 1][1]);
                __half2 h3 = __floats2half2_rn(acc[2 * kt + 1][2], acc[2 * kt + 1][3]);
                Af[kt][0] = *(uint32_t*)&h0;
                Af[kt][1] = *(uint32_t*)&h1;
                Af[kt][2] = *(uint32_t*)&h2;
                Af[kt][3] = *(uint32_t*)&h3;
            }

            // ---- ensure V buffer for this phase has landed (once, before first use) ----
            if (ch == 0) {
                if (phase == 0) asm volatile("cp.async.wait_group 1;" ::: "memory");
                else            asm volatile("cp.async.wait_group 0;" ::: "memory");
                __syncthreads();
            }

#pragma unroll
            for (int kt = 0; kt < 4; kt++) {
#pragma unroll
                for (int nt = 0; nt < 8; nt++) {
                    int vb0 = (8 * nt + qr) * 136 + ch * 64 + 16 * kt + 2 * qq;
                    uint32_t bh0 = *(const uint32_t*)&Vcur[vb0];
                    uint32_t bh1 = *(const uint32_t*)&Vcur[vb0 + 8];
                    mma16816(oacc[nt], Af[kt], bh0, bh1);
                }
            }
        }

        const float inv_r  = 1.f / sr;
        const float inv_r8 = 1.f / sr8;
        const int   r  = wid * 16 + qr;
        const int   r8 = r + 8;

        if (phase == 0) {
            // stage normalized O_h (fp16, c-major rows of 136)
#pragma unroll
            for (int nt = 0; nt < 8; nt++) {
                int c0 = 8 * nt + 2 * qq;
                OsmH[c0 * 136 + r]        = __float2half_rn(oacc[nt][0] * inv_r);
                OsmH[(c0 + 1) * 136 + r]  = __float2half_rn(oacc[nt][1] * inv_r);
                OsmH[c0 * 136 + r8]       = __float2half_rn(oacc[nt][2] * inv_r8);
                OsmH[(c0 + 1) * 136 + r8] = __float2half_rn(oacc[nt][3] * inv_r8);
            }
        } else {
            const float g = gamma[0];
#pragma unroll
            for (int half = 0; half < 2; half++) {
                __syncthreads();   // V0 region (Ost) free: phase-1 used V1
#pragma unroll
                for (int nt = half * 4; nt < half * 4 + 4; nt++) {
                    int cg = 8 * nt + 2 * qq;
                    int cl = cg - 32 * half;
                    Ost[cl * 132 + r]        = oacc[nt][0] * inv_r;
                    Ost[(cl + 1) * 132 + r]  = oacc[nt][1] * inv_r;
                    Ost[cl * 132 + r8]       = oacc[nt][2] * inv_r8;
                    Ost[(cl + 1) * 132 + r8] = oacc[nt][3] * inv_r8;
                }
                __syncthreads();
#pragma unroll
                for (int i = 0; i < 4; i++) {
                    int e = tid + (i << 8);
                    int c = e >> 5, p4 = (e & 31) << 2;
                    int cg = c + 32 * half;
                    size_t off = ((size_t)(bb * CTOT + head * CHV + cg) * HW + line) * HW + p4;
                    float4 ov = *(float4*)&Ost[c * 132 + p4];
                    uint2 ohw = *(uint2*)&OsmH[cg * 136 + p4];
                    float2 oh01 = __half22float2(*(__half2*)&ohw.x);
                    float2 oh23 = __half22float2(*(__half2*)&ohw.y);
                    float4 xv = *(const float4*)&x[off];
                    float4 r4;
                    r4.x = g * (oh01.x + ov.x) + xv.x;
                    r4.y = g * (oh01.y + ov.y) + xv.y;
                    r4.z = g * (oh23.x + ov.z) + xv.z;
                    r4.w = g * (oh23.y + ov.w) + xv.w;
                    *(float4*)&out[off] = r4;
                }
            }
        }
    }
}

// ---------------- launch ----------------
extern "C" void kernel_launch(void* const* d_in, const int* in_sizes, int n_in,
                              void* d_out, int out_size)
{
    const float* x     = (const float*)d_in[0];
    const float* Wq    = (const float*)d_in[1];
    const float* bq    = (const float*)d_in[2];
    const float* Wk    = (const float*)d_in[3];
    const float* bk    = (const float*)d_in[4];
    const float* Wv    = (const float*)d_in[5];
    const float* bv    = (const float*)d_in[6];
    const float* gamma = (const float*)d_in[7];
    float* out = (float*)d_out;

    convert_all<<<8352, 256>>>(x, Wq, Wk, Wv);
    proj_qk<<<dim3(128, 1, 4), 256, PJ_SM>>>(bq, bk);
    proj_v<<<dim3(128, 4, 4), 256, PJ_SM>>>(bv);
    transpose_all<<<1536, 256>>>();

    cudaFuncSetAttribute(attn_fused, cudaFuncAttributeMaxDynamicSharedMemorySize, SM_TOTAL);
    attn_fused<<<dim3(HW, 16), 256, SM_TOTAL>>>(x, gamma, out);
}

// round 12
// speedup vs baseline: 4.4970x; 1.0392x over previous
#include <cuda_runtime.h>
#include <cuda_fp16.h>
#include <cstdint>

// CrissCrossAttention — R12 (traffic reduction; pipeline is DRAM-bound):
//   1) convert_all : W hi/lo split; X hi-only pack (xlp ELIMINATED)
//   2) proj_qk     : reads x fp32 directly, inline hi/lo split in prefetch regs
//      proj_v      : BM=128 (2 m-tiles per X read -> halves xhp traffic)
//   3) transpose_all : unchanged
//   4) attn_fused  : unchanged R11 (cp.async double-buffered V, fp16 OsmH)

#define BATCH 4
#define CTOT 256
#define HW   128
#define CQ   32
#define CHQ  8
#define CHV  64
#define NPIX (HW*HW)

// ---------------- scratch ----------------
__device__ uint32_t g_q  [BATCH*CQ*NPIX];    // packed (hi,lo)
__device__ uint32_t g_k  [BATCH*CQ*NPIX];
__device__ uint32_t g_qT [BATCH*CQ*NPIX];
__device__ uint32_t g_kT [BATCH*CQ*NPIX];
__device__ __half   g_v  [BATCH*CTOT*NPIX];  // fp16 hi only
__device__ __half   g_vT [BATCH*CTOT*NPIX];
__device__ uint32_t g_xhp[BATCH*128*NPIX];   // (hi_k, hi_{k+1}) pairs
__device__ uint32_t g_whp[320*128];
__device__ uint32_t g_wlp[320*128];

__device__ __forceinline__ uint32_t pack2(__half a, __half b)
{
    __half2 t = __halves2half2(a, b);
    return *(uint32_t*)&t;
}

__device__ __forceinline__ void mma16816(float* d, const uint32_t* a, uint32_t b0, uint32_t b1)
{
    asm volatile(
        "mma.sync.aligned.m16n8k16.row.col.f32.f16.f16.f32 "
        "{%0,%1,%2,%3},{%4,%5,%6,%7},{%8,%9},{%0,%1,%2,%3};"
        : "+f"(d[0]), "+f"(d[1]), "+f"(d[2]), "+f"(d[3])
        : "r"(a[0]), "r"(a[1]), "r"(a[2]), "r"(a[3]), "r"(b0), "r"(b1));
}

__device__ __forceinline__ void mma1688(float* d, uint32_t a0, uint32_t a1, uint32_t b0)
{
    asm volatile(
        "mma.sync.aligned.m16n8k8.row.col.f32.f16.f16.f32 "
        "{%0,%1,%2,%3},{%4,%5},{%6},{%0,%1,%2,%3};"
        : "+f"(d[0]), "+f"(d[1]), "+f"(d[2]), "+f"(d[3])
        : "r"(a0), "r"(a1), "r"(b0));
}

__device__ __forceinline__ void cp_async16(uint32_t saddr, const void* gptr)
{
    asm volatile("cp.async.cg.shared.global [%0], [%1], 16;" :: "r"(saddr), "l"(gptr));
}

// ---------------- 1) merged convert (X hi-only + W hi/lo) ----------------
__global__ __launch_bounds__(256) void convert_all(
    const float* __restrict__ x,
    const float* __restrict__ Wq, const float* __restrict__ Wk,
    const float* __restrict__ Wv)
{
    const int gid = blockIdx.x;
    if (gid < 8192) {
        const int bb = gid >> 11;
        const int kq = (gid >> 4) & 127;
        const int px = gid & 15;
        const int p4 = (px * 256 + threadIdx.x) * 4;
        const float* r0 = x + ((size_t)(bb * CTOT + 2 * kq) * NPIX) + p4;
        const float* r1 = r0 + NPIX;
        float4 a = *(const float4*)r0;
        float4 b = *(const float4*)r1;
        float av[4] = {a.x, a.y, a.z, a.w};
        float bv[4] = {b.x, b.y, b.z, b.w};
        uint32_t hw[4];
#pragma unroll
        for (int j = 0; j < 4; j++)
            hw[j] = pack2(__float2half_rn(av[j]), __float2half_rn(bv[j]));
        size_t off = (size_t)(bb * 128 + kq) * NPIX + p4;
        *(uint4*)&g_xhp[off] = make_uint4(hw[0], hw[1], hw[2], hw[3]);
    } else {
        int idx = (gid - 8192) * 256 + threadIdx.x;
        if (idx >= 320 * 128) return;
        int m = idx >> 7, kq = idx & 127;
        const float* wr;
        if (m < 32)      wr = Wq + (size_t)m * 256;
        else if (m < 64) wr = Wk + (size_t)(m - 32) * 256;
        else             wr = Wv + (size_t)(m - 64) * 256;
        float w0 = wr[2 * kq], w1 = wr[2 * kq + 1];
        __half h0 = __float2half_rn(w0), h1 = __float2half_rn(w1);
        __half l0 = __float2half_rn(w0 - __half2float(h0));
        __half l1 = __float2half_rn(w1 - __half2float(h1));
        g_whp[idx] = pack2(h0, h1);
        g_wlp[idx] = pack2(l0, l1);
    }
}

// ---------------- 2a) q/k projection (3-term; reads x fp32, inline split) ----------------
#define PJ_SM 33792

__global__ __launch_bounds__(256) void proj_qk(
    const float* __restrict__ x,
    const float* __restrict__ bq, const float* __restrict__ bk)
{
    extern __shared__ char sm[];
    uint32_t* Wh2s = (uint32_t*)(sm);
    uint32_t* Wl2s = (uint32_t*)(sm + 5120);
    uint32_t* Xh2s = (uint32_t*)(sm + 10240);
    uint32_t* Xl2s = (uint32_t*)(sm + 18944);
    float*    Osm  = (float*)sm;

    const int bb = blockIdx.z;
    const int p0 = blockIdx.x * 128;
    const int tid = threadIdx.x;
    const int wid = tid >> 5, lane = tid & 31;
    const int wm = wid & 1, wp = wid >> 1;
    const int gr = lane >> 2, gq = lane & 3;

    const float* xb = x + (size_t)bb * CTOT * NPIX;

    float acc[2][4][4];
#pragma unroll
    for (int mt = 0; mt < 2; mt++)
#pragma unroll
        for (int nt = 0; nt < 4; nt++)
#pragma unroll
            for (int j = 0; j < 4; j++) acc[mt][nt][j] = 0.f;

    uint32_t pwh[4], pwl[4];
    float pf0[8], pf1[8];

#pragma unroll
    for (int i = 0; i < 4; i++) {
        int e = tid + i * 256;
        size_t goff = (size_t)(e >> 4) * 128 + (e & 15);
        pwh[i] = g_whp[goff];
        pwl[i] = g_wlp[goff];
    }
#pragma unroll
    for (int i = 0; i < 8; i++) {
        int e = tid + i * 256;
        int kq = e >> 7, p = e & 127;
        size_t goff = (size_t)(2 * kq) * NPIX + p0 + p;
        pf0[i] = xb[goff];
        pf1[i] = xb[goff + NPIX];
    }

    for (int chunk = 0; chunk < 8; chunk++) {
#pragma unroll
        for (int i = 0; i < 4; i++) {
            int e = tid + i * 256;
            Wh2s[(e >> 4) * 20 + (e & 15)] = pwh[i];
            Wl2s[(e >> 4) * 20 + (e & 15)] = pwl[i];
        }
#pragma unroll
        for (int i = 0; i < 8; i++) {
            int e = tid + i * 256;
            int kq = e >> 7, p = e & 127;
            __half h0 = __float2half_rn(pf0[i]);
            __half l0 = __float2half_rn(pf0[i] - __half2float(h0));
            __half h1 = __float2half_rn(pf1[i]);
            __half l1 = __float2half_rn(pf1[i] - __half2float(h1));
            Xh2s[kq * 136 + p] = pack2(h0, h1);
            Xl2s[kq * 136 + p] = pack2(l0, l1);
        }
        __syncthreads();

        if (chunk < 7) {
            const int kq0 = (chunk + 1) * 16;
#pragma unroll
            for (int i = 0; i < 4; i++) {
                int e = tid + i * 256;
                size_t goff = (size_t)(e >> 4) * 128 + kq0 + (e & 15);
                pwh[i] = g_whp[goff];
                pwl[i] = g_wlp[goff];
            }
#pragma unroll
            for (int i = 0; i < 8; i++) {
                int e = tid + i * 256;
                int kq = e >> 7, p = e & 127;
                size_t goff = (size_t)(2 * (kq0 + kq)) * NPIX + p0 + p;
                pf0[i] = xb[goff];
                pf1[i] = xb[goff + NPIX];
            }
        }

#pragma unroll
        for (int s = 0; s < 2; s++) {
            uint32_t Ah[2][4], Al[2][4];
#pragma unroll
            for (int mt = 0; mt < 2; mt++) {
                int base = (wm * 32 + mt * 16 + gr) * 20 + s * 8 + gq;
                Ah[mt][0] = Wh2s[base];
                Ah[mt][1] = Wh2s[base + 8 * 20];
                Ah[mt][2] = Wh2s[base + 4];
                Ah[mt][3] = Wh2s[base + 8 * 20 + 4];
                Al[mt][0] = Wl2s[base];
                Al[mt][1] = Wl2s[base + 8 * 20];
                Al[mt][2] = Wl2s[base + 4];
                Al[mt][3] = Wl2s[base + 8 * 20 + 4];
            }
#pragma unroll
            for (int nt = 0; nt < 4; nt++) {
                int p  = wp * 32 + nt * 8 + gr;
                int xbx = (s * 8 + gq) * 136 + p;
                uint32_t bh0 = Xh2s[xbx];
                uint32_t bh1 = Xh2s[xbx + 4 * 136];
                uint32_t bl0 = Xl2s[xbx];
                uint32_t bl1 = Xl2s[xbx + 4 * 136];
#pragma unroll
                for (int mt = 0; mt < 2; mt++) {
                    mma16816(acc[mt][nt], Ah[mt], bh0, bh1);
                    mma16816(acc[mt][nt], Ah[mt], bl0, bl1);
                    mma16816(acc[mt][nt], Al[mt], bh0, bh1);
                }
            }
        }
        __syncthreads();
    }

#pragma unroll
    for (int mt = 0; mt < 2; mt++)
#pragma unroll
        for (int nt = 0; nt < 4; nt++) {
            int row = wm * 32 + mt * 16 + gr;
            int p   = wp * 32 + nt * 8 + 2 * gq;
            Osm[row * 132 + p]           = acc[mt][nt][0];
            Osm[row * 132 + p + 1]       = acc[mt][nt][1];
            Osm[(row + 8) * 132 + p]     = acc[mt][nt][2];
            Osm[(row + 8) * 132 + p + 1] = acc[mt][nt][3];
        }
    __syncthreads();

#pragma unroll
    for (int i = 0; i < 8; i++) {
        int e = tid + i * 256;
        int r = e >> 5, p4 = (e & 31) << 2;
        float bias = (r < 32) ? bq[r] : bk[r - 32];
        uint32_t* dst = (r < 32) ? g_q + (size_t)(bb * CQ + r) * NPIX
                                 : g_k + (size_t)(bb * CQ + r - 32) * NPIX;
        float4 v4 = *(float4*)&Osm[r * 132 + p4];
        float vv[4] = {v4.x + bias, v4.y + bias, v4.z + bias, v4.w + bias};
        uint32_t w[4];
#pragma unroll
        for (int j = 0; j < 4; j++) {
            __half h = __float2half_rn(vv[j]);
            __half l = __float2half_rn(vv[j] - __half2float(h));
            w[j] = pack2(h, l);
        }
        *(uint4*)&dst[p0 + p4] = make_uint4(w[0], w[1], w[2], w[3]);
    }
}

// ---------------- 2b) v projection, BM=128 (halved X traffic) ----------------
// smem mainloop: Wh 128x20 u32 = 10240 | Xh 16x136 u32 = 8704 (18944)
// epilogue overlay Osm[64][132] f32 = 33792, staged in two 64-row halves.
__global__ __launch_bounds__(256) void proj_v(const float* __restrict__ bv)
{
    extern __shared__ char sm[];
    uint32_t* Wh2s = (uint32_t*)(sm);
    uint32_t* Xh2s = (uint32_t*)(sm + 10240);
    float*    Osm  = (float*)sm;

    const int bb = blockIdx.z;
    const int m0 = 64 + blockIdx.y * 128;
    const int p0 = blockIdx.x * 128;
    const int tid = threadIdx.x;
    const int wid = tid >> 5, lane = tid & 31;
    const int wm = wid & 1, wp = wid >> 1;
    const int gr = lane >> 2, gq = lane & 3;

    float acc[4][4][4];
#pragma unroll
    for (int mt = 0; mt < 4; mt++)
#pragma unroll
        for (int nt = 0; nt < 4; nt++)
#pragma unroll
            for (int j = 0; j < 4; j++) acc[mt][nt][j] = 0.f;

    uint32_t pwh[8], pxh[8];
#pragma unroll
    for (int i = 0; i < 8; i++) {
        int e = tid + i * 256;
        pwh[i] = g_whp[(size_t)(m0 + (e >> 4)) * 128 + (e & 15)];
        pxh[i] = g_xhp[(size_t)(bb * 128 + (e >> 7)) * NPIX + p0 + (e & 127)];
    }

    for (int chunk = 0; chunk < 8; chunk++) {
#pragma unroll
        for (int i = 0; i < 8; i++) {
            int e = tid + i * 256;
            Wh2s[(e >> 4) * 20 + (e & 15)] = pwh[i];
            Xh2s[(e >> 7) * 136 + (e & 127)] = pxh[i];
        }
        __syncthreads();

        if (chunk < 7) {
            const int kq0 = (chunk + 1) * 16;
#pragma unroll
            for (int i = 0; i < 8; i++) {
                int e = tid + i * 256;
                pwh[i] = g_whp[(size_t)(m0 + (e >> 4)) * 128 + kq0 + (e & 15)];
                pxh[i] = g_xhp[(size_t)(bb * 128 + kq0 + (e >> 7)) * NPIX + p0 + (e & 127)];
            }
        }

#pragma unroll
        for (int s = 0; s < 2; s++) {
            uint32_t Ah[4][4];
#pragma unroll
            for (int mt = 0; mt < 4; mt++) {
                int base = (wm * 64 + mt * 16 + gr) * 20 + s * 8 + gq;
                Ah[mt][0] = Wh2s[base];
                Ah[mt][1] = Wh2s[base + 8 * 20];
                Ah[mt][2] = Wh2s[base + 4];
                Ah[mt][3] = Wh2s[base + 8 * 20 + 4];
            }
#pragma unroll
            for (int nt = 0; nt < 4; nt++) {
                int p  = wp * 32 + nt * 8 + gr;
                int xbx = (s * 8 + gq) * 136 + p;
                uint32_t bh0 = Xh2s[xbx];
                uint32_t bh1 = Xh2s[xbx + 4 * 136];
#pragma unroll
                for (int mt = 0; mt < 4; mt++)
                    mma16816(acc[mt][nt], Ah[mt], bh0, bh1);
            }
        }
        __syncthreads();
    }

    // epilogue: two 64-row halves through the smem overlay
#pragma unroll
    for (int h = 0; h < 2; h++) {
        __syncthreads();
        if (wm == h) {
#pragma unroll
            for (int mt = 0; mt < 4; mt++)
#pragma unroll
                for (int nt = 0; nt < 4; nt++) {
                    int row = mt * 16 + gr;
                    int p   = wp * 32 + nt * 8 + 2 * gq;
                    Osm[row * 132 + p]           = acc[mt][nt][0];
                    Osm[row * 132 + p + 1]       = acc[mt][nt][1];
                    Osm[(row + 8) * 132 + p]     = acc[mt][nt][2];
                    Osm[(row + 8) * 132 + p + 1] = acc[mt][nt][3];
                }
        }
        __syncthreads();
#pragma unroll
        for (int i = 0; i < 8; i++) {
            int e = tid + i * 256;
            int row = e >> 5, p4 = (e & 31) << 2;
            int r = m0 + h * 64 + row;
            float bias = bv[r - 64];
            __half* dst = g_v + (size_t)(bb * CTOT + r - 64) * NPIX;
            float4 v4 = *(float4*)&Osm[row * 132 + p4];
            __half2 h01 = __floats2half2_rn(v4.x + bias, v4.y + bias);
            __half2 h23 = __floats2half2_rn(v4.z + bias, v4.w + bias);
            uint2 w2 = make_uint2(*(uint32_t*)&h01, *(uint32_t*)&h23);
            *(uint2*)&dst[p0 + p4] = w2;
        }
    }
}

// ---------------- 3) transposes (fat tiles, unchanged) ----------------
__global__ __launch_bounds__(256) void transpose_all()
{
    __shared__ char sbuf[35072];
    const int id = blockIdx.x;
    const int tid = threadIdx.x;

    if (id < 512) {
        uint32_t (*tile)[129] = (uint32_t(*)[129])sbuf;
        const int plane = id >> 1;
        const int y0 = (id & 1) * 64;
        const uint32_t* src;
        uint32_t* dst;
        if (plane < BATCH * CQ) { src = g_q + (size_t)plane * NPIX; dst = g_qT + (size_t)plane * NPIX; }
        else { int p = plane - BATCH * CQ; src = g_k + (size_t)p * NPIX; dst = g_kT + (size_t)p * NPIX; }
#pragma unroll
        for (int it = 0; it < 32; it++) {
            int idx = tid + it * 256;
            int row = idx >> 7, col = idx & 127;
            tile[row][col] = src[(size_t)(y0 + row) * HW + col];
        }
        __syncthreads();
#pragma unroll
        for (int it = 0; it < 32; it++) {
            int idx = tid + it * 256;
            int orow = idx >> 6, r = idx & 63;
            dst[(size_t)orow * HW + y0 + r] = tile[r][orow];
        }
    } else {
        ushort (*tile)[137] = (ushort(*)[137])sbuf;
        const int plane = id - 512;
        const uint32_t* src = (const uint32_t*)(g_v + (size_t)plane * NPIX);
        uint32_t*       dst = (uint32_t*)(g_vT + (size_t)plane * NPIX);
#pragma unroll
        for (int it = 0; it < 32; it++) {
            int idx = tid + it * 256;
            int row = idx >> 6, cu = idx & 63;
            uint32_t w = src[row * 64 + cu];
            tile[row][2 * cu]     = (ushort)(w & 0xffff);
            tile[row][2 * cu + 1] = (ushort)(w >> 16);
        }
        __syncthreads();
#pragma unroll
        for (int it = 0; it < 32; it++) {
            int idx = tid + it * 256;
            int oc = idx >> 6, ru = idx & 63;
            uint32_t w = (uint32_t)tile[2 * ru][oc] | ((uint32_t)tile[2 * ru + 1][oc] << 16);
            dst[oc * 64 + ru] = w;
        }
    }
}

// ---------------- 4) fused attention (unchanged R11) ----------------
#define SM_QH   0
#define SM_QL   2048
#define SM_KH   4096
#define SM_KL   6144
#define SM_V0   8192
#define SM_V1   25600
#define SM_OSMH 43008
#define SM_TOTAL 60416

__global__ __launch_bounds__(256, 3) void attn_fused(
    const float* __restrict__ x,
    const float* __restrict__ gamma, float* __restrict__ out)
{
    extern __shared__ char sm[];
    __half* sQh  = (__half*)(sm + SM_QH);
    __half* sQl  = (__half*)(sm + SM_QL);
    __half* sKh  = (__half*)(sm + SM_KH);
    __half* sKl  = (__half*)(sm + SM_KL);
    __half* V0   = (__half*)(sm + SM_V0);
    __half* V1   = (__half*)(sm + SM_V1);
    __half* OsmH = (__half*)(sm + SM_OSMH);
    float*  Ost  = (float*)(sm + SM_V0);

    const uint32_t smem_u32 = (uint32_t)__cvta_generic_to_shared(sm);

    const int line = blockIdx.x;
    const int bh   = blockIdx.y;
    const int bb = bh >> 2, head = bh & 3;
    const int tid  = threadIdx.x;
    const int wid  = tid >> 5;
    const int lane = tid & 31;
    const int qr   = lane >> 2;
    const int qq   = lane & 3;

    const int p_st = tid & 127;
    const int hc   = tid >> 7;

    for (int phase = 0; phase < 2; phase++) {
        if (phase) __syncthreads();
        const uint32_t* qb = phase ? g_qT : g_q;
        const uint32_t* kb = phase ? g_kT : g_k;

        {
            size_t base = ((size_t)(bb * CQ + head * CHQ + 4 * hc) * NPIX)
                        + (size_t)line * HW + p_st;
            uint32_t qv[4], kv[4];
#pragma unroll
            for (int j = 0; j < 4; j++) {
                qv[j] = qb[base + (size_t)j * NPIX];
                kv[j] = kb[base + (size_t)j * NPIX];
            }
            uint2 qhi, qlo, khi, klo;
            qhi.x = (qv[0] & 0xffffu) | (qv[1] << 16);
            qhi.y = (qv[2] & 0xffffu) | (qv[3] << 16);
            qlo.x = (qv[0] >> 16) | (qv[1] & 0xffff0000u);
            qlo.y = (qv[2] >> 16) | (qv[3] & 0xffff0000u);
            khi.x = (kv[0] & 0xffffu) | (kv[1] << 16);
            khi.y = (kv[2] & 0xffffu) | (kv[3] << 16);
            klo.x = (kv[0] >> 16) | (kv[1] & 0xffff0000u);
            klo.y = (kv[2] >> 16) | (kv[3] & 0xffff0000u);
            int so = p_st * 8 + 4 * hc;
            *(uint2*)&sQh[so] = qhi;
            *(uint2*)&sQl[so] = qlo;
            *(uint2*)&sKh[so] = khi;
            *(uint2*)&sKl[so] = klo;
        }

        if (phase == 0) {
#pragma unroll
            for (int i = 0; i < 4; i++) {
                int e = tid + (i << 8);
                int c = e >> 4, p8 = (e & 15) << 3;
                size_t off = ((size_t)(bb * CTOT + head * CHV + c) * NPIX) + (size_t)line * HW + p8;
                cp_async16(smem_u32 + SM_V0 + (uint32_t)(c * 272 + p8 * 2), &g_v[off]);
            }
            asm volatile("cp.async.commit_group;");
#pragma unroll
            for (int i = 0; i < 4; i++) {
                int e = tid + (i << 8);
                int c = e >> 4, p8 = (e & 15) << 3;
                size_t off = ((size_t)(bb * CTOT + head * CHV + c) * NPIX) + (size_t)line * HW + p8;
                cp_async16(smem_u32 + SM_V1 + (uint32_t)(c * 272 + p8 * 2), &g_vT[off]);
            }
            asm volatile("cp.async.commit_group;");
        }
        __syncthreads();

        const __half* Vcur = phase ? V1 : V0;

        const int aoff = (wid * 16 + qr) * 8 + 2 * qq;
        uint32_t aQh0 = *(const uint32_t*)&sQh[aoff];
        uint32_t aQh1 = *(const uint32_t*)&sQh[aoff + 64];
        uint32_t aQl0 = *(const uint32_t*)&sQl[aoff];
        uint32_t aQl1 = *(const uint32_t*)&sQl[aoff + 64];

        float mr = -1e30f, mr8 = -1e30f, sr = 0.f, sr8 = 0.f;
        float oacc[8][4];
#pragma unroll
        for (int nt = 0; nt < 8; nt++)
#pragma unroll
            for (int j = 0; j < 4; j++) oacc[nt][j] = 0.f;

#pragma unroll
        for (int ch = 0; ch < 2; ch++) {
            float acc[8][4];
#pragma unroll
            for (int nt = 0; nt < 8; nt++)
#pragma unroll
                for (int j = 0; j < 4; j++) acc[nt][j] = 0.f;
#pragma unroll
            for (int nt = 0; nt < 8; nt++) {
                int kbx = (ch * 64 + nt * 8 + qr) * 8 + 2 * qq;
                uint32_t bhh = *(const uint32_t*)&sKh[kbx];
                uint32_t bll = *(const uint32_t*)&sKl[kbx];
                mma1688(acc[nt], aQh0, aQh1, bhh);
                mma1688(acc[nt], aQh0, aQh1, bll);
                mma1688(acc[nt], aQl0, aQl1, bhh);
            }

            float cm = -1e30f, cm8 = -1e30f;
#pragma unroll
            for (int nt = 0; nt < 8; nt++) {
                cm  = fmaxf(cm,  fmaxf(acc[nt][0], acc[nt][1]));
                cm8 = fmaxf(cm8, fmaxf(acc[nt][2], acc[nt][3]));
            }
            cm  = fmaxf(cm,  __shfl_xor_sync(0xffffffffu, cm, 1));
            cm  = fmaxf(cm,  __shfl_xor_sync(0xffffffffu, cm, 2));
            cm8 = fmaxf(cm8, __shfl_xor_sync(0xffffffffu, cm8, 1));
            cm8 = fmaxf(cm8, __shfl_xor_sync(0xffffffffu, cm8, 2));

            float nm  = fmaxf(mr, cm);
            float nm8 = fmaxf(mr8, cm8);
            float sc  = __expf(mr - nm);
            float sc8 = __expf(mr8 - nm8);
            mr = nm; mr8 = nm8;
            sr *= sc; sr8 *= sc8;
#pragma unroll
            for (int nt = 0; nt < 8; nt++) {
                oacc[nt][0] *= sc;  oacc[nt][1] *= sc;
                oacc[nt][2] *= sc8; oacc[nt][3] *= sc8;
            }

            float cs = 0.f, cs8 = 0.f;
#pragma unroll
            for (int nt = 0; nt < 8; nt++) {
                acc[nt][0] = __expf(acc[nt][0] - nm);
                acc[nt][1] = __expf(acc[nt][1] - nm);
                acc[nt][2] = __expf(acc[nt][2] - nm8);
                acc[nt][3] = __expf(acc[nt][3] - nm8);
                cs  += acc[nt][0] + acc[nt][1];
                cs8 += acc[nt][2] + acc[nt][3];
            }
            cs  += __shfl_xor_sync(0xffffffffu, cs, 1);
            cs  += __shfl_xor_sync(0xffffffffu, cs, 2);
            cs8 += __shfl_xor_sync(0xffffffffu, cs8, 1);
            cs8 += __shfl_xor_sync(0xffffffffu, cs8, 2);
            sr  += cs;  sr8 += cs8;

            uint32_t Af[4][4];
#pragma unroll
            for (int kt = 0; kt < 4; kt++) {
                __half2 h0 = __floats2half2_rn(acc[2 * kt][0],     acc[2 * kt][1]);
                __half2 h1 = __floats2half2_rn(acc[2 * kt][2],     acc[2 * kt][3]);
                __half2 h2 = __floats2half2_rn(acc[2 * kt + 1][0], acc[2 * kt + 1][1]);
                __half2 h3 = __floats2half2_rn(acc[2 * kt + 1][2], acc[2 * kt + 1][3]);
                Af[kt][0] = *(uint32_t*)&h0;
                Af[kt][1] = *(uint32_t*)&h1;
                Af[kt][2] = *(uint32_t*)&h2;
                Af[kt][3] = *(uint32_t*)&h3;
            }

            if (ch == 0) {
                if (phase == 0) asm volatile("cp.async.wait_group 1;" ::: "memory");
                else            asm volatile("cp.async.wait_group 0;" ::: "memory");
                __syncthreads();
            }

#pragma unroll
            for (int kt = 0; kt < 4; kt++) {
#pragma unroll
                for (int nt = 0; nt < 8; nt++) {
                    int vb0 = (8 * nt + qr) * 136 + ch * 64 + 16 * kt + 2 * qq;
                    uint32_t bh0 = *(const uint32_t*)&Vcur[vb0];
                    uint32_t bh1 = *(const uint32_t*)&Vcur[vb0 + 8];
                    mma16816(oacc[nt], Af[kt], bh0, bh1);
                }
            }
        }

        const float inv_r  = 1.f / sr;
        const float inv_r8 = 1.f / sr8;
        const int   r  = wid * 16 + qr;
        const int   r8 = r + 8;

        if (phase == 0) {
#pragma unroll
            for (int nt = 0; nt < 8; nt++) {
                int c0 = 8 * nt + 2 * qq;
                OsmH[c0 * 136 + r]        = __float2half_rn(oacc[nt][0] * inv_r);
                OsmH[(c0 + 1) * 136 + r]  = __float2half_rn(oacc[nt][1] * inv_r);
                OsmH[c0 * 136 + r8]       = __float2half_rn(oacc[nt][2] * inv_r8);
                OsmH[(c0 + 1) * 136 + r8] = __float2half_rn(oacc[nt][3] * inv_r8);
            }
        } else {
            const float g = gamma[0];
#pragma unroll
            for (int half = 0; half < 2; half++) {
                __syncthreads();
#pragma unroll
                for (int nt = half * 4; nt < half * 4 + 4; nt++) {
                    int cg = 8 * nt + 2 * qq;
                    int cl = cg - 32 * half;
                    Ost[cl * 132 + r]        = oacc[nt][0] * inv_r;
                    Ost[(cl + 1) * 132 + r]  = oacc[nt][1] * inv_r;
                    Ost[cl * 132 + r8]       = oacc[nt][2] * inv_r8;
                    Ost[(cl + 1) * 132 + r8] = oacc[nt][3] * inv_r8;
                }
                __syncthreads();
#pragma unroll
                for (int i = 0; i < 4; i++) {
                    int e = tid + (i << 8);
                    int c = e >> 5, p4 = (e & 31) << 2;
                    int cg = c + 32 * half;
                    size_t off = ((size_t)(bb * CTOT + head * CHV + cg) * HW + line) * HW + p4;
                    float4 ov = *(float4*)&Ost[c * 132 + p4];
                    uint2 ohw = *(uint2*)&OsmH[cg * 136 + p4];
                    float2 oh01 = __half22float2(*(__half2*)&ohw.x);
                    float2 oh23 = __half22float2(*(__half2*)&ohw.y);
                    float4 xv = *(const float4*)&x[off];
                    float4 r4;
                    r4.x = g * (oh01.x + ov.x) + xv.x;
                    r4.y = g * (oh01.y + ov.y) + xv.y;
                    r4.z = g * (oh23.x + ov.z) + xv.z;
                    r4.w = g * (oh23.y + ov.w) + xv.w;
                    *(float4*)&out[off] = r4;
                }
            }
        }
    }
}

// ---------------- launch ----------------
extern "C" void kernel_launch(void* const* d_in, const int* in_sizes, int n_in,
                              void* d_out, int out_size)
{
    const float* x     = (const float*)d_in[0];
    const float* Wq    = (const float*)d_in[1];
    const float* bq    = (const float*)d_in[2];
    const float* Wk    = (const float*)d_in[3];
    const float* bk    = (const float*)d_in[4];
    const float* Wv    = (const float*)d_in[5];
    const float* bv    = (const float*)d_in[6];
    const float* gamma = (const float*)d_in[7];
    float* out = (float*)d_out;

    convert_all<<<8352, 256>>>(x, Wq, Wk, Wv);
    proj_qk<<<dim3(128, 1, 4), 256, PJ_SM>>>(x, bq, bk);
    proj_v<<<dim3(128, 2, 4), 256, PJ_SM>>>(bv);
    transpose_all<<<1536, 256>>>();

    cudaFuncSetAttribute(attn_fused, cudaFuncAttributeMaxDynamicSharedMemorySize, SM_TOTAL);
    attn_fused<<<dim3(HW, 16), 256, SM_TOTAL>>>(x, gamma, out);
}

// round 13
// speedup vs baseline: 4.7928x; 1.0658x over previous
#include <cuda_runtime.h>
#include <cuda_fp16.h>
#include <cstdint>

// CrissCrossAttention — R13:
//   1) convert_w  : W hi/lo split only (X convert pass ELIMINATED)
//   2) proj_qk    : reads x fp32, inline hi/lo split       (unchanged R12)
//      proj_v     : BM=128, reads x fp32 directly, hi-only inline conversion
//   3) transpose_all : unchanged
//   4) attn_fused : phase-1 epilogue single-pass via fp16 O_v staging

#define BATCH 4
#define CTOT 256
#define HW   128
#define CQ   32
#define CHQ  8
#define CHV  64
#define NPIX (HW*HW)

// ---------------- scratch ----------------
__device__ uint32_t g_q  [BATCH*CQ*NPIX];    // packed (hi,lo)
__device__ uint32_t g_k  [BATCH*CQ*NPIX];
__device__ uint32_t g_qT [BATCH*CQ*NPIX];
__device__ uint32_t g_kT [BATCH*CQ*NPIX];
__device__ __half   g_v  [BATCH*CTOT*NPIX];  // fp16 hi only
__device__ __half   g_vT [BATCH*CTOT*NPIX];
__device__ uint32_t g_whp[320*128];
__device__ uint32_t g_wlp[320*128];

__device__ __forceinline__ uint32_t pack2(__half a, __half b)
{
    __half2 t = __halves2half2(a, b);
    return *(uint32_t*)&t;
}

__device__ __forceinline__ void mma16816(float* d, const uint32_t* a, uint32_t b0, uint32_t b1)
{
    asm volatile(
        "mma.sync.aligned.m16n8k16.row.col.f32.f16.f16.f32 "
        "{%0,%1,%2,%3},{%4,%5,%6,%7},{%8,%9},{%0,%1,%2,%3};"
        : "+f"(d[0]), "+f"(d[1]), "+f"(d[2]), "+f"(d[3])
        : "r"(a[0]), "r"(a[1]), "r"(a[2]), "r"(a[3]), "r"(b0), "r"(b1));
}

__device__ __forceinline__ void mma1688(float* d, uint32_t a0, uint32_t a1, uint32_t b0)
{
    asm volatile(
        "mma.sync.aligned.m16n8k8.row.col.f32.f16.f16.f32 "
        "{%0,%1,%2,%3},{%4,%5},{%6},{%0,%1,%2,%3};"
        : "+f"(d[0]), "+f"(d[1]), "+f"(d[2]), "+f"(d[3])
        : "r"(a0), "r"(a1), "r"(b0));
}

__device__ __forceinline__ void cp_async16(uint32_t saddr, const void* gptr)
{
    asm volatile("cp.async.cg.shared.global [%0], [%1], 16;" :: "r"(saddr), "l"(gptr));
}

// ---------------- 1) W convert only ----------------
__global__ __launch_bounds__(256) void convert_w(
    const float* __restrict__ Wq, const float* __restrict__ Wk,
    const float* __restrict__ Wv)
{
    int idx = blockIdx.x * 256 + threadIdx.x;
    if (idx >= 320 * 128) return;
    int m = idx >> 7, kq = idx & 127;
    const float* wr;
    if (m < 32)      wr = Wq + (size_t)m * 256;
    else if (m < 64) wr = Wk + (size_t)(m - 32) * 256;
    else             wr = Wv + (size_t)(m - 64) * 256;
    float w0 = wr[2 * kq], w1 = wr[2 * kq + 1];
    __half h0 = __float2half_rn(w0), h1 = __float2half_rn(w1);
    __half l0 = __float2half_rn(w0 - __half2float(h0));
    __half l1 = __float2half_rn(w1 - __half2float(h1));
    g_whp[idx] = pack2(h0, h1);
    g_wlp[idx] = pack2(l0, l1);
}

// ---------------- 2a) q/k projection (3-term; reads x fp32, inline split) ----------------
#define PJ_SM 33792

__global__ __launch_bounds__(256) void proj_qk(
    const float* __restrict__ x,
    const float* __restrict__ bq, const float* __restrict__ bk)
{
    extern __shared__ char sm[];
    uint32_t* Wh2s = (uint32_t*)(sm);
    uint32_t* Wl2s = (uint32_t*)(sm + 5120);
    uint32_t* Xh2s = (uint32_t*)(sm + 10240);
    uint32_t* Xl2s = (uint32_t*)(sm + 18944);
    float*    Osm  = (float*)sm;

    const int bb = blockIdx.z;
    const int p0 = blockIdx.x * 128;
    const int tid = threadIdx.x;
    const int wid = tid >> 5, lane = tid & 31;
    const int wm = wid & 1, wp = wid >> 1;
    const int gr = lane >> 2, gq = lane & 3;

    const float* xb = x + (size_t)bb * CTOT * NPIX;

    float acc[2][4][4];
#pragma unroll
    for (int mt = 0; mt < 2; mt++)
#pragma unroll
        for (int nt = 0; nt < 4; nt++)
#pragma unroll
            for (int j = 0; j < 4; j++) acc[mt][nt][j] = 0.f;

    uint32_t pwh[4], pwl[4];
    float pf0[8], pf1[8];

#pragma unroll
    for (int i = 0; i < 4; i++) {
        int e = tid + i * 256;
        size_t goff = (size_t)(e >> 4) * 128 + (e & 15);
        pwh[i] = g_whp[goff];
        pwl[i] = g_wlp[goff];
    }
#pragma unroll
    for (int i = 0; i < 8; i++) {
        int e = tid + i * 256;
        int kq = e >> 7, p = e & 127;
        size_t goff = (size_t)(2 * kq) * NPIX + p0 + p;
        pf0[i] = xb[goff];
        pf1[i] = xb[goff + NPIX];
    }

    for (int chunk = 0; chunk < 8; chunk++) {
#pragma unroll
        for (int i = 0; i < 4; i++) {
            int e = tid + i * 256;
            Wh2s[(e >> 4) * 20 + (e & 15)] = pwh[i];
            Wl2s[(e >> 4) * 20 + (e & 15)] = pwl[i];
        }
#pragma unroll
        for (int i = 0; i < 8; i++) {
            int e = tid + i * 256;
            int kq = e >> 7, p = e & 127;
            __half h0 = __float2half_rn(pf0[i]);
            __half l0 = __float2half_rn(pf0[i] - __half2float(h0));
            __half h1 = __float2half_rn(pf1[i]);
            __half l1 = __float2half_rn(pf1[i] - __half2float(h1));
            Xh2s[kq * 136 + p] = pack2(h0, h1);
            Xl2s[kq * 136 + p] = pack2(l0, l1);
        }
        __syncthreads();

        if (chunk < 7) {
            const int kq0 = (chunk + 1) * 16;
#pragma unroll
            for (int i = 0; i < 4; i++) {
                int e = tid + i * 256;
                size_t goff = (size_t)(e >> 4) * 128 + kq0 + (e & 15);
                pwh[i] = g_whp[goff];
                pwl[i] = g_wlp[goff];
            }
#pragma unroll
            for (int i = 0; i < 8; i++) {
                int e = tid + i * 256;
                int kq = e >> 7, p = e & 127;
                size_t goff = (size_t)(2 * (kq0 + kq)) * NPIX + p0 + p;
                pf0[i] = xb[goff];
                pf1[i] = xb[goff + NPIX];
            }
        }

#pragma unroll
        for (int s = 0; s < 2; s++) {
            uint32_t Ah[2][4], Al[2][4];
#pragma unroll
            for (int mt = 0; mt < 2; mt++) {
                int base = (wm * 32 + mt * 16 + gr) * 20 + s * 8 + gq;
                Ah[mt][0] = Wh2s[base];
                Ah[mt][1] = Wh2s[base + 8 * 20];
                Ah[mt][2] = Wh2s[base + 4];
                Ah[mt][3] = Wh2s[base + 8 * 20 + 4];
                Al[mt][0] = Wl2s[base];
                Al[mt][1] = Wl2s[base + 8 * 20];
                Al[mt][2] = Wl2s[base + 4];
                Al[mt][3] = Wl2s[base + 8 * 20 + 4];
            }
#pragma unroll
            for (int nt = 0; nt < 4; nt++) {
                int p  = wp * 32 + nt * 8 + gr;
                int xbx = (s * 8 + gq) * 136 + p;
                uint32_t bh0 = Xh2s[xbx];
                uint32_t bh1 = Xh2s[xbx + 4 * 136];
                uint32_t bl0 = Xl2s[xbx];
                uint32_t bl1 = Xl2s[xbx + 4 * 136];
#pragma unroll
                for (int mt = 0; mt < 2; mt++) {
                    mma16816(acc[mt][nt], Ah[mt], bh0, bh1);
                    mma16816(acc[mt][nt], Ah[mt], bl0, bl1);
                    mma16816(acc[mt][nt], Al[mt], bh0, bh1);
                }
            }
        }
        __syncthreads();
    }

#pragma unroll
    for (int mt = 0; mt < 2; mt++)
#pragma unroll
        for (int nt = 0; nt < 4; nt++) {
            int row = wm * 32 + mt * 16 + gr;
            int p   = wp * 32 + nt * 8 + 2 * gq;
            Osm[row * 132 + p]           = acc[mt][nt][0];
            Osm[row * 132 + p + 1]       = acc[mt][nt][1];
            Osm[(row + 8) * 132 + p]     = acc[mt][nt][2];
            Osm[(row + 8) * 132 + p + 1] = acc[mt][nt][3];
        }
    __syncthreads();

#pragma unroll
    for (int i = 0; i < 8; i++) {
        int e = tid + i * 256;
        int r = e >> 5, p4 = (e & 31) << 2;
        float bias = (r < 32) ? bq[r] : bk[r - 32];
        uint32_t* dst = (r < 32) ? g_q + (size_t)(bb * CQ + r) * NPIX
                                 : g_k + (size_t)(bb * CQ + r - 32) * NPIX;
        float4 v4 = *(float4*)&Osm[r * 132 + p4];
        float vv[4] = {v4.x + bias, v4.y + bias, v4.z + bias, v4.w + bias};
        uint32_t w[4];
#pragma unroll
        for (int j = 0; j < 4; j++) {
            __half h = __float2half_rn(vv[j]);
            __half l = __float2half_rn(vv[j] - __half2float(h));
            w[j] = pack2(h, l);
        }
        *(uint4*)&dst[p0 + p4] = make_uint4(w[0], w[1], w[2], w[3]);
    }
}

// ---------------- 2b) v projection, BM=128, reads x fp32 (hi-only inline) ----------------
__global__ __launch_bounds__(256) void proj_v(
    const float* __restrict__ x, const float* __restrict__ bv)
{
    extern __shared__ char sm[];
    uint32_t* Wh2s = (uint32_t*)(sm);
    uint32_t* Xh2s = (uint32_t*)(sm + 10240);
    float*    Osm  = (float*)sm;

    const int bb = blockIdx.z;
    const int m0 = 64 + blockIdx.y * 128;
    const int p0 = blockIdx.x * 128;
    const int tid = threadIdx.x;
    const int wid = tid >> 5, lane = tid & 31;
    const int wm = wid & 1, wp = wid >> 1;
    const int gr = lane >> 2, gq = lane & 3;

    const float* xb = x + (size_t)bb * CTOT * NPIX;

    float acc[4][4][4];
#pragma unroll
    for (int mt = 0; mt < 4; mt++)
#pragma unroll
        for (int nt = 0; nt < 4; nt++)
#pragma unroll
            for (int j = 0; j < 4; j++) acc[mt][nt][j] = 0.f;

    uint32_t pwh[8];
    float pf0[8], pf1[8];
#pragma unroll
    for (int i = 0; i < 8; i++) {
        int e = tid + i * 256;
        pwh[i] = g_whp[(size_t)(m0 + (e >> 4)) * 128 + (e & 15)];
    }
#pragma unroll
    for (int i = 0; i < 8; i++) {
        int e = tid + i * 256;
        int kq = e >> 7, p = e & 127;
        size_t goff = (size_t)(2 * kq) * NPIX + p0 + p;
        pf0[i] = xb[goff];
        pf1[i] = xb[goff + NPIX];
    }

    for (int chunk = 0; chunk < 8; chunk++) {
#pragma unroll
        for (int i = 0; i < 8; i++) {
            int e = tid + i * 256;
            Wh2s[(e >> 4) * 20 + (e & 15)] = pwh[i];
        }
#pragma unroll
        for (int i = 0; i < 8; i++) {
            int e = tid + i * 256;
            int kq = e >> 7, p = e & 127;
            Xh2s[kq * 136 + p] = pack2(__float2half_rn(pf0[i]), __float2half_rn(pf1[i]));
        }
        __syncthreads();

        if (chunk < 7) {
            const int kq0 = (chunk + 1) * 16;
#pragma unroll
            for (int i = 0; i < 8; i++) {
                int e = tid + i * 256;
                pwh[i] = g_whp[(size_t)(m0 + (e >> 4)) * 128 + kq0 + (e & 15)];
            }
#pragma unroll
            for (int i = 0; i < 8; i++) {
                int e = tid + i * 256;
                int kq = e >> 7, p = e & 127;
                size_t goff = (size_t)(2 * (kq0 + kq)) * NPIX + p0 + p;
                pf0[i] = xb[goff];
                pf1[i] = xb[goff + NPIX];
            }
        }

#pragma unroll
        for (int s = 0; s < 2; s++) {
            uint32_t Ah[4][4];
#pragma unroll
            for (int mt = 0; mt < 4; mt++) {
                int base = (wm * 64 + mt * 16 + gr) * 20 + s * 8 + gq;
                Ah[mt][0] = Wh2s[base];
                Ah[mt][1] = Wh2s[base + 8 * 20];
                Ah[mt][2] = Wh2s[base + 4];
                Ah[mt][3] = Wh2s[base + 8 * 20 + 4];
            }
#pragma unroll
            for (int nt = 0; nt < 4; nt++) {
                int p  = wp * 32 + nt * 8 + gr;
                int xbx = (s * 8 + gq) * 136 + p;
                uint32_t bh0 = Xh2s[xbx];
                uint32_t bh1 = Xh2s[xbx + 4 * 136];
#pragma unroll
                for (int mt = 0; mt < 4; mt++)
                    mma16816(acc[mt][nt], Ah[mt], bh0, bh1);
            }
        }
        __syncthreads();
    }

    // epilogue: two 64-row halves through the smem overlay
#pragma unroll
    for (int h = 0; h < 2; h++) {
        __syncthreads();
        if (wm == h) {
#pragma unroll
            for (int mt = 0; mt < 4; mt++)
#pragma unroll
                for (int nt = 0; nt < 4; nt++) {
                    int row = mt * 16 + gr;
                    int p   = wp * 32 + nt * 8 + 2 * gq;
                    Osm[row * 132 + p]           = acc[mt][nt][0];
                    Osm[row * 132 + p + 1]       = acc[mt][nt][1];
                    Osm[(row + 8) * 132 + p]     = acc[mt][nt][2];
                    Osm[(row + 8) * 132 + p + 1] = acc[mt][nt][3];
                }
        }
        __syncthreads();
#pragma unroll
        for (int i = 0; i < 8; i++) {
            int e = tid + i * 256;
            int row = e >> 5, p4 = (e & 31) << 2;
            int r = m0 + h * 64 + row;
            float bias = bv[r - 64];
            __half* dst = g_v + (size_t)(bb * CTOT + r - 64) * NPIX;
            float4 v4 = *(float4*)&Osm[row * 132 + p4];
            __half2 h01 = __floats2half2_rn(v4.x + bias, v4.y + bias);
            __half2 h23 = __floats2half2_rn(v4.z + bias, v4.w + bias);
            uint2 w2 = make_uint2(*(uint32_t*)&h01, *(uint32_t*)&h23);
            *(uint2*)&dst[p0 + p4] = w2;
        }
    }
}

// ---------------- 3) transposes (fat tiles, unchanged) ----------------
__global__ __launch_bounds__(256) void transpose_all()
{
    __shared__ char sbuf[35072];
    const int id = blockIdx.x;
    const int tid = threadIdx.x;

    if (id < 512) {
        uint32_t (*tile)[129] = (uint32_t(*)[129])sbuf;
        const int plane = id >> 1;
        const int y0 = (id & 1) * 64;
        const uint32_t* src;
        uint32_t* dst;
        if (plane < BATCH * CQ) { src = g_q + (size_t)plane * NPIX; dst = g_qT + (size_t)plane * NPIX; }
        else { int p = plane - BATCH * CQ; src = g_k + (size_t)p * NPIX; dst = g_kT + (size_t)p * NPIX; }
#pragma unroll
        for (int it = 0; it < 32; it++) {
            int idx = tid + it * 256;
            int row = idx >> 7, col = idx & 127;
            tile[row][col] = src[(size_t)(y0 + row) * HW + col];
        }
        __syncthreads();
#pragma unroll
        for (int it = 0; it < 32; it++) {
            int idx = tid + it * 256;
            int orow = idx >> 6, r = idx & 63;
            dst[(size_t)orow * HW + y0 + r] = tile[r][orow];
        }
    } else {
        ushort (*tile)[137] = (ushort(*)[137])sbuf;
        const int plane = id - 512;
        const uint32_t* src = (const uint32_t*)(g_v + (size_t)plane * NPIX);
        uint32_t*       dst = (uint32_t*)(g_vT + (size_t)plane * NPIX);
#pragma unroll
        for (int it = 0; it < 32; it++) {
            int idx = tid + it * 256;
            int row = idx >> 6, cu = idx & 63;
            uint32_t w = src[row * 64 + cu];
            tile[row][2 * cu]     = (ushort)(w & 0xffff);
            tile[row][2 * cu + 1] = (ushort)(w >> 16);
        }
        __syncthreads();
#pragma unroll
        for (int it = 0; it < 32; it++) {
            int idx = tid + it * 256;
            int oc = idx >> 6, ru = idx & 63;
            uint32_t w = (uint32_t)tile[2 * ru][oc] | ((uint32_t)tile[2 * ru + 1][oc] << 16);
            dst[oc * 64 + ru] = w;
        }
    }
}

// ---------------- 4) fused attention ----------------
#define SM_QH   0
#define SM_QL   2048
#define SM_KH   4096
#define SM_KL   6144
#define SM_V0   8192
#define SM_V1   25600
#define SM_OSMH 43008
#define SM_TOTAL 60416

__global__ __launch_bounds__(256, 3) void attn_fused(
    const float* __restrict__ x,
    const float* __restrict__ gamma, float* __restrict__ out)
{
    extern __shared__ char sm[];
    __half* sQh  = (__half*)(sm + SM_QH);
    __half* sQl  = (__half*)(sm + SM_QL);
    __half* sKh  = (__half*)(sm + SM_KH);
    __half* sKl  = (__half*)(sm + SM_KL);
    __half* V0   = (__half*)(sm + SM_V0);
    __half* V1   = (__half*)(sm + SM_V1);
    __half* OsmH = (__half*)(sm + SM_OSMH);
    __half* OstH = (__half*)(sm + SM_V0);   // phase-1 O_v staging (64x136 half = 17408)

    const uint32_t smem_u32 = (uint32_t)__cvta_generic_to_shared(sm);

    const int line = blockIdx.x;
    const int bh   = blockIdx.y;
    const int bb = bh >> 2, head = bh & 3;
    const int tid  = threadIdx.x;
    const int wid  = tid >> 5;
    const int lane = tid & 31;
    const int qr   = lane >> 2;
    const int qq   = lane & 3;

    const int p_st = tid & 127;
    const int hc   = tid >> 7;

    for (int phase = 0; phase < 2; phase++) {
        if (phase) __syncthreads();
        const uint32_t* qb = phase ? g_qT : g_q;
        const uint32_t* kb = phase ? g_kT : g_k;

        {
            size_t base = ((size_t)(bb * CQ + head * CHQ + 4 * hc) * NPIX)
                        + (size_t)line * HW + p_st;
            uint32_t qv[4], kv[4];
#pragma unroll
            for (int j = 0; j < 4; j++) {
                qv[j] = qb[base + (size_t)j * NPIX];
                kv[j] = kb[base + (size_t)j * NPIX];
            }
            uint2 qhi, qlo, khi, klo;
            qhi.x = (qv[0] & 0xffffu) | (qv[1] << 16);
            qhi.y = (qv[2] & 0xffffu) | (qv[3] << 16);
            qlo.x = (qv[0] >> 16) | (qv[1] & 0xffff0000u);
            qlo.y = (qv[2] >> 16) | (qv[3] & 0xffff0000u);
            khi.x = (kv[0] & 0xffffu) | (kv[1] << 16);
            khi.y = (kv[2] & 0xffffu) | (kv[3] << 16);
            klo.x = (kv[0] >> 16) | (kv[1] & 0xffff0000u);
            klo.y = (kv[2] >> 16) | (kv[3] & 0xffff0000u);
            int so = p_st * 8 + 4 * hc;
            *(uint2*)&sQh[so] = qhi;
            *(uint2*)&sQl[so] = qlo;
            *(uint2*)&sKh[so] = khi;
            *(uint2*)&sKl[so] = klo;
        }

        if (phase == 0) {
#pragma unroll
            for (int i = 0; i < 4; i++) {
                int e = tid + (i << 8);
                int c = e >> 4, p8 = (e & 15) << 3;
                size_t off = ((size_t)(bb * CTOT + head * CHV + c) * NPIX) + (size_t)line * HW + p8;
                cp_async16(smem_u32 + SM_V0 + (uint32_t)(c * 272 + p8 * 2), &g_v[off]);
            }
            asm volatile("cp.async.commit_group;");
#pragma unroll
            for (int i = 0; i < 4; i++) {
                int e = tid + (i << 8);
                int c = e >> 4, p8 = (e & 15) << 3;
                size_t off = ((size_t)(bb * CTOT + head * CHV + c) * NPIX) + (size_t)line * HW + p8;
                cp_async16(smem_u32 + SM_V1 + (uint32_t)(c * 272 + p8 * 2), &g_vT[off]);
            }
            asm volatile("cp.async.commit_group;");
        }
        __syncthreads();

        const __half* Vcur = phase ? V1 : V0;

        const int aoff = (wid * 16 + qr) * 8 + 2 * qq;
        uint32_t aQh0 = *(const uint32_t*)&sQh[aoff];
        uint32_t aQh1 = *(const uint32_t*)&sQh[aoff + 64];
        uint32_t aQl0 = *(const uint32_t*)&sQl[aoff];
        uint32_t aQl1 = *(const uint32_t*)&sQl[aoff + 64];

        float mr = -1e30f, mr8 = -1e30f, sr = 0.f, sr8 = 0.f;
        float oacc[8][4];
#pragma unroll
        for (int nt = 0; nt < 8; nt++)
#pragma unroll
            for (int j = 0; j < 4; j++) oacc[nt][j] = 0.f;

#pragma unroll
        for (int ch = 0; ch < 2; ch++) {
            float acc[8][4];
#pragma unroll
            for (int nt = 0; nt < 8; nt++)
#pragma unroll
                for (int j = 0; j < 4; j++) acc[nt][j] = 0.f;
#pragma unroll
            for (int nt = 0; nt < 8; nt++) {
                int kbx = (ch * 64 + nt * 8 + qr) * 8 + 2 * qq;
                uint32_t bhh = *(const uint32_t*)&sKh[kbx];
                uint32_t bll = *(const uint32_t*)&sKl[kbx];
                mma1688(acc[nt], aQh0, aQh1, bhh);
                mma1688(acc[nt], aQh0, aQh1, bll);
                mma1688(acc[nt], aQl0, aQl1, bhh);
            }

            float cm = -1e30f, cm8 = -1e30f;
#pragma unroll
            for (int nt = 0; nt < 8; nt++) {
                cm  = fmaxf(cm,  fmaxf(acc[nt][0], acc[nt][1]));
                cm8 = fmaxf(cm8, fmaxf(acc[nt][2], acc[nt][3]));
            }
            cm  = fmaxf(cm,  __shfl_xor_sync(0xffffffffu, cm, 1));
            cm  = fmaxf(cm,  __shfl_xor_sync(0xffffffffu, cm, 2));
            cm8 = fmaxf(cm8, __shfl_xor_sync(0xffffffffu, cm8, 1));
            cm8 = fmaxf(cm8, __shfl_xor_sync(0xffffffffu, cm8, 2));

            float nm  = fmaxf(mr, cm);
            float nm8 = fmaxf(mr8, cm8);
            float sc  = __expf(mr - nm);
            float sc8 = __expf(mr8 - nm8);
            mr = nm; mr8 = nm8;
            sr *= sc; sr8 *= sc8;
#pragma unroll
            for (int nt = 0; nt < 8; nt++) {
                oacc[nt][0] *= sc;  oacc[nt][1] *= sc;
                oacc[nt][2] *= sc8; oacc[nt][3] *= sc8;
            }

            float cs = 0.f, cs8 = 0.f;
#pragma unroll
            for (int nt = 0; nt < 8; nt++) {
                acc[nt][0] = __expf(acc[nt][0] - nm);
                acc[nt][1] = __expf(acc[nt][1] - nm);
                acc[nt][2] = __expf(acc[nt][2] - nm8);
                acc[nt][3] = __expf(acc[nt][3] - nm8);
                cs  += acc[nt][0] + acc[nt][1];
                cs8 += acc[nt][2] + acc[nt][3];
            }
            cs  += __shfl_xor_sync(0xffffffffu, cs, 1);
            cs  += __shfl_xor_sync(0xffffffffu, cs, 2);
            cs8 += __shfl_xor_sync(0xffffffffu, cs8, 1);
            cs8 += __shfl_xor_sync(0xffffffffu, cs8, 2);
            sr  += cs;  sr8 += cs8;

            uint32_t Af[4][4];
#pragma unroll
            for (int kt = 0; kt < 4; kt++) {
                __half2 h0 = __floats2half2_rn(acc[2 * kt][0],     acc[2 * kt][1]);
                __half2 h1 = __floats2half2_rn(acc[2 * kt][2],     acc[2 * kt][3]);
                __half2 h2 = __floats2half2_rn(acc[2 * kt + 1][0], acc[2 * kt + 1][1]);
                __half2 h3 = __floats2half2_rn(acc[2 * kt + 1][2], acc[2 * kt + 1][3]);
                Af[kt][0] = *(uint32_t*)&h0;
                Af[kt][1] = *(uint32_t*)&h1;
                Af[kt][2] = *(uint32_t*)&h2;
                Af[kt][3] = *(uint32_t*)&h3;
            }

            if (ch == 0) {
                if (phase == 0) asm volatile("cp.async.wait_group 1;" ::: "memory");
                else            asm volatile("cp.async.wait_group 0;" ::: "memory");
                __syncthreads();
            }

#pragma unroll
            for (int kt = 0; kt < 4; kt++) {
#pragma unroll
                for (int nt = 0; nt < 8; nt++) {
                    int vb0 = (8 * nt + qr) * 136 + ch * 64 + 16 * kt + 2 * qq;
                    uint32_t bh0 = *(const uint32_t*)&Vcur[vb0];
                    uint32_t bh1 = *(const uint32_t*)&Vcur[vb0 + 8];
                    mma16816(oacc[nt], Af[kt], bh0, bh1);
                }
            }
        }

        const float inv_r  = 1.f / sr;
        const float inv_r8 = 1.f / sr8;
        const int   r  = wid * 16 + qr;
        const int   r8 = r + 8;

        if (phase == 0) {
#pragma unroll
            for (int nt = 0; nt < 8; nt++) {
                int c0 = 8 * nt + 2 * qq;
                OsmH[c0 * 136 + r]        = __float2half_rn(oacc[nt][0] * inv_r);
                OsmH[(c0 + 1) * 136 + r]  = __float2half_rn(oacc[nt][1] * inv_r);
                OsmH[c0 * 136 + r8]       = __float2half_rn(oacc[nt][2] * inv_r8);
                OsmH[(c0 + 1) * 136 + r8] = __float2half_rn(oacc[nt][3] * inv_r8);
            }
        } else {
            // single-pass epilogue: stage O_v fp16 in V0 region (dead in phase 1)
            const float g = gamma[0];
#pragma unroll
            for (int nt = 0; nt < 8; nt++) {
                int c0 = 8 * nt + 2 * qq;
                OstH[c0 * 136 + r]        = __float2half_rn(oacc[nt][0] * inv_r);
                OstH[(c0 + 1) * 136 + r]  = __float2half_rn(oacc[nt][1] * inv_r);
                OstH[c0 * 136 + r8]       = __float2half_rn(oacc[nt][2] * inv_r8);
                OstH[(c0 + 1) * 136 + r8] = __float2half_rn(oacc[nt][3] * inv_r8);
            }
            __syncthreads();
#pragma unroll
            for (int i = 0; i < 4; i++) {
                int e = tid + (i << 8);
                int c = e >> 4, p8 = (e & 15) << 3;
                size_t off = ((size_t)(bb * CTOT + head * CHV + c) * HW + line) * HW + p8;
                uint4 ow = *(uint4*)&OstH[c * 136 + p8];
                uint4 hw = *(uint4*)&OsmH[c * 136 + p8];
                float4 x0 = *(const float4*)&x[off];
                float4 x1 = *(const float4*)&x[off + 4];
                float2 ov01 = __half22float2(*(__half2*)&ow.x);
                float2 ov23 = __half22float2(*(__half2*)&ow.y);
                float2 ov45 = __half22float2(*(__half2*)&ow.z);
                float2 ov67 = __half22float2(*(__half2*)&ow.w);
                float2 oh01 = __half22float2(*(__half2*)&hw.x);
                float2 oh23 = __half22float2(*(__half2*)&hw.y);
                float2 oh45 = __half22float2(*(__half2*)&hw.z);
                float2 oh67 = __half22float2(*(__half2*)&hw.w);
                float4 r0, r1;
                r0.x = g * (oh01.x + ov01.x) + x0.x;
                r0.y = g * (oh01.y + ov01.y) + x0.y;
                r0.z = g * (oh23.x + ov23.x) + x0.z;
                r0.w = g * (oh23.y + ov23.y) + x0.w;
                r1.x = g * (oh45.x + ov45.x) + x1.x;
                r1.y = g * (oh45.y + ov45.y) + x1.y;
                r1.z = g * (oh67.x + ov67.x) + x1.z;
                r1.w = g * (oh67.y + ov67.y) + x1.w;
                *(float4*)&out[off]     = r0;
                *(float4*)&out[off + 4] = r1;
            }
        }
    }
}

// ---------------- launch ----------------
extern "C" void kernel_launch(void* const* d_in, const int* in_sizes, int n_in,
                              void* d_out, int out_size)
{
    const float* x     = (const float*)d_in[0];
    const float* Wq    = (const float*)d_in[1];
    const float* bq    = (const float*)d_in[2];
    const float* Wk    = (const float*)d_in[3];
    const float* bk    = (const float*)d_in[4];
    const float* Wv    = (const float*)d_in[5];
    const float* bv    = (const float*)d_in[6];
    const float* gamma = (const float*)d_in[7];
    float* out = (float*)d_out;

    convert_w<<<160, 256>>>(Wq, Wk, Wv);
    proj_qk<<<dim3(128, 1, 4), 256, PJ_SM>>>(x, bq, bk);
    proj_v<<<dim3(128, 2, 4), 256, PJ_SM>>>(x, bv);
    transpose_all<<<1536, 256>>>();

    cudaFuncSetAttribute(attn_fused, cudaFuncAttributeMaxDynamicSharedMemorySize, SM_TOTAL);
    attn_fused<<<dim3(HW, 16), 256, SM_TOTAL>>>(x, gamma, out);
}

// round 15
// speedup vs baseline: 4.9390x; 1.0305x over previous
#include <cuda_runtime.h>
#include <cuda_fp16.h>
#include <cstdint>

// CrissCrossAttention — R15 (= R14 resubmit after infra failure):
//   1) proj_all  : ONE kernel. y==0 -> q/k (3-term split), y in {1,2} -> v
//                  (BM=128, hi-only). W converted inline (convert_w ELIMINATED).
//   2) transpose_all : unchanged
//   3) attn_fused : unchanged R13

#define BATCH 4
#define CTOT 256
#define HW   128
#define CQ   32
#define CHQ  8
#define CHV  64
#define NPIX (HW*HW)

// ---------------- scratch ----------------
__device__ uint32_t g_q  [BATCH*CQ*NPIX];    // packed (hi,lo)
__device__ uint32_t g_k  [BATCH*CQ*NPIX];
__device__ uint32_t g_qT [BATCH*CQ*NPIX];
__device__ uint32_t g_kT [BATCH*CQ*NPIX];
__device__ __half   g_v  [BATCH*CTOT*NPIX];  // fp16 hi only
__device__ __half   g_vT [BATCH*CTOT*NPIX];

__device__ __forceinline__ uint32_t pack2(__half a, __half b)
{
    __half2 t = __halves2half2(a, b);
    return *(uint32_t*)&t;
}

__device__ __forceinline__ void mma16816(float* d, const uint32_t* a, uint32_t b0, uint32_t b1)
{
    asm volatile(
        "mma.sync.aligned.m16n8k16.row.col.f32.f16.f16.f32 "
        "{%0,%1,%2,%3},{%4,%5,%6,%7},{%8,%9},{%0,%1,%2,%3};"
        : "+f"(d[0]), "+f"(d[1]), "+f"(d[2]), "+f"(d[3])
        : "r"(a[0]), "r"(a[1]), "r"(a[2]), "r"(a[3]), "r"(b0), "r"(b1));
}

__device__ __forceinline__ void mma1688(float* d, uint32_t a0, uint32_t a1, uint32_t b0)
{
    asm volatile(
        "mma.sync.aligned.m16n8k8.row.col.f32.f16.f16.f32 "
        "{%0,%1,%2,%3},{%4,%5},{%6},{%0,%1,%2,%3};"
        : "+f"(d[0]), "+f"(d[1]), "+f"(d[2]), "+f"(d[3])
        : "r"(a0), "r"(a1), "r"(b0));
}

__device__ __forceinline__ void cp_async16(uint32_t saddr, const void* gptr)
{
    asm volatile("cp.async.cg.shared.global [%0], [%1], 16;" :: "r"(saddr), "l"(gptr));
}

// ---------------- 1) unified projection ----------------
// smem qk branch: Wh 5120 | Wl 5120 | Xh 8704 | Xl 8704  (overlay Osm 33792)
// smem v  branch: Wh 10240 | Xh 8704                     (overlay Osm 33792)
#define PJ_SM 33792

__global__ __launch_bounds__(256) void proj_all(
    const float* __restrict__ x,
    const float* __restrict__ Wq, const float* __restrict__ bq,
    const float* __restrict__ Wk, const float* __restrict__ bk,
    const float* __restrict__ Wv, const float* __restrict__ bv)
{
    extern __shared__ char sm[];
    float* Osm = (float*)sm;

    const int bb = blockIdx.z;
    const int p0 = blockIdx.x * 128;
    const int tid = threadIdx.x;
    const int wid = tid >> 5, lane = tid & 31;
    const int wm = wid & 1, wp = wid >> 1;
    const int gr = lane >> 2, gq = lane & 3;

    const float* xb = x + (size_t)bb * CTOT * NPIX;

    if (blockIdx.y == 0) {
        // ================= q/k branch: 3-term exact split =================
        uint32_t* Wh2s = (uint32_t*)(sm);
        uint32_t* Wl2s = (uint32_t*)(sm + 5120);
        uint32_t* Xh2s = (uint32_t*)(sm + 10240);
        uint32_t* Xl2s = (uint32_t*)(sm + 18944);

        float acc[2][4][4];
#pragma unroll
        for (int mt = 0; mt < 2; mt++)
#pragma unroll
            for (int nt = 0; nt < 4; nt++)
#pragma unroll
                for (int j = 0; j < 4; j++) acc[mt][nt][j] = 0.f;

        float2 pw[4];
        float pf0[8], pf1[8];

#pragma unroll
        for (int i = 0; i < 4; i++) {
            int e = tid + i * 256;
            int m = e >> 4, kq = e & 15;
            const float* wr = (m < 32) ? Wq + (size_t)m * 256 : Wk + (size_t)(m - 32) * 256;
            pw[i] = *(const float2*)&wr[2 * kq];
        }
#pragma unroll
        for (int i = 0; i < 8; i++) {
            int e = tid + i * 256;
            int kq = e >> 7, p = e & 127;
            size_t goff = (size_t)(2 * kq) * NPIX + p0 + p;
            pf0[i] = xb[goff];
            pf1[i] = xb[goff + NPIX];
        }

        for (int chunk = 0; chunk < 8; chunk++) {
#pragma unroll
            for (int i = 0; i < 4; i++) {
                int e = tid + i * 256;
                int m = e >> 4, kq = e & 15;
                __half h0 = __float2half_rn(pw[i].x);
                __half l0 = __float2half_rn(pw[i].x - __half2float(h0));
                __half h1 = __float2half_rn(pw[i].y);
                __half l1 = __float2half_rn(pw[i].y - __half2float(h1));
                Wh2s[m * 20 + kq] = pack2(h0, h1);
                Wl2s[m * 20 + kq] = pack2(l0, l1);
            }
#pragma unroll
            for (int i = 0; i < 8; i++) {
                int e = tid + i * 256;
                int kq = e >> 7, p = e & 127;
                __half h0 = __float2half_rn(pf0[i]);
                __half l0 = __float2half_rn(pf0[i] - __half2float(h0));
                __half h1 = __float2half_rn(pf1[i]);
                __half l1 = __float2half_rn(pf1[i] - __half2float(h1));
                Xh2s[kq * 136 + p] = pack2(h0, h1);
                Xl2s[kq * 136 + p] = pack2(l0, l1);
            }
            __syncthreads();

            if (chunk < 7) {
                const int kq0 = (chunk + 1) * 16;
#pragma unroll
                for (int i = 0; i < 4; i++) {
                    int e = tid + i * 256;
                    int m = e >> 4, kq = e & 15;
                    const float* wr = (m < 32) ? Wq + (size_t)m * 256 : Wk + (size_t)(m - 32) * 256;
                    pw[i] = *(const float2*)&wr[2 * (kq0 + kq)];
                }
#pragma unroll
                for (int i = 0; i < 8; i++) {
                    int e = tid + i * 256;
                    int kq = e >> 7, p = e & 127;
                    size_t goff = (size_t)(2 * (kq0 + kq)) * NPIX + p0 + p;
                    pf0[i] = xb[goff];
                    pf1[i] = xb[goff + NPIX];
                }
            }

#pragma unroll
            for (int s = 0; s < 2; s++) {
                uint32_t Ah[2][4], Al[2][4];
#pragma unroll
                for (int mt = 0; mt < 2; mt++) {
                    int base = (wm * 32 + mt * 16 + gr) * 20 + s * 8 + gq;
                    Ah[mt][0] = Wh2s[base];
                    Ah[mt][1] = Wh2s[base + 8 * 20];
                    Ah[mt][2] = Wh2s[base + 4];
                    Ah[mt][3] = Wh2s[base + 8 * 20 + 4];
                    Al[mt][0] = Wl2s[base];
                    Al[mt][1] = Wl2s[base + 8 * 20];
                    Al[mt][2] = Wl2s[base + 4];
                    Al[mt][3] = Wl2s[base + 8 * 20 + 4];
                }
#pragma unroll
                for (int nt = 0; nt < 4; nt++) {
                    int p  = wp * 32 + nt * 8 + gr;
                    int xbx = (s * 8 + gq) * 136 + p;
                    uint32_t bh0 = Xh2s[xbx];
                    uint32_t bh1 = Xh2s[xbx + 4 * 136];
                    uint32_t bl0 = Xl2s[xbx];
                    uint32_t bl1 = Xl2s[xbx + 4 * 136];
#pragma unroll
                    for (int mt = 0; mt < 2; mt++) {
                        mma16816(acc[mt][nt], Ah[mt], bh0, bh1);
                        mma16816(acc[mt][nt], Ah[mt], bl0, bl1);
                        mma16816(acc[mt][nt], Al[mt], bh0, bh1);
                    }
                }
            }
            __syncthreads();
        }

#pragma unroll
        for (int mt = 0; mt < 2; mt++)
#pragma unroll
            for (int nt = 0; nt < 4; nt++) {
                int row = wm * 32 + mt * 16 + gr;
                int p   = wp * 32 + nt * 8 + 2 * gq;
                Osm[row * 132 + p]           = acc[mt][nt][0];
                Osm[row * 132 + p + 1]       = acc[mt][nt][1];
                Osm[(row + 8) * 132 + p]     = acc[mt][nt][2];
                Osm[(row + 8) * 132 + p + 1] = acc[mt][nt][3];
            }
        __syncthreads();

#pragma unroll
        for (int i = 0; i < 8; i++) {
            int e = tid + i * 256;
            int r = e >> 5, p4 = (e & 31) << 2;
            float bias = (r < 32) ? bq[r] : bk[r - 32];
            uint32_t* dst = (r < 32) ? g_q + (size_t)(bb * CQ + r) * NPIX
                                     : g_k + (size_t)(bb * CQ + r - 32) * NPIX;
            float4 v4 = *(float4*)&Osm[r * 132 + p4];
            float vv[4] = {v4.x + bias, v4.y + bias, v4.z + bias, v4.w + bias};
            uint32_t w[4];
#pragma unroll
            for (int j = 0; j < 4; j++) {
                __half h = __float2half_rn(vv[j]);
                __half l = __float2half_rn(vv[j] - __half2float(h));
                w[j] = pack2(h, l);
            }
            *(uint4*)&dst[p0 + p4] = make_uint4(w[0], w[1], w[2], w[3]);
        }
    } else {
        // ================= v branch: BM=128, hi-only =================
        uint32_t* Wh2s = (uint32_t*)(sm);
        uint32_t* Xh2s = (uint32_t*)(sm + 10240);

        const int m0 = 64 + (blockIdx.y - 1) * 128;

        float acc[4][4][4];
#pragma unroll
        for (int mt = 0; mt < 4; mt++)
#pragma unroll
            for (int nt = 0; nt < 4; nt++)
#pragma unroll
                for (int j = 0; j < 4; j++) acc[mt][nt][j] = 0.f;

        float2 pw[8];
        float pf0[8], pf1[8];
#pragma unroll
        for (int i = 0; i < 8; i++) {
            int e = tid + i * 256;
            int wrow = m0 - 64 + (e >> 4);
            pw[i] = *(const float2*)&Wv[(size_t)wrow * 256 + 2 * (e & 15)];
        }
#pragma unroll
        for (int i = 0; i < 8; i++) {
            int e = tid + i * 256;
            int kq = e >> 7, p = e & 127;
            size_t goff = (size_t)(2 * kq) * NPIX + p0 + p;
            pf0[i] = xb[goff];
            pf1[i] = xb[goff + NPIX];
        }

        for (int chunk = 0; chunk < 8; chunk++) {
#pragma unroll
            for (int i = 0; i < 8; i++) {
                int e = tid + i * 256;
                Wh2s[(e >> 4) * 20 + (e & 15)] =
                    pack2(__float2half_rn(pw[i].x), __float2half_rn(pw[i].y));
            }
#pragma unroll
            for (int i = 0; i < 8; i++) {
                int e = tid + i * 256;
                int kq = e >> 7, p = e & 127;
                Xh2s[kq * 136 + p] = pack2(__float2half_rn(pf0[i]), __float2half_rn(pf1[i]));
            }
            __syncthreads();

            if (chunk < 7) {
                const int kq0 = (chunk + 1) * 16;
#pragma unroll
                for (int i = 0; i < 8; i++) {
                    int e = tid + i * 256;
                    int wrow = m0 - 64 + (e >> 4);
                    pw[i] = *(const float2*)&Wv[(size_t)wrow * 256 + 2 * (kq0 + (e & 15))];
                }
#pragma unroll
                for (int i = 0; i < 8; i++) {
                    int e = tid + i * 256;
                    int kq = e >> 7, p = e & 127;
                    size_t goff = (size_t)(2 * (kq0 + kq)) * NPIX + p0 + p;
                    pf0[i] = xb[goff];
                    pf1[i] = xb[goff + NPIX];
                }
            }

#pragma unroll
            for (int s = 0; s < 2; s++) {
                uint32_t Ah[4][4];
#pragma unroll
                for (int mt = 0; mt < 4; mt++) {
                    int base = (wm * 64 + mt * 16 + gr) * 20 + s * 8 + gq;
                    Ah[mt][0] = Wh2s[base];
                    Ah[mt][1] = Wh2s[base + 8 * 20];
                    Ah[mt][2] = Wh2s[base + 4];
                    Ah[mt][3] = Wh2s[base + 8 * 20 + 4];
                }
#pragma unroll
                for (int nt = 0; nt < 4; nt++) {
                    int p  = wp * 32 + nt * 8 + gr;
                    int xbx = (s * 8 + gq) * 136 + p;
                    uint32_t bh0 = Xh2s[xbx];
                    uint32_t bh1 = Xh2s[xbx + 4 * 136];
#pragma unroll
                    for (int mt = 0; mt < 4; mt++)
                        mma16816(acc[mt][nt], Ah[mt], bh0, bh1);
                }
            }
            __syncthreads();
        }

#pragma unroll
        for (int h = 0; h < 2; h++) {
            __syncthreads();
            if (wm == h) {
#pragma unroll
                for (int mt = 0; mt < 4; mt++)
#pragma unroll
                    for (int nt = 0; nt < 4; nt++) {
                        int row = mt * 16 + gr;
                        int p   = wp * 32 + nt * 8 + 2 * gq;
                        Osm[row * 132 + p]           = acc[mt][nt][0];
                        Osm[row * 132 + p + 1]       = acc[mt][nt][1];
                        Osm[(row + 8) * 132 + p]     = acc[mt][nt][2];
                        Osm[(row + 8) * 132 + p + 1] = acc[mt][nt][3];
                    }
            }
            __syncthreads();
#pragma unroll
            for (int i = 0; i < 8; i++) {
                int e = tid + i * 256;
                int row = e >> 5, p4 = (e & 31) << 2;
                int r = m0 + h * 64 + row;
                float bias = bv[r - 64];
                __half* dst = g_v + (size_t)(bb * CTOT + r - 64) * NPIX;
                float4 v4 = *(float4*)&Osm[row * 132 + p4];
                __half2 h01 = __floats2half2_rn(v4.x + bias, v4.y + bias);
                __half2 h23 = __floats2half2_rn(v4.z + bias, v4.w + bias);
                uint2 w2 = make_uint2(*(uint32_t*)&h01, *(uint32_t*)&h23);
                *(uint2*)&dst[p0 + p4] = w2;
            }
        }
    }
}

// ---------------- 2) transposes (fat tiles, unchanged) ----------------
__global__ __launch_bounds__(256) void transpose_all()
{
    __shared__ char sbuf[35072];
    const int id = blockIdx.x;
    const int tid = threadIdx.x;

    if (id < 512) {
        uint32_t (*tile)[129] = (uint32_t(*)[129])sbuf;
        const int plane = id >> 1;
        const int y0 = (id & 1) * 64;
        const uint32_t* src;
        uint32_t* dst;
        if (plane < BATCH * CQ) { src = g_q + (size_t)plane * NPIX; dst = g_qT + (size_t)plane * NPIX; }
        else { int p = plane - BATCH * CQ; src = g_k + (size_t)p * NPIX; dst = g_kT + (size_t)p * NPIX; }
#pragma unroll
        for (int it = 0; it < 32; it++) {
            int idx = tid + it * 256;
            int row = idx >> 7, col = idx & 127;
            tile[row][col] = src[(size_t)(y0 + row) * HW + col];
        }
        __syncthreads();
#pragma unroll
        for (int it = 0; it < 32; it++) {
            int idx = tid + it * 256;
            int orow = idx >> 6, r = idx & 63;
            dst[(size_t)orow * HW + y0 + r] = tile[r][orow];
        }
    } else {
        ushort (*tile)[137] = (ushort(*)[137])sbuf;
        const int plane = id - 512;
        const uint32_t* src = (const uint32_t*)(g_v + (size_t)plane * NPIX);
        uint32_t*       dst = (uint32_t*)(g_vT + (size_t)plane * NPIX);
#pragma unroll
        for (int it = 0; it < 32; it++) {
            int idx = tid + it * 256;
            int row = idx >> 6, cu = idx & 63;
            uint32_t w = src[row * 64 + cu];
            tile[row][2 * cu]     = (ushort)(w & 0xffff);
            tile[row][2 * cu + 1] = (ushort)(w >> 16);
        }
        __syncthreads();
#pragma unroll
        for (int it = 0; it < 32; it++) {
            int idx = tid + it * 256;
            int oc = idx >> 6, ru = idx & 63;
            uint32_t w = (uint32_t)tile[2 * ru][oc] | ((uint32_t)tile[2 * ru + 1][oc] << 16);
            dst[oc * 64 + ru] = w;
        }
    }
}

// ---------------- 3) fused attention (unchanged R13) ----------------
#define SM_QH   0
#define SM_QL   2048
#define SM_KH   4096
#define SM_KL   6144
#define SM_V0   8192
#define SM_V1   25600
#define SM_OSMH 43008
#define SM_TOTAL 60416

__global__ __launch_bounds__(256, 3) void attn_fused(
    const float* __restrict__ x,
    const float* __restrict__ gamma, float* __restrict__ out)
{
    extern __shared__ char sm[];
    __half* sQh  = (__half*)(sm + SM_QH);
    __half* sQl  = (__half*)(sm + SM_QL);
    __half* sKh  = (__half*)(sm + SM_KH);
    __half* sKl  = (__half*)(sm + SM_KL);
    __half* V0   = (__half*)(sm + SM_V0);
    __half* V1   = (__half*)(sm + SM_V1);
    __half* OsmH = (__half*)(sm + SM_OSMH);
    __half* OstH = (__half*)(sm + SM_V0);

    const uint32_t smem_u32 = (uint32_t)__cvta_generic_to_shared(sm);

    const int line = blockIdx.x;
    const int bh   = blockIdx.y;
    const int bb = bh >> 2, head = bh & 3;
    const int tid  = threadIdx.x;
    const int wid  = tid >> 5;
    const int lane = tid & 31;
    const int qr   = lane >> 2;
    const int qq   = lane & 3;

    const int p_st = tid & 127;
    const int hc   = tid >> 7;

    for (int phase = 0; phase < 2; phase++) {
        if (phase) __syncthreads();
        const uint32_t* qb = phase ? g_qT : g_q;
        const uint32_t* kb = phase ? g_kT : g_k;

        {
            size_t base = ((size_t)(bb * CQ + head * CHQ + 4 * hc) * NPIX)
                        + (size_t)line * HW + p_st;
            uint32_t qv[4], kv[4];
#pragma unroll
            for (int j = 0; j < 4; j++) {
                qv[j] = qb[base + (size_t)j * NPIX];
                kv[j] = kb[base + (size_t)j * NPIX];
            }
            uint2 qhi, qlo, khi, klo;
            qhi.x = (qv[0] & 0xffffu) | (qv[1] << 16);
            qhi.y = (qv[2] & 0xffffu) | (qv[3] << 16);
            qlo.x = (qv[0] >> 16) | (qv[1] & 0xffff0000u);
            qlo.y = (qv[2] >> 16) | (qv[3] & 0xffff0000u);
            khi.x = (kv[0] & 0xffffu) | (kv[1] << 16);
            khi.y = (kv[2] & 0xffffu) | (kv[3] << 16);
            klo.x = (kv[0] >> 16) | (kv[1] & 0xffff0000u);
            klo.y = (kv[2] >> 16) | (kv[3] & 0xffff0000u);
            int so = p_st * 8 + 4 * hc;
            *(uint2*)&sQh[so] = qhi;
            *(uint2*)&sQl[so] = qlo;
            *(uint2*)&sKh[so] = khi;
            *(uint2*)&sKl[so] = klo;
        }

        if (phase == 0) {
#pragma unroll
            for (int i = 0; i < 4; i++) {
                int e = tid + (i << 8);
                int c = e >> 4, p8 = (e & 15) << 3;
                size_t off = ((size_t)(bb * CTOT + head * CHV + c) * NPIX) + (size_t)line * HW + p8;
                cp_async16(smem_u32 + SM_V0 + (uint32_t)(c * 272 + p8 * 2), &g_v[off]);
            }
            asm volatile("cp.async.commit_group;");
#pragma unroll
            for (int i = 0; i < 4; i++) {
                int e = tid + (i << 8);
                int c = e >> 4, p8 = (e & 15) << 3;
                size_t off = ((size_t)(bb * CTOT + head * CHV + c) * NPIX) + (size_t)line * HW + p8;
                cp_async16(smem_u32 + SM_V1 + (uint32_t)(c * 272 + p8 * 2), &g_vT[off]);
            }
            asm volatile("cp.async.commit_group;");
        }
        __syncthreads();

        const __half* Vcur = phase ? V1 : V0;

        const int aoff = (wid * 16 + qr) * 8 + 2 * qq;
        uint32_t aQh0 = *(const uint32_t*)&sQh[aoff];
        uint32_t aQh1 = *(const uint32_t*)&sQh[aoff + 64];
        uint32_t aQl0 = *(const uint32_t*)&sQl[aoff];
        uint32_t aQl1 = *(const uint32_t*)&sQl[aoff + 64];

        float mr = -1e30f, mr8 = -1e30f, sr = 0.f, sr8 = 0.f;
        float oacc[8][4];
#pragma unroll
        for (int nt = 0; nt < 8; nt++)
#pragma unroll
            for (int j = 0; j < 4; j++) oacc[nt][j] = 0.f;

#pragma unroll
        for (int ch = 0; ch < 2; ch++) {
            float acc[8][4];
#pragma unroll
            for (int nt = 0; nt < 8; nt++)
#pragma unroll
                for (int j = 0; j < 4; j++) acc[nt][j] = 0.f;
#pragma unroll
            for (int nt = 0; nt < 8; nt++) {
                int kbx = (ch * 64 + nt * 8 + qr) * 8 + 2 * qq;
                uint32_t bhh = *(const uint32_t*)&sKh[kbx];
                uint32_t bll = *(const uint32_t*)&sKl[kbx];
                mma1688(acc[nt], aQh0, aQh1, bhh);
                mma1688(acc[nt], aQh0, aQh1, bll);
                mma1688(acc[nt], aQl0, aQl1, bhh);
            }

            float cm = -1e30f, cm8 = -1e30f;
#pragma unroll
            for (int nt = 0; nt < 8; nt++) {
                cm  = fmaxf(cm,  fmaxf(acc[nt][0], acc[nt][1]));
                cm8 = fmaxf(cm8, fmaxf(acc[nt][2], acc[nt][3]));
            }
            cm  = fmaxf(cm,  __shfl_xor_sync(0xffffffffu, cm, 1));
            cm  = fmaxf(cm,  __shfl_xor_sync(0xffffffffu, cm, 2));
            cm8 = fmaxf(cm8, __shfl_xor_sync(0xffffffffu, cm8, 1));
            cm8 = fmaxf(cm8, __shfl_xor_sync(0xffffffffu, cm8, 2));

            float nm  = fmaxf(mr, cm);
            float nm8 = fmaxf(mr8, cm8);
            float sc  = __expf(mr - nm);
            float sc8 = __expf(mr8 - nm8);
            mr = nm; mr8 = nm8;
            sr *= sc; sr8 *= sc8;
#pragma unroll
            for (int nt = 0; nt < 8; nt++) {
                oacc[nt][0] *= sc;  oacc[nt][1] *= sc;
                oacc[nt][2] *= sc8; oacc[nt][3] *= sc8;
            }

            float cs = 0.f, cs8 = 0.f;
#pragma unroll
            for (int nt = 0; nt < 8; nt++) {
                acc[nt][0] = __expf(acc[nt][0] - nm);
                acc[nt][1] = __expf(acc[nt][1] - nm);
                acc[nt][2] = __expf(acc[nt][2] - nm8);
                acc[nt][3] = __expf(acc[nt][3] - nm8);
                cs  += acc[nt][0] + acc[nt][1];
                cs8 += acc[nt][2] + acc[nt][3];
            }
            cs  += __shfl_xor_sync(0xffffffffu, cs, 1);
            cs  += __shfl_xor_sync(0xffffffffu, cs, 2);
            cs8 += __shfl_xor_sync(0xffffffffu, cs8, 1);
            cs8 += __shfl_xor_sync(0xffffffffu, cs8, 2);
            sr  += cs;  sr8 += cs8;

            uint32_t Af[4][4];
#pragma unroll
            for (int kt = 0; kt < 4; kt++) {
                __half2 h0 = __floats2half2_rn(acc[2 * kt][0],     acc[2 * kt][1]);
                __half2 h1 = __floats2half2_rn(acc[2 * kt][2],     acc[2 * kt][3]);
                __half2 h2 = __floats2half2_rn(acc[2 * kt + 1][0], acc[2 * kt + 1][1]);
                __half2 h3 = __floats2half2_rn(acc[2 * kt + 1][2], acc[2 * kt + 1][3]);
                Af[kt][0] = *(uint32_t*)&h0;
                Af[kt][1] = *(uint32_t*)&h1;
                Af[kt][2] = *(uint32_t*)&h2;
                Af[kt][3] = *(uint32_t*)&h3;
            }

            if (ch == 0) {
                if (phase == 0) asm volatile("cp.async.wait_group 1;" ::: "memory");
                else            asm volatile("cp.async.wait_group 0;" ::: "memory");
                __syncthreads();
            }

#pragma unroll
            for (int kt = 0; kt < 4; kt++) {
#pragma unroll
                for (int nt = 0; nt < 8; nt++) {
                    int vb0 = (8 * nt + qr) * 136 + ch * 64 + 16 * kt + 2 * qq;
                    uint32_t bh0 = *(const uint32_t*)&Vcur[vb0];
                    uint32_t bh1 = *(const uint32_t*)&Vcur[vb0 + 8];
                    mma16816(oacc[nt], Af[kt], bh0, bh1);
                }
            }
        }

        const float inv_r  = 1.f / sr;
        const float inv_r8 = 1.f / sr8;
        const int   r  = wid * 16 + qr;
        const int   r8 = r + 8;

        if (phase == 0) {
#pragma unroll
            for (int nt = 0; nt < 8; nt++) {
                int c0 = 8 * nt + 2 * qq;
                OsmH[c0 * 136 + r]        = __float2half_rn(oacc[nt][0] * inv_r);
                OsmH[(c0 + 1) * 136 + r]  = __float2half_rn(oacc[nt][1] * inv_r);
                OsmH[c0 * 136 + r8]       = __float2half_rn(oacc[nt][2] * inv_r8);
                OsmH[(c0 + 1) * 136 + r8] = __float2half_rn(oacc[nt][3] * inv_r8);
            }
        } else {
            const float g = gamma[0];
#pragma unroll
            for (int nt = 0; nt < 8; nt++) {
                int c0 = 8 * nt + 2 * qq;
                OstH[c0 * 136 + r]        = __float2half_rn(oacc[nt][0] * inv_r);
                OstH[(c0 + 1) * 136 + r]  = __float2half_rn(oacc[nt][1] * inv_r);
                OstH[c0 * 136 + r8]       = __float2half_rn(oacc[nt][2] * inv_r8);
                OstH[(c0 + 1) * 136 + r8] = __float2half_rn(oacc[nt][3] * inv_r8);
            }
            __syncthreads();
#pragma unroll
            for (int i = 0; i < 4; i++) {
                int e = tid + (i << 8);
                int c = e >> 4, p8 = (e & 15) << 3;
                size_t off = ((size_t)(bb * CTOT + head * CHV + c) * HW + line) * HW + p8;
                uint4 ow = *(uint4*)&OstH[c * 136 + p8];
                uint4 hw = *(uint4*)&OsmH[c * 136 + p8];
                float4 x0 = *(const float4*)&x[off];
                float4 x1 = *(const float4*)&x[off + 4];
                float2 ov01 = __half22float2(*(__half2*)&ow.x);
                float2 ov23 = __half22float2(*(__half2*)&ow.y);
                float2 ov45 = __half22float2(*(__half2*)&ow.z);
                float2 ov67 = __half22float2(*(__half2*)&ow.w);
                float2 oh01 = __half22float2(*(__half2*)&hw.x);
                float2 oh23 = __half22float2(*(__half2*)&hw.y);
                float2 oh45 = __half22float2(*(__half2*)&hw.z);
                float2 oh67 = __half22float2(*(__half2*)&hw.w);
                float4 r0, r1;
                r0.x = g * (oh01.x + ov01.x) + x0.x;
                r0.y = g * (oh01.y + ov01.y) + x0.y;
                r0.z = g * (oh23.x + ov23.x) + x0.z;
                r0.w = g * (oh23.y + ov23.y) + x0.w;
                r1.x = g * (oh45.x + ov45.x) + x1.x;
                r1.y = g * (oh45.y + ov45.y) + x1.y;
                r1.z = g * (oh67.x + ov67.x) + x1.z;
                r1.w = g * (oh67.y + ov67.y) + x1.w;
                *(float4*)&out[off]     = r0;
                *(float4*)&out[off + 4] = r1;
            }
        }
    }
}

// ---------------- launch ----------------
extern "C" void kernel_launch(void* const* d_in, const int* in_sizes, int n_in,
                              void* d_out, int out_size)
{
    const float* x     = (const float*)d_in[0];
    const float* Wq    = (const float*)d_in[1];
    const float* bq    = (const float*)d_in[2];
    const float* Wk    = (const float*)d_in[3];
    const float* bk    = (const float*)d_in[4];
    const float* Wv    = (const float*)d_in[5];
    const float* bv    = (const float*)d_in[6];
    const float* gamma = (const float*)d_in[7];
    float* out = (float*)d_out;

    proj_all<<<dim3(128, 3, 4), 256, PJ_SM>>>(x, Wq, bq, Wk, bk, Wv, bv);
    transpose_all<<<1536, 256>>>();

    cudaFuncSetAttribute(attn_fused, cudaFuncAttributeMaxDynamicSharedMemorySize, SM_TOTAL);
    attn_fused<<<dim3(HW, 16), 256, SM_TOTAL>>>(x, gamma, out);
}

// round 16
// speedup vs baseline: 5.2761x; 1.0682x over previous
#include <cuda_runtime.h>
#include <cuda_fp16.h>
#include <cstdint>

// CrissCrossAttention — R16 (= R15 with projection UN-merged):
//   R15 post-mortem: single proj_all compiled to 170 regs (union of both
//   branches) -> 1 CTA/SM, 94 us. Split back into proj_qk + proj_v, each
//   __launch_bounds__(256,2). Inline W conversion kept (no convert kernel).
//   transpose_all / attn_fused unchanged.

#define BATCH 4
#define CTOT 256
#define HW   128
#define CQ   32
#define CHQ  8
#define CHV  64
#define NPIX (HW*HW)

// ---------------- scratch ----------------
__device__ uint32_t g_q  [BATCH*CQ*NPIX];    // packed (hi,lo)
__device__ uint32_t g_k  [BATCH*CQ*NPIX];
__device__ uint32_t g_qT [BATCH*CQ*NPIX];
__device__ uint32_t g_kT [BATCH*CQ*NPIX];
__device__ __half   g_v  [BATCH*CTOT*NPIX];  // fp16 hi only
__device__ __half   g_vT [BATCH*CTOT*NPIX];

__device__ __forceinline__ uint32_t pack2(__half a, __half b)
{
    __half2 t = __halves2half2(a, b);
    return *(uint32_t*)&t;
}

__device__ __forceinline__ void mma16816(float* d, const uint32_t* a, uint32_t b0, uint32_t b1)
{
    asm volatile(
        "mma.sync.aligned.m16n8k16.row.col.f32.f16.f16.f32 "
        "{%0,%1,%2,%3},{%4,%5,%6,%7},{%8,%9},{%0,%1,%2,%3};"
        : "+f"(d[0]), "+f"(d[1]), "+f"(d[2]), "+f"(d[3])
        : "r"(a[0]), "r"(a[1]), "r"(a[2]), "r"(a[3]), "r"(b0), "r"(b1));
}

__device__ __forceinline__ void mma1688(float* d, uint32_t a0, uint32_t a1, uint32_t b0)
{
    asm volatile(
        "mma.sync.aligned.m16n8k8.row.col.f32.f16.f16.f32 "
        "{%0,%1,%2,%3},{%4,%5},{%6},{%0,%1,%2,%3};"
        : "+f"(d[0]), "+f"(d[1]), "+f"(d[2]), "+f"(d[3])
        : "r"(a0), "r"(a1), "r"(b0));
}

__device__ __forceinline__ void cp_async16(uint32_t saddr, const void* gptr)
{
    asm volatile("cp.async.cg.shared.global [%0], [%1], 16;" :: "r"(saddr), "l"(gptr));
}

#define PJ_SM 33792

// ---------------- 1a) q/k projection (3-term split, inline W convert) ----------------
__global__ __launch_bounds__(256, 2) void proj_qk(
    const float* __restrict__ x,
    const float* __restrict__ Wq, const float* __restrict__ bq,
    const float* __restrict__ Wk, const float* __restrict__ bk)
{
    extern __shared__ char sm[];
    uint32_t* Wh2s = (uint32_t*)(sm);
    uint32_t* Wl2s = (uint32_t*)(sm + 5120);
    uint32_t* Xh2s = (uint32_t*)(sm + 10240);
    uint32_t* Xl2s = (uint32_t*)(sm + 18944);
    float*    Osm  = (float*)sm;

    const int bb = blockIdx.z;
    const int p0 = blockIdx.x * 128;
    const int tid = threadIdx.x;
    const int wid = tid >> 5, lane = tid & 31;
    const int wm = wid & 1, wp = wid >> 1;
    const int gr = lane >> 2, gq = lane & 3;

    const float* xb = x + (size_t)bb * CTOT * NPIX;

    float acc[2][4][4];
#pragma unroll
    for (int mt = 0; mt < 2; mt++)
#pragma unroll
        for (int nt = 0; nt < 4; nt++)
#pragma unroll
            for (int j = 0; j < 4; j++) acc[mt][nt][j] = 0.f;

    float2 pw[4];
    float pf0[8], pf1[8];

#pragma unroll
    for (int i = 0; i < 4; i++) {
        int e = tid + i * 256;
        int m = e >> 4, kq = e & 15;
        const float* wr = (m < 32) ? Wq + (size_t)m * 256 : Wk + (size_t)(m - 32) * 256;
        pw[i] = *(const float2*)&wr[2 * kq];
    }
#pragma unroll
    for (int i = 0; i < 8; i++) {
        int e = tid + i * 256;
        int kq = e >> 7, p = e & 127;
        size_t goff = (size_t)(2 * kq) * NPIX + p0 + p;
        pf0[i] = xb[goff];
        pf1[i] = xb[goff + NPIX];
    }

    for (int chunk = 0; chunk < 8; chunk++) {
#pragma unroll
        for (int i = 0; i < 4; i++) {
            int e = tid + i * 256;
            int m = e >> 4, kq = e & 15;
            __half h0 = __float2half_rn(pw[i].x);
            __half l0 = __float2half_rn(pw[i].x - __half2float(h0));
            __half h1 = __float2half_rn(pw[i].y);
            __half l1 = __float2half_rn(pw[i].y - __half2float(h1));
            Wh2s[m * 20 + kq] = pack2(h0, h1);
            Wl2s[m * 20 + kq] = pack2(l0, l1);
        }
#pragma unroll
        for (int i = 0; i < 8; i++) {
            int e = tid + i * 256;
            int kq = e >> 7, p = e & 127;
            __half h0 = __float2half_rn(pf0[i]);
            __half l0 = __float2half_rn(pf0[i] - __half2float(h0));
            __half h1 = __float2half_rn(pf1[i]);
            __half l1 = __float2half_rn(pf1[i] - __half2float(h1));
            Xh2s[kq * 136 + p] = pack2(h0, h1);
            Xl2s[kq * 136 + p] = pack2(l0, l1);
        }
        __syncthreads();

        if (chunk < 7) {
            const int kq0 = (chunk + 1) * 16;
#pragma unroll
            for (int i = 0; i < 4; i++) {
                int e = tid + i * 256;
                int m = e >> 4, kq = e & 15;
                const float* wr = (m < 32) ? Wq + (size_t)m * 256 : Wk + (size_t)(m - 32) * 256;
                pw[i] = *(const float2*)&wr[2 * (kq0 + kq)];
            }
#pragma unroll
            for (int i = 0; i < 8; i++) {
                int e = tid + i * 256;
                int kq = e >> 7, p = e & 127;
                size_t goff = (size_t)(2 * (kq0 + kq)) * NPIX + p0 + p;
                pf0[i] = xb[goff];
                pf1[i] = xb[goff + NPIX];
            }
        }

#pragma unroll
        for (int s = 0; s < 2; s++) {
            uint32_t Ah[2][4], Al[2][4];
#pragma unroll
            for (int mt = 0; mt < 2; mt++) {
                int base = (wm * 32 + mt * 16 + gr) * 20 + s * 8 + gq;
                Ah[mt][0] = Wh2s[base];
                Ah[mt][1] = Wh2s[base + 8 * 20];
                Ah[mt][2] = Wh2s[base + 4];
                Ah[mt][3] = Wh2s[base + 8 * 20 + 4];
                Al[mt][0] = Wl2s[base];
                Al[mt][1] = Wl2s[base + 8 * 20];
                Al[mt][2] = Wl2s[base + 4];
                Al[mt][3] = Wl2s[base + 8 * 20 + 4];
            }
#pragma unroll
            for (int nt = 0; nt < 4; nt++) {
                int p  = wp * 32 + nt * 8 + gr;
                int xbx = (s * 8 + gq) * 136 + p;
                uint32_t bh0 = Xh2s[xbx];
                uint32_t bh1 = Xh2s[xbx + 4 * 136];
                uint32_t bl0 = Xl2s[xbx];
                uint32_t bl1 = Xl2s[xbx + 4 * 136];
#pragma unroll
                for (int mt = 0; mt < 2; mt++) {
                    mma16816(acc[mt][nt], Ah[mt], bh0, bh1);
                    mma16816(acc[mt][nt], Ah[mt], bl0, bl1);
                    mma16816(acc[mt][nt], Al[mt], bh0, bh1);
                }
            }
        }
        __syncthreads();
    }

#pragma unroll
    for (int mt = 0; mt < 2; mt++)
#pragma unroll
        for (int nt = 0; nt < 4; nt++) {
            int row = wm * 32 + mt * 16 + gr;
            int p   = wp * 32 + nt * 8 + 2 * gq;
            Osm[row * 132 + p]           = acc[mt][nt][0];
            Osm[row * 132 + p + 1]       = acc[mt][nt][1];
            Osm[(row + 8) * 132 + p]     = acc[mt][nt][2];
            Osm[(row + 8) * 132 + p + 1] = acc[mt][nt][3];
        }
    __syncthreads();

#pragma unroll
    for (int i = 0; i < 8; i++) {
        int e = tid + i * 256;
        int r = e >> 5, p4 = (e & 31) << 2;
        float bias = (r < 32) ? bq[r] : bk[r - 32];
        uint32_t* dst = (r < 32) ? g_q + (size_t)(bb * CQ + r) * NPIX
                                 : g_k + (size_t)(bb * CQ + r - 32) * NPIX;
        float4 v4 = *(float4*)&Osm[r * 132 + p4];
        float vv[4] = {v4.x + bias, v4.y + bias, v4.z + bias, v4.w + bias};
        uint32_t w[4];
#pragma unroll
        for (int j = 0; j < 4; j++) {
            __half h = __float2half_rn(vv[j]);
            __half l = __float2half_rn(vv[j] - __half2float(h));
            w[j] = pack2(h, l);
        }
        *(uint4*)&dst[p0 + p4] = make_uint4(w[0], w[1], w[2], w[3]);
    }
}

// ---------------- 1b) v projection (BM=128 hi-only, inline W convert) ----------------
__global__ __launch_bounds__(256, 2) void proj_v(
    const float* __restrict__ x,
    const float* __restrict__ Wv, const float* __restrict__ bv)
{
    extern __shared__ char sm[];
    uint32_t* Wh2s = (uint32_t*)(sm);
    uint32_t* Xh2s = (uint32_t*)(sm + 10240);
    float*    Osm  = (float*)sm;

    const int bb = blockIdx.z;
    const int m0 = 64 + blockIdx.y * 128;
    const int p0 = blockIdx.x * 128;
    const int tid = threadIdx.x;
    const int wid = tid >> 5, lane = tid & 31;
    const int wm = wid & 1, wp = wid >> 1;
    const int gr = lane >> 2, gq = lane & 3;

    const float* xb = x + (size_t)bb * CTOT * NPIX;

    float acc[4][4][4];
#pragma unroll
    for (int mt = 0; mt < 4; mt++)
#pragma unroll
        for (int nt = 0; nt < 4; nt++)
#pragma unroll
            for (int j = 0; j < 4; j++) acc[mt][nt][j] = 0.f;

    float2 pw[8];
    float pf0[8], pf1[8];
#pragma unroll
    for (int i = 0; i < 8; i++) {
        int e = tid + i * 256;
        int wrow = m0 - 64 + (e >> 4);
        pw[i] = *(const float2*)&Wv[(size_t)wrow * 256 + 2 * (e & 15)];
    }
#pragma unroll
    for (int i = 0; i < 8; i++) {
        int e = tid + i * 256;
        int kq = e >> 7, p = e & 127;
        size_t goff = (size_t)(2 * kq) * NPIX + p0 + p;
        pf0[i] = xb[goff];
        pf1[i] = xb[goff + NPIX];
    }

    for (int chunk = 0; chunk < 8; chunk++) {
#pragma unroll
        for (int i = 0; i < 8; i++) {
            int e = tid + i * 256;
            Wh2s[(e >> 4) * 20 + (e & 15)] =
                pack2(__float2half_rn(pw[i].x), __float2half_rn(pw[i].y));
        }
#pragma unroll
        for (int i = 0; i < 8; i++) {
            int e = tid + i * 256;
            int kq = e >> 7, p = e & 127;
            Xh2s[kq * 136 + p] = pack2(__float2half_rn(pf0[i]), __float2half_rn(pf1[i]));
        }
        __syncthreads();

        if (chunk < 7) {
            const int kq0 = (chunk + 1) * 16;
#pragma unroll
            for (int i = 0; i < 8; i++) {
                int e = tid + i * 256;
                int wrow = m0 - 64 + (e >> 4);
                pw[i] = *(const float2*)&Wv[(size_t)wrow * 256 + 2 * (kq0 + (e & 15))];
            }
#pragma unroll
            for (int i = 0; i < 8; i++) {
                int e = tid + i * 256;
                int kq = e >> 7, p = e & 127;
                size_t goff = (size_t)(2 * (kq0 + kq)) * NPIX + p0 + p;
                pf0[i] = xb[goff];
                pf1[i] = xb[goff + NPIX];
            }
        }

#pragma unroll
        for (int s = 0; s < 2; s++) {
            uint32_t Ah[4][4];
#pragma unroll
            for (int mt = 0; mt < 4; mt++) {
                int base = (wm * 64 + mt * 16 + gr) * 20 + s * 8 + gq;
                Ah[mt][0] = Wh2s[base];
                Ah[mt][1] = Wh2s[base + 8 * 20];
                Ah[mt][2] = Wh2s[base + 4];
                Ah[mt][3] = Wh2s[base + 8 * 20 + 4];
            }
#pragma unroll
            for (int nt = 0; nt < 4; nt++) {
                int p  = wp * 32 + nt * 8 + gr;
                int xbx = (s * 8 + gq) * 136 + p;
                uint32_t bh0 = Xh2s[xbx];
                uint32_t bh1 = Xh2s[xbx + 4 * 136];
#pragma unroll
                for (int mt = 0; mt < 4; mt++)
                    mma16816(acc[mt][nt], Ah[mt], bh0, bh1);
            }
        }
        __syncthreads();
    }

#pragma unroll
    for (int h = 0; h < 2; h++) {
        __syncthreads();
        if (wm == h) {
#pragma unroll
            for (int mt = 0; mt < 4; mt++)
#pragma unroll
                for (int nt = 0; nt < 4; nt++) {
                    int row = mt * 16 + gr;
                    int p   = wp * 32 + nt * 8 + 2 * gq;
                    Osm[row * 132 + p]           = acc[mt][nt][0];
                    Osm[row * 132 + p + 1]       = acc[mt][nt][1];
                    Osm[(row + 8) * 132 + p]     = acc[mt][nt][2];
                    Osm[(row + 8) * 132 + p + 1] = acc[mt][nt][3];
                }
        }
        __syncthreads();
#pragma unroll
        for (int i = 0; i < 8; i++) {
            int e = tid + i * 256;
            int row = e >> 5, p4 = (e & 31) << 2;
            int r = m0 + h * 64 + row;
            float bias = bv[r - 64];
            __half* dst = g_v + (size_t)(bb * CTOT + r - 64) * NPIX;
            float4 v4 = *(float4*)&Osm[row * 132 + p4];
            __half2 h01 = __floats2half2_rn(v4.x + bias, v4.y + bias);
            __half2 h23 = __floats2half2_rn(v4.z + bias, v4.w + bias);
            uint2 w2 = make_uint2(*(uint32_t*)&h01, *(uint32_t*)&h23);
            *(uint2*)&dst[p0 + p4] = w2;
        }
    }
}

// ---------------- 2) transposes (fat tiles, unchanged) ----------------
__global__ __launch_bounds__(256) void transpose_all()
{
    __shared__ char sbuf[35072];
    const int id = blockIdx.x;
    const int tid = threadIdx.x;

    if (id < 512) {
        uint32_t (*tile)[129] = (uint32_t(*)[129])sbuf;
        const int plane = id >> 1;
        const int y0 = (id & 1) * 64;
        const uint32_t* src;
        uint32_t* dst;
        if (plane < BATCH * CQ) { src = g_q + (size_t)plane * NPIX; dst = g_qT + (size_t)plane * NPIX; }
        else { int p = plane - BATCH * CQ; src = g_k + (size_t)p * NPIX; dst = g_kT + (size_t)p * NPIX; }
#pragma unroll
        for (int it = 0; it < 32; it++) {
            int idx = tid + it * 256;
            int row = idx >> 7, col = idx & 127;
            tile[row][col] = src[(size_t)(y0 + row) * HW + col];
        }
        __syncthreads();
#pragma unroll
        for (int it = 0; it < 32; it++) {
            int idx = tid + it * 256;
            int orow = idx >> 6, r = idx & 63;
            dst[(size_t)orow * HW + y0 + r] = tile[r][orow];
        }
    } else {
        ushort (*tile)[137] = (ushort(*)[137])sbuf;
        const int plane = id - 512;
        const uint32_t* src = (const uint32_t*)(g_v + (size_t)plane * NPIX);
        uint32_t*       dst = (uint32_t*)(g_vT + (size_t)plane * NPIX);
#pragma unroll
        for (int it = 0; it < 32; it++) {
            int idx = tid + it * 256;
            int row = idx >> 6, cu = idx & 63;
            uint32_t w = src[row * 64 + cu];
            tile[row][2 * cu]     = (ushort)(w & 0xffff);
            tile[row][2 * cu + 1] = (ushort)(w >> 16);
        }
        __syncthreads();
#pragma unroll
        for (int it = 0; it < 32; it++) {
            int idx = tid + it * 256;
            int oc = idx >> 6, ru = idx & 63;
            uint32_t w = (uint32_t)tile[2 * ru][oc] | ((uint32_t)tile[2 * ru + 1][oc] << 16);
            dst[oc * 64 + ru] = w;
        }
    }
}

// ---------------- 3) fused attention (unchanged R13) ----------------
#define SM_QH   0
#define SM_QL   2048
#define SM_KH   4096
#define SM_KL   6144
#define SM_V0   8192
#define SM_V1   25600
#define SM_OSMH 43008
#define SM_TOTAL 60416

__global__ __launch_bounds__(256, 3) void attn_fused(
    const float* __restrict__ x,
    const float* __restrict__ gamma, float* __restrict__ out)
{
    extern __shared__ char sm[];
    __half* sQh  = (__half*)(sm + SM_QH);
    __half* sQl  = (__half*)(sm + SM_QL);
    __half* sKh  = (__half*)(sm + SM_KH);
    __half* sKl  = (__half*)(sm + SM_KL);
    __half* V0   = (__half*)(sm + SM_V0);
    __half* V1   = (__half*)(sm + SM_V1);
    __half* OsmH = (__half*)(sm + SM_OSMH);
    __half* OstH = (__half*)(sm + SM_V0);

    const uint32_t smem_u32 = (uint32_t)__cvta_generic_to_shared(sm);

    const int line = blockIdx.x;
    const int bh   = blockIdx.y;
    const int bb = bh >> 2, head = bh & 3;
    const int tid  = threadIdx.x;
    const int wid  = tid >> 5;
    const int lane = tid & 31;
    const int qr   = lane >> 2;
    const int qq   = lane & 3;

    const int p_st = tid & 127;
    const int hc   = tid >> 7;

    for (int phase = 0; phase < 2; phase++) {
        if (phase) __syncthreads();
        const uint32_t* qb = phase ? g_qT : g_q;
        const uint32_t* kb = phase ? g_kT : g_k;

        {
            size_t base = ((size_t)(bb * CQ + head * CHQ + 4 * hc) * NPIX)
                        + (size_t)line * HW + p_st;
            uint32_t qv[4], kv[4];
#pragma unroll
            for (int j = 0; j < 4; j++) {
                qv[j] = qb[base + (size_t)j * NPIX];
                kv[j] = kb[base + (size_t)j * NPIX];
            }
            uint2 qhi, qlo, khi, klo;
            qhi.x = (qv[0] & 0xffffu) | (qv[1] << 16);
            qhi.y = (qv[2] & 0xffffu) | (qv[3] << 16);
            qlo.x = (qv[0] >> 16) | (qv[1] & 0xffff0000u);
            qlo.y = (qv[2] >> 16) | (qv[3] & 0xffff0000u);
            khi.x = (kv[0] & 0xffffu) | (kv[1] << 16);
            khi.y = (kv[2] & 0xffffu) | (kv[3] << 16);
            klo.x = (kv[0] >> 16) | (kv[1] & 0xffff0000u);
            klo.y = (kv[2] >> 16) | (kv[3] & 0xffff0000u);
            int so = p_st * 8 + 4 * hc;
            *(uint2*)&sQh[so] = qhi;
            *(uint2*)&sQl[so] = qlo;
            *(uint2*)&sKh[so] = khi;
            *(uint2*)&sKl[so] = klo;
        }

        if (phase == 0) {
#pragma unroll
            for (int i = 0; i < 4; i++) {
                int e = tid + (i << 8);
                int c = e >> 4, p8 = (e & 15) << 3;
                size_t off = ((size_t)(bb * CTOT + head * CHV + c) * NPIX) + (size_t)line * HW + p8;
                cp_async16(smem_u32 + SM_V0 + (uint32_t)(c * 272 + p8 * 2), &g_v[off]);
            }
            asm volatile("cp.async.commit_group;");
#pragma unroll
            for (int i = 0; i < 4; i++) {
                int e = tid + (i << 8);
                int c = e >> 4, p8 = (e & 15) << 3;
                size_t off = ((size_t)(bb * CTOT + head * CHV + c) * NPIX) + (size_t)line * HW + p8;
                cp_async16(smem_u32 + SM_V1 + (uint32_t)(c * 272 + p8 * 2), &g_vT[off]);
            }
            asm volatile("cp.async.commit_group;");
        }
        __syncthreads();

        const __half* Vcur = phase ? V1 : V0;

        const int aoff = (wid * 16 + qr) * 8 + 2 * qq;
        uint32_t aQh0 = *(const uint32_t*)&sQh[aoff];
        uint32_t aQh1 = *(const uint32_t*)&sQh[aoff + 64];
        uint32_t aQl0 = *(const uint32_t*)&sQl[aoff];
        uint32_t aQl1 = *(const uint32_t*)&sQl[aoff + 64];

        float mr = -1e30f, mr8 = -1e30f, sr = 0.f, sr8 = 0.f;
        float oacc[8][4];
#pragma unroll
        for (int nt = 0; nt < 8; nt++)
#pragma unroll
            for (int j = 0; j < 4; j++) oacc[nt][j] = 0.f;

#pragma unroll
        for (int ch = 0; ch < 2; ch++) {
            float acc[8][4];
#pragma unroll
            for (int nt = 0; nt < 8; nt++)
#pragma unroll
                for (int j = 0; j < 4; j++) acc[nt][j] = 0.f;
#pragma unroll
            for (int nt = 0; nt < 8; nt++) {
                int kbx = (ch * 64 + nt * 8 + qr) * 8 + 2 * qq;
                uint32_t bhh = *(const uint32_t*)&sKh[kbx];
                uint32_t bll = *(const uint32_t*)&sKl[kbx];
                mma1688(acc[nt], aQh0, aQh1, bhh);
                mma1688(acc[nt], aQh0, aQh1, bll);
                mma1688(acc[nt], aQl0, aQl1, bhh);
            }

            float cm = -1e30f, cm8 = -1e30f;
#pragma unroll
            for (int nt = 0; nt < 8; nt++) {
                cm  = fmaxf(cm,  fmaxf(acc[nt][0], acc[nt][1]));
                cm8 = fmaxf(cm8, fmaxf(acc[nt][2], acc[nt][3]));
            }
            cm  = fmaxf(cm,  __shfl_xor_sync(0xffffffffu, cm, 1));
            cm  = fmaxf(cm,  __shfl_xor_sync(0xffffffffu, cm, 2));
            cm8 = fmaxf(cm8, __shfl_xor_sync(0xffffffffu, cm8, 1));
            cm8 = fmaxf(cm8, __shfl_xor_sync(0xffffffffu, cm8, 2));

            float nm  = fmaxf(mr, cm);
            float nm8 = fmaxf(mr8, cm8);
            float sc  = __expf(mr - nm);
            float sc8 = __expf(mr8 - nm8);
            mr = nm; mr8 = nm8;
            sr *= sc; sr8 *= sc8;
#pragma unroll
            for (int nt = 0; nt < 8; nt++) {
                oacc[nt][0] *= sc;  oacc[nt][1] *= sc;
                oacc[nt][2] *= sc8; oacc[nt][3] *= sc8;
            }

            float cs = 0.f, cs8 = 0.f;
#pragma unroll
            for (int nt = 0; nt < 8; nt++) {
                acc[nt][0] = __expf(acc[nt][0] - nm);
                acc[nt][1] = __expf(acc[nt][1] - nm);
                acc[nt][2] = __expf(acc[nt][2] - nm8);
                acc[nt][3] = __expf(acc[nt][3] - nm8);
                cs  += acc[nt][0] + acc[nt][1];
                cs8 += acc[nt][2] + acc[nt][3];
            }
            cs  += __shfl_xor_sync(0xffffffffu, cs, 1);
            cs  += __shfl_xor_sync(0xffffffffu, cs, 2);
            cs8 += __shfl_xor_sync(0xffffffffu, cs8, 1);
            cs8 += __shfl_xor_sync(0xffffffffu, cs8, 2);
            sr  += cs;  sr8 += cs8;

            uint32_t Af[4][4];
#pragma unroll
            for (int kt = 0; kt < 4; kt++) {
                __half2 h0 = __floats2half2_rn(acc[2 * kt][0],     acc[2 * kt][1]);
                __half2 h1 = __floats2half2_rn(acc[2 * kt][2],     acc[2 * kt][3]);
                __half2 h2 = __floats2half2_rn(acc[2 * kt + 1][0], acc[2 * kt + 1][1]);
                __half2 h3 = __floats2half2_rn(acc[2 * kt + 1][2], acc[2 * kt + 1][3]);
                Af[kt][0] = *(uint32_t*)&h0;
                Af[kt][1] = *(uint32_t*)&h1;
                Af[kt][2] = *(uint32_t*)&h2;
                Af[kt][3] = *(uint32_t*)&h3;
            }

            if (ch == 0) {
                if (phase == 0) asm volatile("cp.async.wait_group 1;" ::: "memory");
                else            asm volatile("cp.async.wait_group 0;" ::: "memory");
                __syncthreads();
            }

#pragma unroll
            for (int kt = 0; kt < 4; kt++) {
#pragma unroll
                for (int nt = 0; nt < 8; nt++) {
                    int vb0 = (8 * nt + qr) * 136 + ch * 64 + 16 * kt + 2 * qq;
                    uint32_t bh0 = *(const uint32_t*)&Vcur[vb0];
                    uint32_t bh1 = *(const uint32_t*)&Vcur[vb0 + 8];
                    mma16816(oacc[nt], Af[kt], bh0, bh1);
                }
            }
        }

        const float inv_r  = 1.f / sr;
        const float inv_r8 = 1.f / sr8;
        const int   r  = wid * 16 + qr;
        const int   r8 = r + 8;

        if (phase == 0) {
#pragma unroll
            for (int nt = 0; nt < 8; nt++) {
                int c0 = 8 * nt + 2 * qq;
                OsmH[c0 * 136 + r]        = __float2half_rn(oacc[nt][0] * inv_r);
                OsmH[(c0 + 1) * 136 + r]  = __float2half_rn(oacc[nt][1] * inv_r);
                OsmH[c0 * 136 + r8]       = __float2half_rn(oacc[nt][2] * inv_r8);
                OsmH[(c0 + 1) * 136 + r8] = __float2half_rn(oacc[nt][3] * inv_r8);
            }
        } else {
            const float g = gamma[0];
#pragma unroll
            for (int nt = 0; nt < 8; nt++) {
                int c0 = 8 * nt + 2 * qq;
                OstH[c0 * 136 + r]        = __float2half_rn(oacc[nt][0] * inv_r);
                OstH[(c0 + 1) * 136 + r]  = __float2half_rn(oacc[nt][1] * inv_r);
                OstH[c0 * 136 + r8]       = __float2half_rn(oacc[nt][2] * inv_r8);
                OstH[(c0 + 1) * 136 + r8] = __float2half_rn(oacc[nt][3] * inv_r8);
            }
            __syncthreads();
#pragma unroll
            for (int i = 0; i < 4; i++) {
                int e = tid + (i << 8);
                int c = e >> 4, p8 = (e & 15) << 3;
                size_t off = ((size_t)(bb * CTOT + head * CHV + c) * HW + line) * HW + p8;
                uint4 ow = *(uint4*)&OstH[c * 136 + p8];
                uint4 hw = *(uint4*)&OsmH[c * 136 + p8];
                float4 x0 = *(const float4*)&x[off];
                float4 x1 = *(const float4*)&x[off + 4];
                float2 ov01 = __half22float2(*(__half2*)&ow.x);
                float2 ov23 = __half22float2(*(__half2*)&ow.y);
                float2 ov45 = __half22float2(*(__half2*)&ow.z);
                float2 ov67 = __half22float2(*(__half2*)&ow.w);
                float2 oh01 = __half22float2(*(__half2*)&hw.x);
                float2 oh23 = __half22float2(*(__half2*)&hw.y);
                float2 oh45 = __half22float2(*(__half2*)&hw.z);
                float2 oh67 = __half22float2(*(__half2*)&hw.w);
                float4 r0, r1;
                r0.x = g * (oh01.x + ov01.x) + x0.x;
                r0.y = g * (oh01.y + ov01.y) + x0.y;
                r0.z = g * (oh23.x + ov23.x) + x0.z;
                r0.w = g * (oh23.y + ov23.y) + x0.w;
                r1.x = g * (oh45.x + ov45.x) + x1.x;
                r1.y = g * (oh45.y + ov45.y) + x1.y;
                r1.z = g * (oh67.x + ov67.x) + x1.z;
                r1.w = g * (oh67.y + ov67.y) + x1.w;
                *(float4*)&out[off]     = r0;
                *(float4*)&out[off + 4] = r1;
            }
        }
    }
}

// ---------------- launch ----------------
extern "C" void kernel_launch(void* const* d_in, const int* in_sizes, int n_in,
                              void* d_out, int out_size)
{
    const float* x     = (const float*)d_in[0];
    const float* Wq    = (const float*)d_in[1];
    const float* bq    = (const float*)d_in[2];
    const float* Wk    = (const float*)d_in[3];
    const float* bk    = (const float*)d_in[4];
    const float* Wv    = (const float*)d_in[5];
    const float* bv    = (const float*)d_in[6];
    const float* gamma = (const float*)d_in[7];
    float* out = (float*)d_out;

    proj_qk<<<dim3(128, 1, 4), 256, PJ_SM>>>(x, Wq, bq, Wk, bk);
    proj_v<<<dim3(128, 2, 4), 256, PJ_SM>>>(x, Wv, bv);
    transpose_all<<<1536, 256>>>();

    cudaFuncSetAttribute(attn_fused, cudaFuncAttributeMaxDynamicSharedMemorySize, SM_TOTAL);
    attn_fused<<<dim3(HW, 16), 256, SM_TOTAL>>>(x, gamma, out);
}